// round 5
// baseline (speedup 1.0000x reference)
#include <cuda_runtime.h>
#include <math.h>
#include <stdint.h>

#define NATOM 32768
#define MNBR 12
#define DIM 64
#define FNBR 41
#define ORIG 92
#define TWO_D 128
#define KTOT 169
#define NCRY 512
#define NA 64
#define CNT1F (393216.0f)
#define CNT2F (32768.0f)
#define EPSBN 1e-5f

// ---------------- scratch (device globals; no allocation) ----------------
__device__ float g_x[2][NATOM * DIM];
__device__ float g_zself[NATOM * TWO_D];
__device__ float g_z[NATOM * MNBR * TWO_D];          // 201 MB
__device__ float g_summed[NATOM * DIM];
__device__ float g_G[NCRY * NA * 384];               // 50 MB
__device__ float g_Wt[3 * 64 * TWO_D];               // self W [l][k][o]
__device__ uint32_t g_WnT[3 * 112 * TWO_D];          // nbr W tf32 [l][k][n], k padded to 112
__device__ float g_embT[ORIG * DIM];                 // [k][d]
__device__ float g_bilT[DIM * 6 * DIM];              // [d][o*64+k]
__device__ float g_fcaT[DIM * ORIG];                 // [k][c]
__device__ float g_s1[TWO_D], g_ss1[TWO_D], g_s2[DIM], g_ss2[DIM];

__device__ __forceinline__ float softplusf(float v) {
    return v > 20.0f ? v : log1pf(expf(v));
}
__device__ __forceinline__ uint32_t tf32r(float v) {
    uint32_t r;
    asm("cvt.rna.tf32.f32 %0, %1;" : "=r"(r) : "f"(v));
    return r;
}
__device__ __forceinline__ void mma_tf32(float* c, const uint32_t* a, const uint32_t* b) {
    asm volatile(
        "mma.sync.aligned.m16n8k8.row.col.f32.tf32.tf32.f32 "
        "{%0,%1,%2,%3}, {%4,%5,%6,%7}, {%8,%9}, {%0,%1,%2,%3};"
        : "+f"(c[0]), "+f"(c[1]), "+f"(c[2]), "+f"(c[3])
        : "r"(a[0]), "r"(a[1]), "r"(a[2]), "r"(a[3]), "r"(b[0]), "r"(b[1]));
}

// ---------------- prep: weight layouts ----------------
__global__ void prep_kernel(const float* __restrict__ conv_W,
                            const float* __restrict__ embed_W,
                            const float* __restrict__ bil_W,
                            const float* __restrict__ fca_W) {
    int idx = blockIdx.x * blockDim.x + threadIdx.x;
    if (idx < 3 * 64 * TWO_D) {                       // g_Wt self [l][k][o]
        int l = idx / 8192, r = idx % 8192, k = r >> 7, o = r & 127;
        g_Wt[idx] = conv_W[(l * TWO_D + o) * KTOT + k];
        return;
    }
    int i1 = idx - 3 * 64 * TWO_D;
    if (i1 < 3 * 112 * TWO_D) {                       // g_WnT tf32 [l][k][n]
        int l = i1 / (112 * TWO_D), r = i1 % (112 * TWO_D);
        int k = r >> 7, n = r & 127;
        float v = (k < 105) ? conv_W[(l * TWO_D + n) * KTOT + 64 + k] : 0.f;
        g_WnT[i1] = tf32r(v);
        return;
    }
    int i2 = i1 - 3 * 112 * TWO_D;
    if (i2 < ORIG * DIM) {                            // g_embT [k][d]
        int k = i2 / DIM, d = i2 % DIM;
        g_embT[i2] = embed_W[d * ORIG + k];
        return;
    }
    int i3 = i2 - ORIG * DIM;
    if (i3 < DIM * 6 * DIM) {                         // g_bilT [d][o*64+k]
        int d = i3 / 384, ok = i3 % 384;
        int o = ok >> 6, k2 = ok & 63;
        g_bilT[i3] = bil_W[(o * DIM + d) * DIM + k2];
        return;
    }
    int i4 = i3 - DIM * 6 * DIM;
    if (i4 < DIM * ORIG) {
        int k = i4 / ORIG, c = i4 % ORIG;
        g_fcaT[i4] = fca_W[c * DIM + k];
    }
}

// ---------------- embedding: x = atom_fea @ embed_W^T  (K=92) ----------------
__global__ __launch_bounds__(256) void embed_kernel(const float* __restrict__ atom_fea) {
    __shared__ float As[64 * ORIG];
    __shared__ float Ws[ORIG * DIM];
    int t = threadIdx.x;
    int rb = blockIdx.x * 64;
    for (int e = t; e < ORIG * DIM; e += 256) Ws[e] = g_embT[e];
    int warp = t >> 5, lane = t & 31;
    for (int m = warp; m < 64; m += 8) {
        const float* row = atom_fea + (rb + m) * ORIG;
        As[m * ORIG + lane] = row[lane];
        As[m * ORIG + 32 + lane] = row[32 + lane];
        if (lane < ORIG - 64) As[m * ORIG + 64 + lane] = row[64 + lane];
    }
    __syncthreads();
    int ty = t >> 5, tx = t & 31;
    float acc[8][2];
#pragma unroll
    for (int i = 0; i < 8; i++) { acc[i][0] = 0.f; acc[i][1] = 0.f; }
    for (int k = 0; k < ORIG; k++) {
        float2 b = *(const float2*)&Ws[k * DIM + tx * 2];
#pragma unroll
        for (int i = 0; i < 8; i++) {
            float a = As[(ty * 8 + i) * ORIG + k];
            acc[i][0] = fmaf(a, b.x, acc[i][0]);
            acc[i][1] = fmaf(a, b.y, acc[i][1]);
        }
    }
#pragma unroll
    for (int i = 0; i < 8; i++)
        *(float2*)&g_x[0][(rb + ty * 8 + i) * DIM + tx * 2] = make_float2(acc[i][0], acc[i][1]);
}

// ---------------- per-layer stat zeroing ----------------
__global__ void zero_stats() {
    int t = threadIdx.x;
    if (t < TWO_D) { g_s1[t] = 0.f; g_ss1[t] = 0.f; }
    if (t < DIM)   { g_s2[t] = 0.f; g_ss2[t] = 0.f; }
}

// ---------------- zself[n,o] = b[o] + W[:, :64] . x[n]  (K=64 GEMM, scalar) ----------------
__global__ __launch_bounds__(256) void zself_kernel(int l, int buf,
                                                    const float* __restrict__ conv_b) {
    extern __shared__ float sm[];
    float* Ws = sm;                // [64][128]
    float* As = sm + 64 * TWO_D;   // [64][64]
    int t = threadIdx.x;
    int rb = blockIdx.x * 64;
    const float* x = g_x[buf];
    for (int e = t; e < 64 * TWO_D; e += 256) Ws[e] = g_Wt[l * 8192 + e];
    int warp = t >> 5, lane = t & 31;
    for (int m = warp; m < 64; m += 8) {
        As[m * 64 + lane]      = x[(rb + m) * DIM + lane];
        As[m * 64 + 32 + lane] = x[(rb + m) * DIM + 32 + lane];
    }
    __syncthreads();
    int ty = t >> 5, tx = t & 31;
    float acc[8][4];
#pragma unroll
    for (int i = 0; i < 8; i++)
#pragma unroll
        for (int c = 0; c < 4; c++) acc[i][c] = conv_b[l * TWO_D + tx * 4 + c];
    for (int k = 0; k < 64; k++) {
        float4 b = *(const float4*)&Ws[k * TWO_D + tx * 4];
#pragma unroll
        for (int i = 0; i < 8; i++) {
            float a = As[(ty * 8 + i) * 64 + k];
            acc[i][0] = fmaf(a, b.x, acc[i][0]);
            acc[i][1] = fmaf(a, b.y, acc[i][1]);
            acc[i][2] = fmaf(a, b.z, acc[i][2]);
            acc[i][3] = fmaf(a, b.w, acc[i][3]);
        }
    }
#pragma unroll
    for (int i = 0; i < 8; i++)
        *(float4*)&g_zself[(rb + ty * 8 + i) * TWO_D + tx * 4] =
            make_float4(acc[i][0], acc[i][1], acc[i][2], acc[i][3]);
}

// ---------------- main conv GEMM via mma.sync tf32 ----------------
// Per CTA: z[128 rows, 128 cols] = A[128,112] x W[112,128] (+zself), 16 warps,
// warp tile 32x32 (2x4 m16n8k8 fragments), K in 14 steps of 8.
#define APITCH 116
#define BPITCH 136
#define CZ_SMEM ((128 * APITCH + 112 * BPITCH + 256) * 4)

__global__ __launch_bounds__(512, 1) void convz_kernel(int l, int buf,
                                                       const float* __restrict__ nbr_fea,
                                                       const int* __restrict__ nbr_idx) {
    extern __shared__ uint32_t smu[];
    uint32_t* As = smu;                          // [128][116]
    uint32_t* Bs = smu + 128 * APITCH;           // [112][136]
    float* redS = (float*)(Bs + 112 * BPITCH);   // [128]
    float* redQ = redS + 128;                    // [128]
    __shared__ int nbr_s[128];
    int t = threadIdx.x, w = t >> 5, lane = t & 31;
    int rb = blockIdx.x * 128;
    const float* x = g_x[buf];

    if (t < 128) {
        nbr_s[t] = nbr_idx[rb + t];
        redS[t] = 0.f;
        redQ[t] = 0.f;
    }
    // B: copy pre-converted tf32 weights, k-major
    {
        const uint32_t* src = g_WnT + l * 112 * TWO_D;
        for (int e = t; e < 112 * TWO_D; e += 512)
            Bs[(e >> 7) * BPITCH + (e & 127)] = src[e];
    }
    __syncthreads();
    // A: gather [x[nbr] | nbr_fea | pad] with tf32 conversion
    for (int m = w; m < 128; m += 16) {
        uint32_t* Ar = As + m * APITCH;
        int nbr = nbr_s[m];
        Ar[lane]      = tf32r(x[nbr * DIM + lane]);
        Ar[32 + lane] = tf32r(x[nbr * DIM + 32 + lane]);
        const float* nf = nbr_fea + (long)(rb + m) * FNBR;
        Ar[64 + lane] = tf32r(nf[lane]);
        if (lane < 9) Ar[96 + lane] = tf32r(nf[32 + lane]);
        if (lane < 7) Ar[105 + lane] = 0u;
    }
    __syncthreads();

    int wm = w >> 2, wn = w & 3;
    int q = lane >> 2, r = lane & 3;
    float c[2][4][4];
#pragma unroll
    for (int mt = 0; mt < 2; mt++)
#pragma unroll
        for (int nt = 0; nt < 4; nt++)
#pragma unroll
            for (int e = 0; e < 4; e++) c[mt][nt][e] = 0.f;

#pragma unroll
    for (int ks = 0; ks < 14; ks++) {
        int klo = ks * 8;
        uint32_t a[2][4];
#pragma unroll
        for (int mt = 0; mt < 2; mt++) {
            const uint32_t* ap = As + (wm * 32 + mt * 16 + q) * APITCH + klo + r;
            a[mt][0] = ap[0];
            a[mt][1] = ap[8 * APITCH];
            a[mt][2] = ap[4];
            a[mt][3] = ap[8 * APITCH + 4];
        }
        uint32_t bf[4][2];
#pragma unroll
        for (int nt = 0; nt < 4; nt++) {
            const uint32_t* bp = Bs + (klo + r) * BPITCH + wn * 32 + nt * 8 + q;
            bf[nt][0] = bp[0];
            bf[nt][1] = bp[4 * BPITCH];
        }
#pragma unroll
        for (int mt = 0; mt < 2; mt++)
#pragma unroll
            for (int nt = 0; nt < 4; nt++)
                mma_tf32(c[mt][nt], a[mt], bf[nt]);
    }

    // epilogue: + zself, store z, BN1 partial stats
#pragma unroll
    for (int nt = 0; nt < 4; nt++) {
        int cc = wn * 32 + nt * 8 + r * 2;
        float s0 = 0.f, s1 = 0.f, q0 = 0.f, q1 = 0.f;
#pragma unroll
        for (int mt = 0; mt < 2; mt++) {
            int m0 = wm * 32 + mt * 16 + q;
            int row0 = rb + m0, row1 = row0 + 8;
            float2 z0 = *(const float2*)&g_zself[(row0 / MNBR) * TWO_D + cc];
            float2 z1 = *(const float2*)&g_zself[(row1 / MNBR) * TWO_D + cc];
            float v00 = c[mt][nt][0] + z0.x, v01 = c[mt][nt][1] + z0.y;
            float v10 = c[mt][nt][2] + z1.x, v11 = c[mt][nt][3] + z1.y;
            *(float2*)&g_z[(long)row0 * TWO_D + cc] = make_float2(v00, v01);
            *(float2*)&g_z[(long)row1 * TWO_D + cc] = make_float2(v10, v11);
            s0 += v00 + v10; q0 += v00 * v00 + v10 * v10;
            s1 += v01 + v11; q1 += v01 * v01 + v11 * v11;
        }
        atomicAdd(&redS[cc], s0);
        atomicAdd(&redS[cc + 1], s1);
        atomicAdd(&redQ[cc], q0);
        atomicAdd(&redQ[cc + 1], q1);
    }
    __syncthreads();
    if (t < 128) {
        atomicAdd(&g_s1[t], redS[t]);
        atomicAdd(&g_ss1[t], redQ[t]);
    }
}

// ---------------- BN1 + gate + sum over neighbors, BN2 stats (float2) ----------------
__global__ __launch_bounds__(256) void reduce_kernel(int l,
                                                     const float* __restrict__ bn1_g,
                                                     const float* __restrict__ bn1_b) {
    int c = threadIdx.x & 31, grp = threadIdx.x >> 5;
    int d0 = 2 * c;
    float inv = 1.0f / CNT1F;
    float mf0 = g_s1[d0] * inv, mf1 = g_s1[d0 + 1] * inv;
    float vf0 = g_ss1[d0] * inv - mf0 * mf0, vf1 = g_ss1[d0 + 1] * inv - mf1 * mf1;
    float scf0 = rsqrtf(vf0 + EPSBN) * bn1_g[l * TWO_D + d0];
    float scf1 = rsqrtf(vf1 + EPSBN) * bn1_g[l * TWO_D + d0 + 1];
    float shf0 = bn1_b[l * TWO_D + d0] - mf0 * scf0;
    float shf1 = bn1_b[l * TWO_D + d0 + 1] - mf1 * scf1;
    float mc0 = g_s1[64 + d0] * inv, mc1 = g_s1[64 + d0 + 1] * inv;
    float vc0 = g_ss1[64 + d0] * inv - mc0 * mc0, vc1 = g_ss1[64 + d0 + 1] * inv - mc1 * mc1;
    float scc0 = rsqrtf(vc0 + EPSBN) * bn1_g[l * TWO_D + 64 + d0];
    float scc1 = rsqrtf(vc1 + EPSBN) * bn1_g[l * TWO_D + 64 + d0 + 1];
    float shc0 = bn1_b[l * TWO_D + 64 + d0] - mc0 * scc0;
    float shc1 = bn1_b[l * TWO_D + 64 + d0 + 1] - mc1 * scc1;

    float ls0 = 0.f, ls1 = 0.f, lq0 = 0.f, lq1 = 0.f;
    int n0 = blockIdx.x * 16 + grp * 2;
    for (int a = 0; a < 2; a++) {
        int n = n0 + a;
        const float* zr = g_z + (long)n * MNBR * TWO_D;
        float a0 = 0.f, a1 = 0.f;
#pragma unroll
        for (int m = 0; m < MNBR; m++) {
            float2 zf = *(const float2*)&zr[m * TWO_D + d0];
            float2 zc = *(const float2*)&zr[m * TWO_D + 64 + d0];
            float f0 = zf.x * scf0 + shf0, f1 = zf.y * scf1 + shf1;
            float c0v = zc.x * scc0 + shc0, c1v = zc.y * scc1 + shc1;
            a0 += softplusf(c0v) / (1.0f + expf(-f0));
            a1 += softplusf(c1v) / (1.0f + expf(-f1));
        }
        *(float2*)&g_summed[n * DIM + d0] = make_float2(a0, a1);
        ls0 += a0; lq0 += a0 * a0;
        ls1 += a1; lq1 += a1 * a1;
    }
    atomicAdd(&g_s2[d0], ls0);
    atomicAdd(&g_s2[d0 + 1], ls1);
    atomicAdd(&g_ss2[d0], lq0);
    atomicAdd(&g_ss2[d0 + 1], lq1);
}

// ---------------- BN2 + residual softplus -> x_out ----------------
__global__ __launch_bounds__(256) void bnres_kernel(int l, int buf,
                                                    const float* __restrict__ bn2_g,
                                                    const float* __restrict__ bn2_b) {
    int gid = blockIdx.x * 256 + threadIdx.x;
    int d = gid & 63;
    float inv = 1.0f / CNT2F;
    float m2 = g_s2[d] * inv;
    float v2 = g_ss2[d] * inv - m2 * m2;
    float sc = rsqrtf(v2 + EPSBN) * bn2_g[l * DIM + d];
    float sh = bn2_b[l * DIM + d] - m2 * sc;
    float v = g_x[buf][gid] + g_summed[gid] * sc + sh;
    g_x[1 - buf][gid] = softplusf(v);
}

// ---------------- G[bi, o*64+k] = f[bi,:] @ bilT  (K=64, scalar) ----------------
__global__ __launch_bounds__(256) void gmat_kernel(int buf, const int* __restrict__ cidx) {
    extern __shared__ float sm[];
    float* Ws = sm;                // [64][128]
    float* As = sm + 64 * TWO_D;   // [64][64]
    __shared__ int cid_s[64];
    int t = threadIdx.x;
    int rb = blockIdx.x * 64;
    int co = blockIdx.y * 128;
    const float* x = g_x[buf];
    if (t < 64) cid_s[t] = cidx[rb + t];
    for (int e = t; e < 64 * TWO_D; e += 256) {
        int k = e >> 7, oc = e & 127;
        Ws[e] = g_bilT[k * 384 + co + oc];
    }
    __syncthreads();
    int warp = t >> 5, lane = t & 31;
    for (int m = warp; m < 64; m += 8) {
        int a = cid_s[m];
        As[m * 64 + lane]      = x[a * DIM + lane];
        As[m * 64 + 32 + lane] = x[a * DIM + 32 + lane];
    }
    __syncthreads();
    int ty = t >> 5, tx = t & 31;
    float acc[8][4];
#pragma unroll
    for (int i = 0; i < 8; i++)
#pragma unroll
        for (int c = 0; c < 4; c++) acc[i][c] = 0.f;
    for (int k = 0; k < 64; k++) {
        float4 b = *(const float4*)&Ws[k * TWO_D + tx * 4];
#pragma unroll
        for (int i = 0; i < 8; i++) {
            float a = As[(ty * 8 + i) * 64 + k];
            acc[i][0] = fmaf(a, b.x, acc[i][0]);
            acc[i][1] = fmaf(a, b.y, acc[i][1]);
            acc[i][2] = fmaf(a, b.z, acc[i][2]);
            acc[i][3] = fmaf(a, b.w, acc[i][3]);
        }
    }
#pragma unroll
    for (int i = 0; i < 8; i++)
        *(float4*)&g_G[(long)(rb + ty * 8 + i) * 384 + co + tx * 4] =
            make_float4(acc[i][0], acc[i][1], acc[i][2], acc[i][3]);
}

// ---------------- edge: per-pair bilinear dot + fc1 + log_softmax ----------------
__global__ __launch_bounds__(256) void edge_kernel(int buf, const int* __restrict__ cidx,
                                                   const float* __restrict__ bil_b,
                                                   const float* __restrict__ fc1_W,
                                                   const float* __restrict__ fc1_b,
                                                   float* __restrict__ out) {
    __shared__ float f_s[64][65];
    __shared__ float Gi[4][384];
    __shared__ int cid_s[64];
    __shared__ float s_fc1W[36], s_fc1b[6], s_bilb[6];
    int b = blockIdx.x, it = blockIdx.y, t = threadIdx.x;
    const float* x = g_x[buf];
    if (t < 64) cid_s[t] = cidx[b * 64 + t];
    if (t < 36) s_fc1W[t] = fc1_W[t];
    if (t >= 64 && t < 70) s_fc1b[t - 64] = fc1_b[t - 64];
    if (t >= 96 && t < 102) s_bilb[t - 96] = bil_b[t - 96];
    __syncthreads();
    for (int e = t; e < 4096; e += 256) {
        int m = e >> 6, k = e & 63;
        f_s[m][k] = x[cid_s[m] * DIM + k];
    }
    for (int e = t; e < 1536; e += 256) {
        int i4 = e / 384, ok = e % 384;
        Gi[i4][ok] = g_G[(long)(b * 64 + it * 4 + i4) * 384 + ok];
    }
    __syncthreads();
    int i4 = t >> 6, j = t & 63;
    float ev[6];
#pragma unroll
    for (int o = 0; o < 6; o++) {
        float a = s_bilb[o];
#pragma unroll 16
        for (int k = 0; k < 64; k++) a = fmaf(Gi[i4][o * 64 + k], f_s[j][k], a);
        ev[o] = a;
    }
    float tr[6];
#pragma unroll
    for (int r = 0; r < 6; r++) {
        float a = s_fc1b[r];
#pragma unroll
        for (int o = 0; o < 6; o++) a = fmaf(s_fc1W[r * 6 + o], ev[o], a);
        tr[r] = a;
    }
    float mx = tr[0];
#pragma unroll
    for (int r = 1; r < 6; r++) mx = fmaxf(mx, tr[r]);
    float se = 0.f;
#pragma unroll
    for (int r = 0; r < 6; r++) se += expf(tr[r] - mx);
    float lse = mx + logf(se);
    int pair = (it * 4 + i4) * 64 + j;
    float* op = out + ((long)b * 4096 + pair) * 6;
#pragma unroll
    for (int r = 0; r < 6; r++) op[r] = tr[r] - lse;
}

// ---------------- atom_out = f @ fca_W^T + fca_b ----------------
__global__ __launch_bounds__(96) void atomout_kernel(int buf, const int* __restrict__ cidx,
                                                     const float* __restrict__ fca_b,
                                                     float* __restrict__ out2) {
    __shared__ float xr[64];
    int t = threadIdx.x;
    int r = blockIdx.x;
    int atom = cidx[r];
    if (t < 64) xr[t] = g_x[buf][atom * DIM + t];
    __syncthreads();
    if (t < ORIG) {
        float a = fca_b[t];
#pragma unroll 16
        for (int k = 0; k < 64; k++) a = fmaf(xr[k], g_fcaT[k * ORIG + t], a);
        out2[(long)r * ORIG + t] = a;
    }
}

// ---------------- launch ----------------
#define ZS_SM ((64 * TWO_D + 64 * 64) * 4)

extern "C" void kernel_launch(void* const* d_in, const int* in_sizes, int n_in,
                              void* d_out, int out_size) {
    (void)in_sizes; (void)n_in; (void)out_size;
    const float* atom_fea = (const float*)d_in[0];
    const float* nbr_fea  = (const float*)d_in[1];
    const int*   nbr_idx  = (const int*)d_in[2];
    const int*   cidx     = (const int*)d_in[3];
    const float* embed_W  = (const float*)d_in[4];
    const float* conv_W   = (const float*)d_in[5];
    const float* conv_b   = (const float*)d_in[6];
    const float* bn1_g    = (const float*)d_in[7];
    const float* bn1_b    = (const float*)d_in[8];
    const float* bn2_g    = (const float*)d_in[9];
    const float* bn2_b    = (const float*)d_in[10];
    const float* bil_W    = (const float*)d_in[11];
    const float* bil_b    = (const float*)d_in[12];
    const float* fc1_W    = (const float*)d_in[13];
    const float* fc1_b    = (const float*)d_in[14];
    const float* fca_W    = (const float*)d_in[15];
    const float* fca_b    = (const float*)d_in[16];
    float* out = (float*)d_out;

    cudaFuncSetAttribute(convz_kernel, cudaFuncAttributeMaxDynamicSharedMemorySize, CZ_SMEM);
    cudaFuncSetAttribute(zself_kernel, cudaFuncAttributeMaxDynamicSharedMemorySize, ZS_SM);
    cudaFuncSetAttribute(gmat_kernel,  cudaFuncAttributeMaxDynamicSharedMemorySize, ZS_SM);

    int prep_elems = 3 * 64 * TWO_D + 3 * 112 * TWO_D + ORIG * DIM + DIM * 384 + DIM * ORIG;
    prep_kernel<<<(prep_elems + 255) / 256, 256>>>(conv_W, embed_W, bil_W, fca_W);
    embed_kernel<<<NATOM / 64, 256>>>(atom_fea);

    int buf = 0;
    for (int l = 0; l < 3; l++) {
        zero_stats<<<1, 128>>>();
        zself_kernel<<<NATOM / 64, 256, ZS_SM>>>(l, buf, conv_b);
        convz_kernel<<<NATOM * MNBR / 128, 512, CZ_SMEM>>>(l, buf, nbr_fea, nbr_idx);
        reduce_kernel<<<NATOM / 16, 256>>>(l, bn1_g, bn1_b);
        bnres_kernel<<<(NATOM * DIM) / 256, 256>>>(l, buf, bn2_g, bn2_b);
        buf = 1 - buf;
    }

    gmat_kernel<<<dim3(NCRY * NA / 64, 3), 256, ZS_SM>>>(buf, cidx);
    edge_kernel<<<dim3(NCRY, 16), 256>>>(buf, cidx, bil_b, fc1_W, fc1_b, out);
    atomout_kernel<<<NCRY * NA, 96>>>(buf, cidx, fca_b, out + (long)NCRY * NA * NA * 6);
}

// round 6
// speedup vs baseline: 1.3469x; 1.3469x over previous
#include <cuda_runtime.h>
#include <cuda_fp16.h>
#include <math.h>
#include <stdint.h>

#define NATOM 32768
#define MNBR 12
#define DIM 64
#define FNBR 41
#define ORIG 92
#define TWO_D 128
#define KTOT 169
#define NCRY 512
#define NA 64
#define CNT1F (393216.0f)
#define CNT2F (32768.0f)
#define EPSBN 1e-5f

// ---------------- scratch (device globals; no allocation) ----------------
__device__ float g_x[2][NATOM * DIM];
__device__ float g_zself[NATOM * TWO_D];
__device__ float g_z[NATOM * MNBR * TWO_D];          // 201 MB
__device__ float g_summed[NATOM * DIM];
__device__ float g_G[NCRY * NA * 384];               // 50 MB
__device__ float g_Wt[3 * 64 * TWO_D];               // self W [l][k][o]
__device__ uint32_t g_WnH[3 * 56 * TWO_D];           // nbr W half2 [l][k2][n]
__device__ float g_embT[ORIG * DIM];                 // [k][d]
__device__ float g_bilT[DIM * 6 * DIM];              // [d][o*64+k]
__device__ float g_fcaT[DIM * ORIG];                 // [k][c]
__device__ float g_s1[TWO_D], g_ss1[TWO_D], g_s2[DIM], g_ss2[DIM];

__device__ __forceinline__ float softplusf(float v) {
    return v > 20.0f ? v : log1pf(expf(v));
}
__device__ __forceinline__ void mma_f16(float* c, const uint32_t* a, const uint32_t* b) {
    asm volatile(
        "mma.sync.aligned.m16n8k16.row.col.f32.f16.f16.f32 "
        "{%0,%1,%2,%3}, {%4,%5,%6,%7}, {%8,%9}, {%0,%1,%2,%3};"
        : "+f"(c[0]), "+f"(c[1]), "+f"(c[2]), "+f"(c[3])
        : "r"(a[0]), "r"(a[1]), "r"(a[2]), "r"(a[3]), "r"(b[0]), "r"(b[1]));
}

// ---------------- prep: weight layouts + layer-0 stat zeroing ----------------
__global__ void prep_kernel(const float* __restrict__ conv_W,
                            const float* __restrict__ embed_W,
                            const float* __restrict__ bil_W,
                            const float* __restrict__ fca_W) {
    int idx = blockIdx.x * blockDim.x + threadIdx.x;
    if (idx < 3 * 64 * TWO_D) {                       // g_Wt self [l][k][o]
        int l = idx / 8192, r = idx % 8192, k = r >> 7, o = r & 127;
        g_Wt[idx] = conv_W[(l * TWO_D + o) * KTOT + k];
        return;
    }
    int i1 = idx - 3 * 64 * TWO_D;
    if (i1 < 3 * 56 * TWO_D) {                        // g_WnH half2 [l][k2][n]
        int l = i1 / 7168, r = i1 % 7168;
        int k2 = r >> 7, n = r & 127;
        int kk = 2 * k2;
        float a = (kk < 105) ? conv_W[(l * TWO_D + n) * KTOT + 64 + kk] : 0.f;
        float b = (kk + 1 < 105) ? conv_W[(l * TWO_D + n) * KTOT + 64 + kk + 1] : 0.f;
        __half2 h = __floats2half2_rn(a, b);
        g_WnH[i1] = *(uint32_t*)&h;
        return;
    }
    int i2 = i1 - 3 * 56 * TWO_D;
    if (i2 < ORIG * DIM) {                            // g_embT [k][d]
        int k = i2 / DIM, d = i2 % DIM;
        g_embT[i2] = embed_W[d * ORIG + k];
        return;
    }
    int i3 = i2 - ORIG * DIM;
    if (i3 < DIM * 6 * DIM) {                         // g_bilT [d][o*64+k]
        int d = i3 / 384, ok = i3 % 384;
        int o = ok >> 6, k2 = ok & 63;
        g_bilT[i3] = bil_W[(o * DIM + d) * DIM + k2];
        return;
    }
    int i4 = i3 - DIM * 6 * DIM;
    if (i4 < DIM * ORIG) {
        int k = i4 / ORIG, c = i4 % ORIG;
        g_fcaT[i4] = fca_W[c * DIM + k];
        return;
    }
    int i5 = i4 - DIM * ORIG;
    if (i5 < TWO_D) { g_s1[i5] = 0.f; g_ss1[i5] = 0.f; return; }
    int i6 = i5 - TWO_D;
    if (i6 < DIM) { g_s2[i6] = 0.f; g_ss2[i6] = 0.f; }
}

// ---------------- embedding: x = atom_fea @ embed_W^T  (K=92) ----------------
__global__ __launch_bounds__(256) void embed_kernel(const float* __restrict__ atom_fea) {
    __shared__ float As[64 * ORIG];
    __shared__ float Ws[ORIG * DIM];
    int t = threadIdx.x;
    int rb = blockIdx.x * 64;
    for (int e = t; e < ORIG * DIM; e += 256) Ws[e] = g_embT[e];
    int warp = t >> 5, lane = t & 31;
    for (int m = warp; m < 64; m += 8) {
        const float* row = atom_fea + (rb + m) * ORIG;
        As[m * ORIG + lane] = row[lane];
        As[m * ORIG + 32 + lane] = row[32 + lane];
        if (lane < ORIG - 64) As[m * ORIG + 64 + lane] = row[64 + lane];
    }
    __syncthreads();
    int ty = t >> 5, tx = t & 31;
    float acc[8][2];
#pragma unroll
    for (int i = 0; i < 8; i++) { acc[i][0] = 0.f; acc[i][1] = 0.f; }
    for (int k = 0; k < ORIG; k++) {
        float2 b = *(const float2*)&Ws[k * DIM + tx * 2];
#pragma unroll
        for (int i = 0; i < 8; i++) {
            float a = As[(ty * 8 + i) * ORIG + k];
            acc[i][0] = fmaf(a, b.x, acc[i][0]);
            acc[i][1] = fmaf(a, b.y, acc[i][1]);
        }
    }
#pragma unroll
    for (int i = 0; i < 8; i++)
        *(float2*)&g_x[0][(rb + ty * 8 + i) * DIM + tx * 2] = make_float2(acc[i][0], acc[i][1]);
}

// ---------------- per-layer stat zeroing (layers 1,2) ----------------
__global__ void zero_stats() {
    int t = threadIdx.x;
    if (t < TWO_D) { g_s1[t] = 0.f; g_ss1[t] = 0.f; }
    if (t < DIM)   { g_s2[t] = 0.f; g_ss2[t] = 0.f; }
}

// ---------------- zself[n,o] = b[o] + W[:, :64] . x[n]  (K=64 GEMM, scalar) ----------------
__global__ __launch_bounds__(256) void zself_kernel(int l, int buf,
                                                    const float* __restrict__ conv_b) {
    extern __shared__ float sm[];
    float* Ws = sm;                // [64][128]
    float* As = sm + 64 * TWO_D;   // [64][64]
    int t = threadIdx.x;
    int rb = blockIdx.x * 64;
    const float* x = g_x[buf];
    for (int e = t; e < 64 * TWO_D; e += 256) Ws[e] = g_Wt[l * 8192 + e];
    int warp = t >> 5, lane = t & 31;
    for (int m = warp; m < 64; m += 8) {
        As[m * 64 + lane]      = x[(rb + m) * DIM + lane];
        As[m * 64 + 32 + lane] = x[(rb + m) * DIM + 32 + lane];
    }
    __syncthreads();
    int ty = t >> 5, tx = t & 31;
    float acc[8][4];
#pragma unroll
    for (int i = 0; i < 8; i++)
#pragma unroll
        for (int c = 0; c < 4; c++) acc[i][c] = conv_b[l * TWO_D + tx * 4 + c];
    for (int k = 0; k < 64; k++) {
        float4 b = *(const float4*)&Ws[k * TWO_D + tx * 4];
#pragma unroll
        for (int i = 0; i < 8; i++) {
            float a = As[(ty * 8 + i) * 64 + k];
            acc[i][0] = fmaf(a, b.x, acc[i][0]);
            acc[i][1] = fmaf(a, b.y, acc[i][1]);
            acc[i][2] = fmaf(a, b.z, acc[i][2]);
            acc[i][3] = fmaf(a, b.w, acc[i][3]);
        }
    }
#pragma unroll
    for (int i = 0; i < 8; i++)
        *(float4*)&g_zself[(rb + ty * 8 + i) * TWO_D + tx * 4] =
            make_float4(acc[i][0], acc[i][1], acc[i][2], acc[i][3]);
}

// ---------------- main conv GEMM via mma.sync fp16 ----------------
// Per CTA: z[64 rows, 128 cols] = A[64,112] x W[112,128] (+zself).
// 8 warps, warp tile 32x32 (2x4 m16n8k16 frags), K in 7 steps of 16.
#define AP2 60          // A pitch in half2 units (120 halves)
#define BP2 136         // B pitch in half2 units
#define CZ_SMEM ((64 * AP2 + 56 * BP2) * 4)

__global__ __launch_bounds__(256, 2) void convz_kernel(int l, int buf,
                                                       const float* __restrict__ nbr_fea,
                                                       const int* __restrict__ nbr_idx) {
    extern __shared__ uint32_t smu[];
    uint32_t* As2 = smu;               // [64][60] half2
    uint32_t* Bs2 = smu + 64 * AP2;    // [56][136] half2
    __shared__ float redS[128], redQ[128];
    __shared__ int nbr_s[64];
    int t = threadIdx.x, w = t >> 5, lane = t & 31;
    int rb = blockIdx.x * 64;
    const float* x = g_x[buf];
    if (t < 64) nbr_s[t] = nbr_idx[rb + t];
    if (t < 128) { redS[t] = 0.f; redQ[t] = 0.f; }
    // B: copy pre-packed half2 weights with conflict-free pitch
    {
        const uint32_t* src = g_WnH + l * 56 * TWO_D;
        for (int e = t; e < 56 * TWO_D; e += 256)
            Bs2[(e >> 7) * BP2 + (e & 127)] = src[e];
    }
    __syncthreads();
    // A: gather [x[nbr] | nbr_fea | pad] as half2
    for (int m = w; m < 64; m += 8) {
        int nbr = nbr_s[m];
        float2 v = ((const float2*)(x + nbr * DIM))[lane];
        __half2 h = __floats2half2_rn(v.x, v.y);
        As2[m * AP2 + lane] = *(uint32_t*)&h;
        if (lane < 21) {
            const float* nf = nbr_fea + (long)(rb + m) * FNBR;
            float a = nf[2 * lane];
            float b = (2 * lane + 1 < FNBR) ? nf[2 * lane + 1] : 0.f;
            __half2 hh = __floats2half2_rn(a, b);
            As2[m * AP2 + 32 + lane] = *(uint32_t*)&hh;
        } else if (lane < 28) {
            As2[m * AP2 + 32 + lane] = 0u;
        }
    }
    __syncthreads();

    int wm = w & 1, wn = w >> 1;             // wm 0..1 (32 rows), wn 0..3 (32 cols)
    int q = lane >> 2, r = lane & 3;
    float c[2][4][4];
#pragma unroll
    for (int mt = 0; mt < 2; mt++)
#pragma unroll
        for (int nf = 0; nf < 4; nf++)
#pragma unroll
            for (int e = 0; e < 4; e++) c[mt][nf][e] = 0.f;

#pragma unroll
    for (int ks = 0; ks < 7; ks++) {
        uint32_t a[2][4];
#pragma unroll
        for (int mt = 0; mt < 2; mt++) {
            const uint32_t* ap = As2 + (wm * 32 + mt * 16 + q) * AP2 + ks * 8 + r;
            a[mt][0] = ap[0];
            a[mt][1] = ap[8 * AP2];
            a[mt][2] = ap[4];
            a[mt][3] = ap[8 * AP2 + 4];
        }
        uint32_t bf[4][2];
#pragma unroll
        for (int nf = 0; nf < 4; nf++) {
            const uint32_t* bp = Bs2 + (ks * 8 + r) * BP2 + wn * 32 + nf * 8 + q;
            bf[nf][0] = bp[0];
            bf[nf][1] = bp[4 * BP2];
        }
#pragma unroll
        for (int mt = 0; mt < 2; mt++)
#pragma unroll
            for (int nf = 0; nf < 4; nf++)
                mma_f16(c[mt][nf], a[mt], bf[nf]);
    }

    // stage zself rows (<=7 distinct atoms per CTA) in smem (reuse A region)
    __syncthreads();
    float* zss = (float*)As2;                // [7][128]
    int nbase = rb / MNBR;
    for (int e = t; e < 7 * TWO_D; e += 256) {
        int n = nbase + (e >> 7);
        zss[e] = (n < NATOM) ? g_zself[n * TWO_D + (e & 127)] : 0.f;
    }
    __syncthreads();

    // epilogue: + zself, store z, BN1 stats (shuffle-reduced)
#pragma unroll
    for (int nf = 0; nf < 4; nf++) {
        int cc = wn * 32 + nf * 8 + r * 2;
        float s0 = 0.f, s1 = 0.f, q0 = 0.f, q1 = 0.f;
#pragma unroll
        for (int mt = 0; mt < 2; mt++) {
            int m0 = wm * 32 + mt * 16 + q;
            int row0 = rb + m0, row1 = row0 + 8;
            int z0 = (row0 / MNBR - nbase) * TWO_D + cc;
            int z1 = (row1 / MNBR - nbase) * TWO_D + cc;
            float v00 = c[mt][nf][0] + zss[z0], v01 = c[mt][nf][1] + zss[z0 + 1];
            float v10 = c[mt][nf][2] + zss[z1], v11 = c[mt][nf][3] + zss[z1 + 1];
            *(float2*)&g_z[(long)row0 * TWO_D + cc] = make_float2(v00, v01);
            *(float2*)&g_z[(long)row1 * TWO_D + cc] = make_float2(v10, v11);
            s0 += v00 + v10; q0 += v00 * v00 + v10 * v10;
            s1 += v01 + v11; q1 += v01 * v01 + v11 * v11;
        }
#pragma unroll
        for (int off = 4; off < 32; off <<= 1) {
            s0 += __shfl_xor_sync(0xffffffffu, s0, off);
            s1 += __shfl_xor_sync(0xffffffffu, s1, off);
            q0 += __shfl_xor_sync(0xffffffffu, q0, off);
            q1 += __shfl_xor_sync(0xffffffffu, q1, off);
        }
        if (lane < 4) {
            atomicAdd(&redS[cc], s0);
            atomicAdd(&redS[cc + 1], s1);
            atomicAdd(&redQ[cc], q0);
            atomicAdd(&redQ[cc + 1], q1);
        }
    }
    __syncthreads();
    if (t < 128) {
        atomicAdd(&g_s1[t], redS[t]);
        atomicAdd(&g_ss1[t], redQ[t]);
    }
}

// ---------------- BN1 + gate + sum over neighbors, BN2 stats (float2) ----------------
__global__ __launch_bounds__(256) void reduce_kernel(int l,
                                                     const float* __restrict__ bn1_g,
                                                     const float* __restrict__ bn1_b) {
    int c = threadIdx.x & 31, grp = threadIdx.x >> 5;
    int d0 = 2 * c;
    float inv = 1.0f / CNT1F;
    float mf0 = g_s1[d0] * inv, mf1 = g_s1[d0 + 1] * inv;
    float vf0 = g_ss1[d0] * inv - mf0 * mf0, vf1 = g_ss1[d0 + 1] * inv - mf1 * mf1;
    float scf0 = rsqrtf(vf0 + EPSBN) * bn1_g[l * TWO_D + d0];
    float scf1 = rsqrtf(vf1 + EPSBN) * bn1_g[l * TWO_D + d0 + 1];
    float shf0 = bn1_b[l * TWO_D + d0] - mf0 * scf0;
    float shf1 = bn1_b[l * TWO_D + d0 + 1] - mf1 * scf1;
    float mc0 = g_s1[64 + d0] * inv, mc1 = g_s1[64 + d0 + 1] * inv;
    float vc0 = g_ss1[64 + d0] * inv - mc0 * mc0, vc1 = g_ss1[64 + d0 + 1] * inv - mc1 * mc1;
    float scc0 = rsqrtf(vc0 + EPSBN) * bn1_g[l * TWO_D + 64 + d0];
    float scc1 = rsqrtf(vc1 + EPSBN) * bn1_g[l * TWO_D + 64 + d0 + 1];
    float shc0 = bn1_b[l * TWO_D + 64 + d0] - mc0 * scc0;
    float shc1 = bn1_b[l * TWO_D + 64 + d0 + 1] - mc1 * scc1;

    float ls0 = 0.f, ls1 = 0.f, lq0 = 0.f, lq1 = 0.f;
    int n0 = blockIdx.x * 16 + grp * 2;
    for (int a = 0; a < 2; a++) {
        int n = n0 + a;
        const float* zr = g_z + (long)n * MNBR * TWO_D;
        float a0 = 0.f, a1 = 0.f;
#pragma unroll
        for (int m = 0; m < MNBR; m++) {
            float2 zf = *(const float2*)&zr[m * TWO_D + d0];
            float2 zc = *(const float2*)&zr[m * TWO_D + 64 + d0];
            float f0 = zf.x * scf0 + shf0, f1 = zf.y * scf1 + shf1;
            float c0v = zc.x * scc0 + shc0, c1v = zc.y * scc1 + shc1;
            a0 += softplusf(c0v) / (1.0f + expf(-f0));
            a1 += softplusf(c1v) / (1.0f + expf(-f1));
        }
        *(float2*)&g_summed[n * DIM + d0] = make_float2(a0, a1);
        ls0 += a0; lq0 += a0 * a0;
        ls1 += a1; lq1 += a1 * a1;
    }
    atomicAdd(&g_s2[d0], ls0);
    atomicAdd(&g_s2[d0 + 1], ls1);
    atomicAdd(&g_ss2[d0], lq0);
    atomicAdd(&g_ss2[d0 + 1], lq1);
}

// ---------------- BN2 + residual softplus -> x_out ----------------
__global__ __launch_bounds__(256) void bnres_kernel(int l, int buf,
                                                    const float* __restrict__ bn2_g,
                                                    const float* __restrict__ bn2_b) {
    int gid = blockIdx.x * 256 + threadIdx.x;
    int d = gid & 63;
    float inv = 1.0f / CNT2F;
    float m2 = g_s2[d] * inv;
    float v2 = g_ss2[d] * inv - m2 * m2;
    float sc = rsqrtf(v2 + EPSBN) * bn2_g[l * DIM + d];
    float sh = bn2_b[l * DIM + d] - m2 * sc;
    float v = g_x[buf][gid] + g_summed[gid] * sc + sh;
    g_x[1 - buf][gid] = softplusf(v);
}

// ---------------- G[bi, o*64+k] = f[bi,:] @ bilT  (K=64, scalar) ----------------
__global__ __launch_bounds__(256) void gmat_kernel(int buf, const int* __restrict__ cidx) {
    extern __shared__ float sm[];
    float* Ws = sm;                // [64][128]
    float* As = sm + 64 * TWO_D;   // [64][64]
    __shared__ int cid_s[64];
    int t = threadIdx.x;
    int rb = blockIdx.x * 64;
    int co = blockIdx.y * 128;
    const float* x = g_x[buf];
    if (t < 64) cid_s[t] = cidx[rb + t];
    for (int e = t; e < 64 * TWO_D; e += 256) {
        int k = e >> 7, oc = e & 127;
        Ws[e] = g_bilT[k * 384 + co + oc];
    }
    __syncthreads();
    int warp = t >> 5, lane = t & 31;
    for (int m = warp; m < 64; m += 8) {
        int a = cid_s[m];
        As[m * 64 + lane]      = x[a * DIM + lane];
        As[m * 64 + 32 + lane] = x[a * DIM + 32 + lane];
    }
    __syncthreads();
    int ty = t >> 5, tx = t & 31;
    float acc[8][4];
#pragma unroll
    for (int i = 0; i < 8; i++)
#pragma unroll
        for (int c = 0; c < 4; c++) acc[i][c] = 0.f;
    for (int k = 0; k < 64; k++) {
        float4 b = *(const float4*)&Ws[k * TWO_D + tx * 4];
#pragma unroll
        for (int i = 0; i < 8; i++) {
            float a = As[(ty * 8 + i) * 64 + k];
            acc[i][0] = fmaf(a, b.x, acc[i][0]);
            acc[i][1] = fmaf(a, b.y, acc[i][1]);
            acc[i][2] = fmaf(a, b.z, acc[i][2]);
            acc[i][3] = fmaf(a, b.w, acc[i][3]);
        }
    }
#pragma unroll
    for (int i = 0; i < 8; i++)
        *(float4*)&g_G[(long)(rb + ty * 8 + i) * 384 + co + tx * 4] =
            make_float4(acc[i][0], acc[i][1], acc[i][2], acc[i][3]);
}

// ---------------- edge: per-pair bilinear dot + fc1 + log_softmax ----------------
__global__ __launch_bounds__(256) void edge_kernel(int buf, const int* __restrict__ cidx,
                                                   const float* __restrict__ bil_b,
                                                   const float* __restrict__ fc1_W,
                                                   const float* __restrict__ fc1_b,
                                                   float* __restrict__ out) {
    __shared__ float f_s[64][65];
    __shared__ float Gi[4][384];
    __shared__ int cid_s[64];
    __shared__ float s_fc1W[36], s_fc1b[6], s_bilb[6];
    int b = blockIdx.x, it = blockIdx.y, t = threadIdx.x;
    const float* x = g_x[buf];
    if (t < 64) cid_s[t] = cidx[b * 64 + t];
    if (t < 36) s_fc1W[t] = fc1_W[t];
    if (t >= 64 && t < 70) s_fc1b[t - 64] = fc1_b[t - 64];
    if (t >= 96 && t < 102) s_bilb[t - 96] = bil_b[t - 96];
    __syncthreads();
    for (int e = t; e < 4096; e += 256) {
        int m = e >> 6, k = e & 63;
        f_s[m][k] = x[cid_s[m] * DIM + k];
    }
    for (int e = t; e < 1536; e += 256) {
        int i4 = e / 384, ok = e % 384;
        Gi[i4][ok] = g_G[(long)(b * 64 + it * 4 + i4) * 384 + ok];
    }
    __syncthreads();
    int i4 = t >> 6, j = t & 63;
    float ev[6];
#pragma unroll
    for (int o = 0; o < 6; o++) {
        float a = s_bilb[o];
#pragma unroll 16
        for (int k = 0; k < 64; k++) a = fmaf(Gi[i4][o * 64 + k], f_s[j][k], a);
        ev[o] = a;
    }
    float tr[6];
#pragma unroll
    for (int r = 0; r < 6; r++) {
        float a = s_fc1b[r];
#pragma unroll
        for (int o = 0; o < 6; o++) a = fmaf(s_fc1W[r * 6 + o], ev[o], a);
        tr[r] = a;
    }
    float mx = tr[0];
#pragma unroll
    for (int r = 1; r < 6; r++) mx = fmaxf(mx, tr[r]);
    float se = 0.f;
#pragma unroll
    for (int r = 0; r < 6; r++) se += expf(tr[r] - mx);
    float lse = mx + logf(se);
    int pair = (it * 4 + i4) * 64 + j;
    float* op = out + ((long)b * 4096 + pair) * 6;
#pragma unroll
    for (int r = 0; r < 6; r++) op[r] = tr[r] - lse;
}

// ---------------- atom_out = f @ fca_W^T + fca_b ----------------
__global__ __launch_bounds__(96) void atomout_kernel(int buf, const int* __restrict__ cidx,
                                                     const float* __restrict__ fca_b,
                                                     float* __restrict__ out2) {
    __shared__ float xr[64];
    int t = threadIdx.x;
    int r = blockIdx.x;
    int atom = cidx[r];
    if (t < 64) xr[t] = g_x[buf][atom * DIM + t];
    __syncthreads();
    if (t < ORIG) {
        float a = fca_b[t];
#pragma unroll 16
        for (int k = 0; k < 64; k++) a = fmaf(xr[k], g_fcaT[k * ORIG + t], a);
        out2[(long)r * ORIG + t] = a;
    }
}

// ---------------- launch ----------------
#define ZS_SM ((64 * TWO_D + 64 * 64) * 4)

extern "C" void kernel_launch(void* const* d_in, const int* in_sizes, int n_in,
                              void* d_out, int out_size) {
    (void)in_sizes; (void)n_in; (void)out_size;
    const float* atom_fea = (const float*)d_in[0];
    const float* nbr_fea  = (const float*)d_in[1];
    const int*   nbr_idx  = (const int*)d_in[2];
    const int*   cidx     = (const int*)d_in[3];
    const float* embed_W  = (const float*)d_in[4];
    const float* conv_W   = (const float*)d_in[5];
    const float* conv_b   = (const float*)d_in[6];
    const float* bn1_g    = (const float*)d_in[7];
    const float* bn1_b    = (const float*)d_in[8];
    const float* bn2_g    = (const float*)d_in[9];
    const float* bn2_b    = (const float*)d_in[10];
    const float* bil_W    = (const float*)d_in[11];
    const float* bil_b    = (const float*)d_in[12];
    const float* fc1_W    = (const float*)d_in[13];
    const float* fc1_b    = (const float*)d_in[14];
    const float* fca_W    = (const float*)d_in[15];
    const float* fca_b    = (const float*)d_in[16];
    float* out = (float*)d_out;

    cudaFuncSetAttribute(zself_kernel, cudaFuncAttributeMaxDynamicSharedMemorySize, ZS_SM);
    cudaFuncSetAttribute(gmat_kernel,  cudaFuncAttributeMaxDynamicSharedMemorySize, ZS_SM);

    int prep_elems = 3 * 64 * TWO_D + 3 * 56 * TWO_D + ORIG * DIM + DIM * 384 +
                     DIM * ORIG + TWO_D + DIM;
    prep_kernel<<<(prep_elems + 255) / 256, 256>>>(conv_W, embed_W, bil_W, fca_W);
    embed_kernel<<<NATOM / 64, 256>>>(atom_fea);

    int buf = 0;
    for (int l = 0; l < 3; l++) {
        if (l > 0) zero_stats<<<1, 128>>>();
        zself_kernel<<<NATOM / 64, 256, ZS_SM>>>(l, buf, conv_b);
        convz_kernel<<<NATOM * MNBR / 64, 256, CZ_SMEM>>>(l, buf, nbr_fea, nbr_idx);
        reduce_kernel<<<NATOM / 16, 256>>>(l, bn1_g, bn1_b);
        bnres_kernel<<<(NATOM * DIM) / 256, 256>>>(l, buf, bn2_g, bn2_b);
        buf = 1 - buf;
    }

    gmat_kernel<<<dim3(NCRY * NA / 64, 3), 256, ZS_SM>>>(buf, cidx);
    edge_kernel<<<dim3(NCRY, 16), 256>>>(buf, cidx, bil_b, fc1_W, fc1_b, out);
    atomout_kernel<<<NCRY * NA, 96>>>(buf, cidx, fca_b, out + (long)NCRY * NA * NA * 6);
}

// round 7
// speedup vs baseline: 1.5689x; 1.1648x over previous
#include <cuda_runtime.h>
#include <cuda_fp16.h>
#include <math.h>
#include <stdint.h>

#define NATOM 32768
#define MNBR 12
#define DIM 64
#define FNBR 41
#define ORIG 92
#define TWO_D 128
#define KTOT 169
#define NCRY 512
#define NA 64
#define CNT1F (393216.0f)
#define CNT2F (32768.0f)
#define EPSBN 1e-5f

// ---------------- scratch (device globals; no allocation) ----------------
__device__ float g_x[2][NATOM * DIM];
__device__ float g_zself[NATOM * TWO_D];
__device__ uint32_t g_z[NATOM * MNBR * 64];          // z as half2, 100 MB
__device__ float g_summed[NATOM * DIM];
__device__ float g_G[NCRY * NA * 384];               // 50 MB
__device__ float g_Wt[3 * 64 * TWO_D];               // self W [l][k][o]
__device__ uint32_t g_WnH[3 * 56 * TWO_D];           // nbr W half2 [l][k2][n]
__device__ float g_embT[ORIG * DIM];                 // [k][d]
__device__ float g_bilT[DIM * 6 * DIM];              // [d][o*64+k]
__device__ float g_fcaT[DIM * ORIG];                 // [k][c]
__device__ float g_s1[TWO_D], g_ss1[TWO_D], g_s2[DIM], g_ss2[DIM];

__device__ __forceinline__ float softplusf(float v) {
    return v > 20.0f ? v : log1pf(expf(v));
}
__device__ __forceinline__ void mma_f16(float* c, const uint32_t* a, const uint32_t* b) {
    asm volatile(
        "mma.sync.aligned.m16n8k16.row.col.f32.f16.f16.f32 "
        "{%0,%1,%2,%3}, {%4,%5,%6,%7}, {%8,%9}, {%0,%1,%2,%3};"
        : "+f"(c[0]), "+f"(c[1]), "+f"(c[2]), "+f"(c[3])
        : "r"(a[0]), "r"(a[1]), "r"(a[2]), "r"(a[3]), "r"(b[0]), "r"(b[1]));
}

// ---------------- prep: weight layouts + layer-0 stat zeroing ----------------
__global__ void prep_kernel(const float* __restrict__ conv_W,
                            const float* __restrict__ embed_W,
                            const float* __restrict__ bil_W,
                            const float* __restrict__ fca_W) {
    int idx = blockIdx.x * blockDim.x + threadIdx.x;
    if (idx < 3 * 64 * TWO_D) {                       // g_Wt self [l][k][o]
        int l = idx / 8192, r = idx % 8192, k = r >> 7, o = r & 127;
        g_Wt[idx] = conv_W[(l * TWO_D + o) * KTOT + k];
        return;
    }
    int i1 = idx - 3 * 64 * TWO_D;
    if (i1 < 3 * 56 * TWO_D) {                        // g_WnH half2 [l][k2][n]
        int l = i1 / 7168, r = i1 % 7168;
        int k2 = r >> 7, n = r & 127;
        int kk = 2 * k2;
        float a = (kk < 105) ? conv_W[(l * TWO_D + n) * KTOT + 64 + kk] : 0.f;
        float b = (kk + 1 < 105) ? conv_W[(l * TWO_D + n) * KTOT + 64 + kk + 1] : 0.f;
        __half2 h = __floats2half2_rn(a, b);
        g_WnH[i1] = *(uint32_t*)&h;
        return;
    }
    int i2 = i1 - 3 * 56 * TWO_D;
    if (i2 < ORIG * DIM) {                            // g_embT [k][d]
        int k = i2 / DIM, d = i2 % DIM;
        g_embT[i2] = embed_W[d * ORIG + k];
        return;
    }
    int i3 = i2 - ORIG * DIM;
    if (i3 < DIM * 6 * DIM) {                         // g_bilT [d][o*64+k]
        int d = i3 / 384, ok = i3 % 384;
        int o = ok >> 6, k2 = ok & 63;
        g_bilT[i3] = bil_W[(o * DIM + d) * DIM + k2];
        return;
    }
    int i4 = i3 - DIM * 6 * DIM;
    if (i4 < DIM * ORIG) {
        int k = i4 / ORIG, c = i4 % ORIG;
        g_fcaT[i4] = fca_W[c * DIM + k];
        return;
    }
    int i5 = i4 - DIM * ORIG;
    if (i5 < TWO_D) { g_s1[i5] = 0.f; g_ss1[i5] = 0.f; return; }
    int i6 = i5 - TWO_D;
    if (i6 < DIM) { g_s2[i6] = 0.f; g_ss2[i6] = 0.f; }
}

// ---------------- embedding: x = atom_fea @ embed_W^T  (K=92) ----------------
__global__ __launch_bounds__(256) void embed_kernel(const float* __restrict__ atom_fea) {
    __shared__ float As[64 * ORIG];
    __shared__ float Ws[ORIG * DIM];
    int t = threadIdx.x;
    int rb = blockIdx.x * 64;
    for (int e = t; e < ORIG * DIM; e += 256) Ws[e] = g_embT[e];
    int warp = t >> 5, lane = t & 31;
    for (int m = warp; m < 64; m += 8) {
        const float* row = atom_fea + (rb + m) * ORIG;
        As[m * ORIG + lane] = row[lane];
        As[m * ORIG + 32 + lane] = row[32 + lane];
        if (lane < ORIG - 64) As[m * ORIG + 64 + lane] = row[64 + lane];
    }
    __syncthreads();
    int ty = t >> 5, tx = t & 31;
    float acc[8][2];
#pragma unroll
    for (int i = 0; i < 8; i++) { acc[i][0] = 0.f; acc[i][1] = 0.f; }
    for (int k = 0; k < ORIG; k++) {
        float2 b = *(const float2*)&Ws[k * DIM + tx * 2];
#pragma unroll
        for (int i = 0; i < 8; i++) {
            float a = As[(ty * 8 + i) * ORIG + k];
            acc[i][0] = fmaf(a, b.x, acc[i][0]);
            acc[i][1] = fmaf(a, b.y, acc[i][1]);
        }
    }
#pragma unroll
    for (int i = 0; i < 8; i++)
        *(float2*)&g_x[0][(rb + ty * 8 + i) * DIM + tx * 2] = make_float2(acc[i][0], acc[i][1]);
}

// ---------------- per-layer stat zeroing (layers 1,2) ----------------
__global__ void zero_stats() {
    int t = threadIdx.x;
    if (t < TWO_D) { g_s1[t] = 0.f; g_ss1[t] = 0.f; }
    if (t < DIM)   { g_s2[t] = 0.f; g_ss2[t] = 0.f; }
}

// ---------------- zself[n,o] = b[o] + W[:, :64] . x[n]  (K=64 GEMM, scalar) ----------------
__global__ __launch_bounds__(256) void zself_kernel(int l, int buf,
                                                    const float* __restrict__ conv_b) {
    extern __shared__ float sm[];
    float* Ws = sm;                // [64][128]
    float* As = sm + 64 * TWO_D;   // [64][64]
    int t = threadIdx.x;
    int rb = blockIdx.x * 64;
    const float* x = g_x[buf];
    for (int e = t; e < 64 * TWO_D; e += 256) Ws[e] = g_Wt[l * 8192 + e];
    int warp = t >> 5, lane = t & 31;
    for (int m = warp; m < 64; m += 8) {
        As[m * 64 + lane]      = x[(rb + m) * DIM + lane];
        As[m * 64 + 32 + lane] = x[(rb + m) * DIM + 32 + lane];
    }
    __syncthreads();
    int ty = t >> 5, tx = t & 31;
    float acc[8][4];
#pragma unroll
    for (int i = 0; i < 8; i++)
#pragma unroll
        for (int c = 0; c < 4; c++) acc[i][c] = conv_b[l * TWO_D + tx * 4 + c];
    for (int k = 0; k < 64; k++) {
        float4 b = *(const float4*)&Ws[k * TWO_D + tx * 4];
#pragma unroll
        for (int i = 0; i < 8; i++) {
            float a = As[(ty * 8 + i) * 64 + k];
            acc[i][0] = fmaf(a, b.x, acc[i][0]);
            acc[i][1] = fmaf(a, b.y, acc[i][1]);
            acc[i][2] = fmaf(a, b.z, acc[i][2]);
            acc[i][3] = fmaf(a, b.w, acc[i][3]);
        }
    }
#pragma unroll
    for (int i = 0; i < 8; i++)
        *(float4*)&g_zself[(rb + ty * 8 + i) * TWO_D + tx * 4] =
            make_float4(acc[i][0], acc[i][1], acc[i][2], acc[i][3]);
}

// ---------------- main conv GEMM via mma.sync fp16, z stored as half2 ----------------
// Per CTA: z[64 rows, 128 cols] = A[64,112] x W[112,128] (+zself).
// 8 warps, warp tile 32x32 (2x4 m16n8k16 frags), K in 7 steps of 16.
#define AP2 60          // A pitch in half2 units (120 halves)
#define BP2 136         // B pitch in half2 units
#define CZ_SMEM ((64 * AP2 + 56 * BP2) * 4)

__global__ __launch_bounds__(256, 3) void convz_kernel(int l, int buf,
                                                       const float* __restrict__ nbr_fea,
                                                       const int* __restrict__ nbr_idx) {
    extern __shared__ uint32_t smu[];
    uint32_t* As2 = smu;               // [64][60] half2
    uint32_t* Bs2 = smu + 64 * AP2;    // [56][136] half2
    __shared__ float redS[128], redQ[128];
    __shared__ int nbr_s[64];
    int t = threadIdx.x, w = t >> 5, lane = t & 31;
    int rb = blockIdx.x * 64;
    const float* x = g_x[buf];
    if (t < 64) nbr_s[t] = nbr_idx[rb + t];
    if (t < 128) { redS[t] = 0.f; redQ[t] = 0.f; }
    // B: copy pre-packed half2 weights with conflict-free pitch
    {
        const uint32_t* src = g_WnH + l * 56 * TWO_D;
        for (int e = t; e < 56 * TWO_D; e += 256)
            Bs2[(e >> 7) * BP2 + (e & 127)] = src[e];
    }
    __syncthreads();
    // A: gather [x[nbr] | nbr_fea | pad] as half2
    for (int m = w; m < 64; m += 8) {
        int nbr = nbr_s[m];
        float2 v = ((const float2*)(x + nbr * DIM))[lane];
        __half2 h = __floats2half2_rn(v.x, v.y);
        As2[m * AP2 + lane] = *(uint32_t*)&h;
        if (lane < 21) {
            const float* nf = nbr_fea + (long)(rb + m) * FNBR;
            float a = nf[2 * lane];
            float b = (2 * lane + 1 < FNBR) ? nf[2 * lane + 1] : 0.f;
            __half2 hh = __floats2half2_rn(a, b);
            As2[m * AP2 + 32 + lane] = *(uint32_t*)&hh;
        } else if (lane < 28) {
            As2[m * AP2 + 32 + lane] = 0u;
        }
    }
    __syncthreads();

    int wm = w & 1, wn = w >> 1;             // wm 0..1 (32 rows), wn 0..3 (32 cols)
    int q = lane >> 2, r = lane & 3;
    float c[2][4][4];
#pragma unroll
    for (int mt = 0; mt < 2; mt++)
#pragma unroll
        for (int nf = 0; nf < 4; nf++)
#pragma unroll
            for (int e = 0; e < 4; e++) c[mt][nf][e] = 0.f;

#pragma unroll
    for (int ks = 0; ks < 7; ks++) {
        uint32_t a[2][4];
#pragma unroll
        for (int mt = 0; mt < 2; mt++) {
            const uint32_t* ap = As2 + (wm * 32 + mt * 16 + q) * AP2 + ks * 8 + r;
            a[mt][0] = ap[0];
            a[mt][1] = ap[8 * AP2];
            a[mt][2] = ap[4];
            a[mt][3] = ap[8 * AP2 + 4];
        }
        uint32_t bf[4][2];
#pragma unroll
        for (int nf = 0; nf < 4; nf++) {
            const uint32_t* bp = Bs2 + (ks * 8 + r) * BP2 + wn * 32 + nf * 8 + q;
            bf[nf][0] = bp[0];
            bf[nf][1] = bp[4 * BP2];
        }
#pragma unroll
        for (int mt = 0; mt < 2; mt++)
#pragma unroll
            for (int nf = 0; nf < 4; nf++)
                mma_f16(c[mt][nf], a[mt], bf[nf]);
    }

    // stage zself rows (<=7 distinct atoms per CTA) in smem (reuse A region)
    __syncthreads();
    float* zss = (float*)As2;                // [7][128]
    int nbase = rb / MNBR;
    for (int e = t; e < 7 * TWO_D; e += 256) {
        int n = nbase + (e >> 7);
        zss[e] = (n < NATOM) ? g_zself[n * TWO_D + (e & 127)] : 0.f;
    }
    __syncthreads();

    // epilogue: + zself, half2 round-trip (stats on rounded values), store z fp16
#pragma unroll
    for (int nf = 0; nf < 4; nf++) {
        int cc = wn * 32 + nf * 8 + r * 2;
        float s0 = 0.f, s1 = 0.f, q0 = 0.f, q1 = 0.f;
#pragma unroll
        for (int mt = 0; mt < 2; mt++) {
            int m0 = wm * 32 + mt * 16 + q;
            int row0 = rb + m0, row1 = row0 + 8;
            int z0 = (row0 / MNBR - nbase) * TWO_D + cc;
            int z1 = (row1 / MNBR - nbase) * TWO_D + cc;
            __half2 h0 = __floats2half2_rn(c[mt][nf][0] + zss[z0], c[mt][nf][1] + zss[z0 + 1]);
            __half2 h1 = __floats2half2_rn(c[mt][nf][2] + zss[z1], c[mt][nf][3] + zss[z1 + 1]);
            g_z[(long)row0 * 64 + (cc >> 1)] = *(uint32_t*)&h0;
            g_z[(long)row1 * 64 + (cc >> 1)] = *(uint32_t*)&h1;
            float2 v0 = __half22float2(h0);
            float2 v1 = __half22float2(h1);
            s0 += v0.x + v1.x; q0 += v0.x * v0.x + v1.x * v1.x;
            s1 += v0.y + v1.y; q1 += v0.y * v0.y + v1.y * v1.y;
        }
#pragma unroll
        for (int off = 4; off < 32; off <<= 1) {
            s0 += __shfl_xor_sync(0xffffffffu, s0, off);
            s1 += __shfl_xor_sync(0xffffffffu, s1, off);
            q0 += __shfl_xor_sync(0xffffffffu, q0, off);
            q1 += __shfl_xor_sync(0xffffffffu, q1, off);
        }
        if (lane < 4) {
            atomicAdd(&redS[cc], s0);
            atomicAdd(&redS[cc + 1], s1);
            atomicAdd(&redQ[cc], q0);
            atomicAdd(&redQ[cc + 1], q1);
        }
    }
    __syncthreads();
    if (t < 128) {
        atomicAdd(&g_s1[t], redS[t]);
        atomicAdd(&g_ss1[t], redQ[t]);
    }
}

// ---------------- BN1 + gate + sum over neighbors (half2 z), BN2 stats ----------------
__global__ __launch_bounds__(256) void reduce_kernel(int l,
                                                     const float* __restrict__ bn1_g,
                                                     const float* __restrict__ bn1_b) {
    int c = threadIdx.x & 31, grp = threadIdx.x >> 5;
    int d0 = 2 * c;
    float inv = 1.0f / CNT1F;
    float mf0 = g_s1[d0] * inv, mf1 = g_s1[d0 + 1] * inv;
    float vf0 = g_ss1[d0] * inv - mf0 * mf0, vf1 = g_ss1[d0 + 1] * inv - mf1 * mf1;
    float scf0 = rsqrtf(vf0 + EPSBN) * bn1_g[l * TWO_D + d0];
    float scf1 = rsqrtf(vf1 + EPSBN) * bn1_g[l * TWO_D + d0 + 1];
    float shf0 = bn1_b[l * TWO_D + d0] - mf0 * scf0;
    float shf1 = bn1_b[l * TWO_D + d0 + 1] - mf1 * scf1;
    float mc0 = g_s1[64 + d0] * inv, mc1 = g_s1[64 + d0 + 1] * inv;
    float vc0 = g_ss1[64 + d0] * inv - mc0 * mc0, vc1 = g_ss1[64 + d0 + 1] * inv - mc1 * mc1;
    float scc0 = rsqrtf(vc0 + EPSBN) * bn1_g[l * TWO_D + 64 + d0];
    float scc1 = rsqrtf(vc1 + EPSBN) * bn1_g[l * TWO_D + 64 + d0 + 1];
    float shc0 = bn1_b[l * TWO_D + 64 + d0] - mc0 * scc0;
    float shc1 = bn1_b[l * TWO_D + 64 + d0 + 1] - mc1 * scc1;

    float ls0 = 0.f, ls1 = 0.f, lq0 = 0.f, lq1 = 0.f;
    int n0 = blockIdx.x * 16 + grp * 2;
    for (int a = 0; a < 2; a++) {
        int n = n0 + a;
        const uint32_t* zr = g_z + (long)n * MNBR * 64;
        float a0 = 0.f, a1 = 0.f;
#pragma unroll
        for (int m = 0; m < MNBR; m++) {
            uint32_t zfp = zr[m * 64 + c];
            uint32_t zcp = zr[m * 64 + 32 + c];
            float2 zf = __half22float2(*(__half2*)&zfp);
            float2 zc = __half22float2(*(__half2*)&zcp);
            float f0 = zf.x * scf0 + shf0, f1 = zf.y * scf1 + shf1;
            float c0v = zc.x * scc0 + shc0, c1v = zc.y * scc1 + shc1;
            a0 += softplusf(c0v) / (1.0f + expf(-f0));
            a1 += softplusf(c1v) / (1.0f + expf(-f1));
        }
        *(float2*)&g_summed[n * DIM + d0] = make_float2(a0, a1);
        ls0 += a0; lq0 += a0 * a0;
        ls1 += a1; lq1 += a1 * a1;
    }
    atomicAdd(&g_s2[d0], ls0);
    atomicAdd(&g_s2[d0 + 1], ls1);
    atomicAdd(&g_ss2[d0], lq0);
    atomicAdd(&g_ss2[d0 + 1], lq1);
}

// ---------------- BN2 + residual softplus -> x_out ----------------
__global__ __launch_bounds__(256) void bnres_kernel(int l, int buf,
                                                    const float* __restrict__ bn2_g,
                                                    const float* __restrict__ bn2_b) {
    int gid = blockIdx.x * 256 + threadIdx.x;
    int d = gid & 63;
    float inv = 1.0f / CNT2F;
    float m2 = g_s2[d] * inv;
    float v2 = g_ss2[d] * inv - m2 * m2;
    float sc = rsqrtf(v2 + EPSBN) * bn2_g[l * DIM + d];
    float sh = bn2_b[l * DIM + d] - m2 * sc;
    float v = g_x[buf][gid] + g_summed[gid] * sc + sh;
    g_x[1 - buf][gid] = softplusf(v);
}

// ---------------- G[bi, o*64+k] = f[bi,:] @ bilT  (K=64, scalar) ----------------
__global__ __launch_bounds__(256) void gmat_kernel(int buf, const int* __restrict__ cidx) {
    extern __shared__ float sm[];
    float* Ws = sm;                // [64][128]
    float* As = sm + 64 * TWO_D;   // [64][64]
    __shared__ int cid_s[64];
    int t = threadIdx.x;
    int rb = blockIdx.x * 64;
    int co = blockIdx.y * 128;
    const float* x = g_x[buf];
    if (t < 64) cid_s[t] = cidx[rb + t];
    for (int e = t; e < 64 * TWO_D; e += 256) {
        int k = e >> 7, oc = e & 127;
        Ws[e] = g_bilT[k * 384 + co + oc];
    }
    __syncthreads();
    int warp = t >> 5, lane = t & 31;
    for (int m = warp; m < 64; m += 8) {
        int a = cid_s[m];
        As[m * 64 + lane]      = x[a * DIM + lane];
        As[m * 64 + 32 + lane] = x[a * DIM + 32 + lane];
    }
    __syncthreads();
    int ty = t >> 5, tx = t & 31;
    float acc[8][4];
#pragma unroll
    for (int i = 0; i < 8; i++)
#pragma unroll
        for (int c = 0; c < 4; c++) acc[i][c] = 0.f;
    for (int k = 0; k < 64; k++) {
        float4 b = *(const float4*)&Ws[k * TWO_D + tx * 4];
#pragma unroll
        for (int i = 0; i < 8; i++) {
            float a = As[(ty * 8 + i) * 64 + k];
            acc[i][0] = fmaf(a, b.x, acc[i][0]);
            acc[i][1] = fmaf(a, b.y, acc[i][1]);
            acc[i][2] = fmaf(a, b.z, acc[i][2]);
            acc[i][3] = fmaf(a, b.w, acc[i][3]);
        }
    }
#pragma unroll
    for (int i = 0; i < 8; i++)
        *(float4*)&g_G[(long)(rb + ty * 8 + i) * 384 + co + tx * 4] =
            make_float4(acc[i][0], acc[i][1], acc[i][2], acc[i][3]);
}

// ---------------- edge: per-pair bilinear dot + fc1 + log_softmax ----------------
__global__ __launch_bounds__(256) void edge_kernel(int buf, const int* __restrict__ cidx,
                                                   const float* __restrict__ bil_b,
                                                   const float* __restrict__ fc1_W,
                                                   const float* __restrict__ fc1_b,
                                                   float* __restrict__ out) {
    __shared__ float f_s[64][65];
    __shared__ float Gi[4][384];
    __shared__ int cid_s[64];
    __shared__ float s_fc1W[36], s_fc1b[6], s_bilb[6];
    int b = blockIdx.x, it = blockIdx.y, t = threadIdx.x;
    const float* x = g_x[buf];
    if (t < 64) cid_s[t] = cidx[b * 64 + t];
    if (t < 36) s_fc1W[t] = fc1_W[t];
    if (t >= 64 && t < 70) s_fc1b[t - 64] = fc1_b[t - 64];
    if (t >= 96 && t < 102) s_bilb[t - 96] = bil_b[t - 96];
    __syncthreads();
    for (int e = t; e < 4096; e += 256) {
        int m = e >> 6, k = e & 63;
        f_s[m][k] = x[cid_s[m] * DIM + k];
    }
    for (int e = t; e < 1536; e += 256) {
        int i4 = e / 384, ok = e % 384;
        Gi[i4][ok] = g_G[(long)(b * 64 + it * 4 + i4) * 384 + ok];
    }
    __syncthreads();
    int i4 = t >> 6, j = t & 63;
    float ev[6];
#pragma unroll
    for (int o = 0; o < 6; o++) {
        float a = s_bilb[o];
#pragma unroll 16
        for (int k = 0; k < 64; k++) a = fmaf(Gi[i4][o * 64 + k], f_s[j][k], a);
        ev[o] = a;
    }
    float tr[6];
#pragma unroll
    for (int r = 0; r < 6; r++) {
        float a = s_fc1b[r];
#pragma unroll
        for (int o = 0; o < 6; o++) a = fmaf(s_fc1W[r * 6 + o], ev[o], a);
        tr[r] = a;
    }
    float mx = tr[0];
#pragma unroll
    for (int r = 1; r < 6; r++) mx = fmaxf(mx, tr[r]);
    float se = 0.f;
#pragma unroll
    for (int r = 0; r < 6; r++) se += expf(tr[r] - mx);
    float lse = mx + logf(se);
    int pair = (it * 4 + i4) * 64 + j;
    float* op = out + ((long)b * 4096 + pair) * 6;
#pragma unroll
    for (int r = 0; r < 6; r++) op[r] = tr[r] - lse;
}

// ---------------- atom_out = f @ fca_W^T + fca_b ----------------
__global__ __launch_bounds__(96) void atomout_kernel(int buf, const int* __restrict__ cidx,
                                                     const float* __restrict__ fca_b,
                                                     float* __restrict__ out2) {
    __shared__ float xr[64];
    int t = threadIdx.x;
    int r = blockIdx.x;
    int atom = cidx[r];
    if (t < 64) xr[t] = g_x[buf][atom * DIM + t];
    __syncthreads();
    if (t < ORIG) {
        float a = fca_b[t];
#pragma unroll 16
        for (int k = 0; k < 64; k++) a = fmaf(xr[k], g_fcaT[k * ORIG + t], a);
        out2[(long)r * ORIG + t] = a;
    }
}

// ---------------- launch ----------------
#define ZS_SM ((64 * TWO_D + 64 * 64) * 4)

extern "C" void kernel_launch(void* const* d_in, const int* in_sizes, int n_in,
                              void* d_out, int out_size) {
    (void)in_sizes; (void)n_in; (void)out_size;
    const float* atom_fea = (const float*)d_in[0];
    const float* nbr_fea  = (const float*)d_in[1];
    const int*   nbr_idx  = (const int*)d_in[2];
    const int*   cidx     = (const int*)d_in[3];
    const float* embed_W  = (const float*)d_in[4];
    const float* conv_W   = (const float*)d_in[5];
    const float* conv_b   = (const float*)d_in[6];
    const float* bn1_g    = (const float*)d_in[7];
    const float* bn1_b    = (const float*)d_in[8];
    const float* bn2_g    = (const float*)d_in[9];
    const float* bn2_b    = (const float*)d_in[10];
    const float* bil_W    = (const float*)d_in[11];
    const float* bil_b    = (const float*)d_in[12];
    const float* fc1_W    = (const float*)d_in[13];
    const float* fc1_b    = (const float*)d_in[14];
    const float* fca_W    = (const float*)d_in[15];
    const float* fca_b    = (const float*)d_in[16];
    float* out = (float*)d_out;

    cudaFuncSetAttribute(zself_kernel, cudaFuncAttributeMaxDynamicSharedMemorySize, ZS_SM);
    cudaFuncSetAttribute(gmat_kernel,  cudaFuncAttributeMaxDynamicSharedMemorySize, ZS_SM);

    int prep_elems = 3 * 64 * TWO_D + 3 * 56 * TWO_D + ORIG * DIM + DIM * 384 +
                     DIM * ORIG + TWO_D + DIM;
    prep_kernel<<<(prep_elems + 255) / 256, 256>>>(conv_W, embed_W, bil_W, fca_W);
    embed_kernel<<<NATOM / 64, 256>>>(atom_fea);

    int buf = 0;
    for (int l = 0; l < 3; l++) {
        if (l > 0) zero_stats<<<1, 128>>>();
        zself_kernel<<<NATOM / 64, 256, ZS_SM>>>(l, buf, conv_b);
        convz_kernel<<<NATOM * MNBR / 64, 256, CZ_SMEM>>>(l, buf, nbr_fea, nbr_idx);
        reduce_kernel<<<NATOM / 16, 256>>>(l, bn1_g, bn1_b);
        bnres_kernel<<<(NATOM * DIM) / 256, 256>>>(l, buf, bn2_g, bn2_b);
        buf = 1 - buf;
    }

    gmat_kernel<<<dim3(NCRY * NA / 64, 3), 256, ZS_SM>>>(buf, cidx);
    edge_kernel<<<dim3(NCRY, 16), 256>>>(buf, cidx, bil_b, fc1_W, fc1_b, out);
    atomout_kernel<<<NCRY * NA, 96>>>(buf, cidx, fca_b, out + (long)NCRY * NA * NA * 6);
}

// round 8
// speedup vs baseline: 1.6365x; 1.0431x over previous
#include <cuda_runtime.h>
#include <cuda_fp16.h>
#include <math.h>
#include <stdint.h>

#define NATOM 32768
#define MNBR 12
#define DIM 64
#define FNBR 41
#define ORIG 92
#define TWO_D 128
#define KTOT 169
#define NCRY 512
#define NA 64
#define CNT1F (393216.0f)
#define CNT2F (32768.0f)
#define EPSBN 1e-5f

#define K2N 88          // u32 (half2) count per B row: K=170 padded to 176 halves
#define AP 92           // A smem pitch in u32
#define BP 92           // B smem pitch in u32
#define NKS 11          // k-steps of 16

// ---------------- scratch (device globals; no allocation) ----------------
__device__ float g_x[2][NATOM * DIM];
__device__ uint32_t g_z[NATOM * MNBR * 64];          // z as half2, 100 MB
__device__ float g_summed[NATOM * DIM];
__device__ float g_G[NCRY * NA * 384];               // 50 MB
__device__ uint32_t g_WnH[3 * TWO_D * K2N];          // fused W half2 [l][n][k2]
__device__ float g_embT[ORIG * DIM];                 // [k][d]
__device__ float g_bilT[DIM * 6 * DIM];              // [d][o*64+k]
__device__ float g_fcaT[DIM * ORIG];                 // [k][c]
__device__ float g_s1[TWO_D], g_ss1[TWO_D], g_s2[DIM], g_ss2[DIM];

__device__ __forceinline__ float softplusf(float v) {
    return v > 20.0f ? v : log1pf(expf(v));
}
__device__ __forceinline__ void mma_f16(float* c, const uint32_t* a, const uint32_t* b) {
    asm volatile(
        "mma.sync.aligned.m16n8k16.row.col.f32.f16.f16.f32 "
        "{%0,%1,%2,%3}, {%4,%5,%6,%7}, {%8,%9}, {%0,%1,%2,%3};"
        : "+f"(c[0]), "+f"(c[1]), "+f"(c[2]), "+f"(c[3])
        : "r"(a[0]), "r"(a[1]), "r"(a[2]), "r"(a[3]), "r"(b[0]), "r"(b[1]));
}
__device__ __forceinline__ void ldsm4(uint32_t* r, uint32_t addr) {
    asm volatile("ldmatrix.sync.aligned.m8n8.x4.shared.b16 {%0,%1,%2,%3}, [%4];"
                 : "=r"(r[0]), "=r"(r[1]), "=r"(r[2]), "=r"(r[3]) : "r"(addr));
}

// ---------------- prep: fused weight layout + stat zeroing ----------------
__global__ void prep_kernel(const float* __restrict__ conv_W,
                            const float* __restrict__ conv_b,
                            const float* __restrict__ embed_W,
                            const float* __restrict__ bil_W,
                            const float* __restrict__ fca_W) {
    int idx = blockIdx.x * blockDim.x + threadIdx.x;
    if (idx < 3 * TWO_D * K2N) {                      // g_WnH [l][n][j]
        int l = idx / (TWO_D * K2N), r = idx % (TWO_D * K2N);
        int n = r / K2N, j = r % K2N;
        int k0 = 2 * j, k1 = 2 * j + 1;
        const float* wr = conv_W + (l * TWO_D + n) * KTOT;
        float a = (k0 < KTOT) ? wr[k0] : (k0 == KTOT ? conv_b[l * TWO_D + n] : 0.f);
        float b = (k1 < KTOT) ? wr[k1] : (k1 == KTOT ? conv_b[l * TWO_D + n] : 0.f);
        __half2 h = __floats2half2_rn(a, b);
        g_WnH[idx] = *(uint32_t*)&h;
        return;
    }
    int i2 = idx - 3 * TWO_D * K2N;
    if (i2 < ORIG * DIM) {                            // g_embT [k][d]
        int k = i2 / DIM, d = i2 % DIM;
        g_embT[i2] = embed_W[d * ORIG + k];
        return;
    }
    int i3 = i2 - ORIG * DIM;
    if (i3 < DIM * 6 * DIM) {                         // g_bilT [d][o*64+k]
        int d = i3 / 384, ok = i3 % 384;
        int o = ok >> 6, k2 = ok & 63;
        g_bilT[i3] = bil_W[(o * DIM + d) * DIM + k2];
        return;
    }
    int i4 = i3 - DIM * 6 * DIM;
    if (i4 < DIM * ORIG) {
        int k = i4 / ORIG, c = i4 % ORIG;
        g_fcaT[i4] = fca_W[c * DIM + k];
        return;
    }
    int i5 = i4 - DIM * ORIG;
    if (i5 < TWO_D) { g_s1[i5] = 0.f; g_ss1[i5] = 0.f; return; }
    int i6 = i5 - TWO_D;
    if (i6 < DIM) { g_s2[i6] = 0.f; g_ss2[i6] = 0.f; }
}

// ---------------- embedding: x = atom_fea @ embed_W^T  (K=92) ----------------
__global__ __launch_bounds__(256) void embed_kernel(const float* __restrict__ atom_fea) {
    __shared__ float As[64 * ORIG];
    __shared__ float Ws[ORIG * DIM];
    int t = threadIdx.x;
    int rb = blockIdx.x * 64;
    for (int e = t; e < ORIG * DIM; e += 256) Ws[e] = g_embT[e];
    int warp = t >> 5, lane = t & 31;
    for (int m = warp; m < 64; m += 8) {
        const float* row = atom_fea + (rb + m) * ORIG;
        As[m * ORIG + lane] = row[lane];
        As[m * ORIG + 32 + lane] = row[32 + lane];
        if (lane < ORIG - 64) As[m * ORIG + 64 + lane] = row[64 + lane];
    }
    __syncthreads();
    int ty = t >> 5, tx = t & 31;
    float acc[8][2];
#pragma unroll
    for (int i = 0; i < 8; i++) { acc[i][0] = 0.f; acc[i][1] = 0.f; }
    for (int k = 0; k < ORIG; k++) {
        float2 b = *(const float2*)&Ws[k * DIM + tx * 2];
#pragma unroll
        for (int i = 0; i < 8; i++) {
            float a = As[(ty * 8 + i) * ORIG + k];
            acc[i][0] = fmaf(a, b.x, acc[i][0]);
            acc[i][1] = fmaf(a, b.y, acc[i][1]);
        }
    }
#pragma unroll
    for (int i = 0; i < 8; i++)
        *(float2*)&g_x[0][(rb + ty * 8 + i) * DIM + tx * 2] = make_float2(acc[i][0], acc[i][1]);
}

// ---------------- per-layer stat zeroing (layers 1,2) ----------------
__global__ void zero_stats() {
    int t = threadIdx.x;
    if (t < TWO_D) { g_s1[t] = 0.f; g_ss1[t] = 0.f; }
    if (t < DIM)   { g_s2[t] = 0.f; g_ss2[t] = 0.f; }
}

// ---------------- fused conv GEMM: z = [x_self|x_nbr|nbr_fea|1] @ Wfull, fp16 MMA ----------------
// Per CTA: 64 rows x 128 cols, K=176 (11 steps), ldmatrix fragment loads.
#define CZ_SMEM ((64 * AP + 128 * BP) * 4)

__global__ __launch_bounds__(256, 3) void convz_kernel(int l, int buf,
                                                       const float* __restrict__ nbr_fea,
                                                       const int* __restrict__ nbr_idx) {
    extern __shared__ uint32_t smu[];
    uint32_t* As2 = smu;               // [64][AP]
    uint32_t* Bs2 = smu + 64 * AP;     // [128][BP]
    __shared__ float redS[128], redQ[128];
    __shared__ int nbr_s[64];
    int t = threadIdx.x, w = t >> 5, lane = t & 31;
    int rb = blockIdx.x * 64;
    const float* x = g_x[buf];
    if (t < 64) nbr_s[t] = nbr_idx[rb + t];
    if (t < 128) { redS[t] = 0.f; redQ[t] = 0.f; }
    // B: copy fused weights [128][88] -> pitch BP
    {
        const uint32_t* src = g_WnH + l * TWO_D * K2N;
        for (int e = t; e < TWO_D * K2N; e += 256)
            Bs2[(e / K2N) * BP + (e % K2N)] = src[e];
    }
    __syncthreads();
    // A: gather [x_self | x_nbr | nbr_fea | 1 | pad] as half2
    for (int m = w; m < 64; m += 8) {
        uint32_t* Ar = As2 + m * AP;
        int nself = (rb + m) / MNBR;
        int nbr = nbr_s[m];
        float2 vs = ((const float2*)(x + nself * DIM))[lane];
        __half2 hs = __floats2half2_rn(vs.x, vs.y);
        Ar[lane] = *(uint32_t*)&hs;
        float2 vn = ((const float2*)(x + nbr * DIM))[lane];
        __half2 hn = __floats2half2_rn(vn.x, vn.y);
        Ar[32 + lane] = *(uint32_t*)&hn;
        if (lane < 20) {
            const float* nf = nbr_fea + (long)(rb + m) * FNBR;
            __half2 hh = __floats2half2_rn(nf[2 * lane], nf[2 * lane + 1]);
            Ar[64 + lane] = *(uint32_t*)&hh;
        } else if (lane == 20) {
            const float* nf = nbr_fea + (long)(rb + m) * FNBR;
            __half2 hh = __floats2half2_rn(nf[40], 1.0f);
            Ar[84] = *(uint32_t*)&hh;
        } else if (lane < 24) {
            Ar[64 + lane] = 0u;     // u32 85..87
        }
    }
    __syncthreads();

    int wm = w & 1, wn = w >> 1;             // wm 0..1 (32 rows), wn 0..3 (32 cols)
    int q = lane >> 2, r = lane & 3;

    uint32_t sAs = (uint32_t)__cvta_generic_to_shared(As2);
    uint32_t sBs = (uint32_t)__cvta_generic_to_shared(Bs2);
    uint32_t aAddr0 = sAs + (((wm * 32) + (lane & 7) + ((lane >> 3) & 1) * 8) * AP +
                             ((lane >> 4) & 1) * 4) * 4;
    uint32_t aAddr1 = aAddr0 + 16 * AP * 4;
    uint32_t bAddr0 = sBs + (((wn * 32) + (lane & 7) + ((lane >> 4) & 1) * 8) * BP +
                             ((lane >> 3) & 1) * 4) * 4;
    uint32_t bAddr1 = bAddr0 + 16 * BP * 4;

    float c[2][4][4];
#pragma unroll
    for (int mt = 0; mt < 2; mt++)
#pragma unroll
        for (int nf = 0; nf < 4; nf++)
#pragma unroll
            for (int e = 0; e < 4; e++) c[mt][nf][e] = 0.f;

#pragma unroll
    for (int ks = 0; ks < NKS; ks++) {
        uint32_t ko = ks * 32;               // 8 u32 per step
        uint32_t a[2][4], b01[4], b23[4];
        ldsm4(a[0], aAddr0 + ko);
        ldsm4(a[1], aAddr1 + ko);
        ldsm4(b01, bAddr0 + ko);
        ldsm4(b23, bAddr1 + ko);
        uint32_t bf[4][2] = {{b01[0], b01[1]}, {b01[2], b01[3]},
                             {b23[0], b23[1]}, {b23[2], b23[3]}};
#pragma unroll
        for (int mt = 0; mt < 2; mt++)
#pragma unroll
            for (int nf = 0; nf < 4; nf++)
                mma_f16(c[mt][nf], a[mt], bf[nf]);
    }

    // epilogue: half2 round-trip (stats on rounded values), store z fp16
#pragma unroll
    for (int nf = 0; nf < 4; nf++) {
        int cc = wn * 32 + nf * 8 + r * 2;
        float s0 = 0.f, s1 = 0.f, q0 = 0.f, q1 = 0.f;
#pragma unroll
        for (int mt = 0; mt < 2; mt++) {
            int m0 = wm * 32 + mt * 16 + q;
            int row0 = rb + m0, row1 = row0 + 8;
            __half2 h0 = __floats2half2_rn(c[mt][nf][0], c[mt][nf][1]);
            __half2 h1 = __floats2half2_rn(c[mt][nf][2], c[mt][nf][3]);
            g_z[(long)row0 * 64 + (cc >> 1)] = *(uint32_t*)&h0;
            g_z[(long)row1 * 64 + (cc >> 1)] = *(uint32_t*)&h1;
            float2 v0 = __half22float2(h0);
            float2 v1 = __half22float2(h1);
            s0 += v0.x + v1.x; q0 += v0.x * v0.x + v1.x * v1.x;
            s1 += v0.y + v1.y; q1 += v0.y * v0.y + v1.y * v1.y;
        }
#pragma unroll
        for (int off = 4; off < 32; off <<= 1) {
            s0 += __shfl_xor_sync(0xffffffffu, s0, off);
            s1 += __shfl_xor_sync(0xffffffffu, s1, off);
            q0 += __shfl_xor_sync(0xffffffffu, q0, off);
            q1 += __shfl_xor_sync(0xffffffffu, q1, off);
        }
        if (lane < 4) {
            atomicAdd(&redS[cc], s0);
            atomicAdd(&redS[cc + 1], s1);
            atomicAdd(&redQ[cc], q0);
            atomicAdd(&redQ[cc + 1], q1);
        }
    }
    __syncthreads();
    if (t < 128) {
        atomicAdd(&g_s1[t], redS[t]);
        atomicAdd(&g_ss1[t], redQ[t]);
    }
}

// ---------------- BN1 + gate + sum over neighbors (half2 z), BN2 stats ----------------
__global__ __launch_bounds__(256) void reduce_kernel(int l,
                                                     const float* __restrict__ bn1_g,
                                                     const float* __restrict__ bn1_b) {
    int c = threadIdx.x & 31, grp = threadIdx.x >> 5;
    int d0 = 2 * c;
    float inv = 1.0f / CNT1F;
    float mf0 = g_s1[d0] * inv, mf1 = g_s1[d0 + 1] * inv;
    float vf0 = g_ss1[d0] * inv - mf0 * mf0, vf1 = g_ss1[d0 + 1] * inv - mf1 * mf1;
    float scf0 = rsqrtf(vf0 + EPSBN) * bn1_g[l * TWO_D + d0];
    float scf1 = rsqrtf(vf1 + EPSBN) * bn1_g[l * TWO_D + d0 + 1];
    float shf0 = bn1_b[l * TWO_D + d0] - mf0 * scf0;
    float shf1 = bn1_b[l * TWO_D + d0 + 1] - mf1 * scf1;
    float mc0 = g_s1[64 + d0] * inv, mc1 = g_s1[64 + d0 + 1] * inv;
    float vc0 = g_ss1[64 + d0] * inv - mc0 * mc0, vc1 = g_ss1[64 + d0 + 1] * inv - mc1 * mc1;
    float scc0 = rsqrtf(vc0 + EPSBN) * bn1_g[l * TWO_D + 64 + d0];
    float scc1 = rsqrtf(vc1 + EPSBN) * bn1_g[l * TWO_D + 64 + d0 + 1];
    float shc0 = bn1_b[l * TWO_D + 64 + d0] - mc0 * scc0;
    float shc1 = bn1_b[l * TWO_D + 64 + d0 + 1] - mc1 * scc1;

    float ls0 = 0.f, ls1 = 0.f, lq0 = 0.f, lq1 = 0.f;
    int n0 = blockIdx.x * 16 + grp * 2;
    for (int a = 0; a < 2; a++) {
        int n = n0 + a;
        const uint32_t* zr = g_z + (long)n * MNBR * 64;
        float a0 = 0.f, a1 = 0.f;
#pragma unroll
        for (int m = 0; m < MNBR; m++) {
            uint32_t zfp = zr[m * 64 + c];
            uint32_t zcp = zr[m * 64 + 32 + c];
            float2 zf = __half22float2(*(__half2*)&zfp);
            float2 zc = __half22float2(*(__half2*)&zcp);
            float f0 = zf.x * scf0 + shf0, f1 = zf.y * scf1 + shf1;
            float c0v = zc.x * scc0 + shc0, c1v = zc.y * scc1 + shc1;
            a0 += softplusf(c0v) / (1.0f + expf(-f0));
            a1 += softplusf(c1v) / (1.0f + expf(-f1));
        }
        *(float2*)&g_summed[n * DIM + d0] = make_float2(a0, a1);
        ls0 += a0; lq0 += a0 * a0;
        ls1 += a1; lq1 += a1 * a1;
    }
    atomicAdd(&g_s2[d0], ls0);
    atomicAdd(&g_s2[d0 + 1], ls1);
    atomicAdd(&g_ss2[d0], lq0);
    atomicAdd(&g_ss2[d0 + 1], lq1);
}

// ---------------- BN2 + residual softplus -> x_out ----------------
__global__ __launch_bounds__(256) void bnres_kernel(int l, int buf,
                                                    const float* __restrict__ bn2_g,
                                                    const float* __restrict__ bn2_b) {
    int gid = blockIdx.x * 256 + threadIdx.x;
    int d = gid & 63;
    float inv = 1.0f / CNT2F;
    float m2 = g_s2[d] * inv;
    float v2 = g_ss2[d] * inv - m2 * m2;
    float sc = rsqrtf(v2 + EPSBN) * bn2_g[l * DIM + d];
    float sh = bn2_b[l * DIM + d] - m2 * sc;
    float v = g_x[buf][gid] + g_summed[gid] * sc + sh;
    g_x[1 - buf][gid] = softplusf(v);
}

// ---------------- G[bi, o*64+k] = f[bi,:] @ bilT  (K=64, scalar) ----------------
__global__ __launch_bounds__(256) void gmat_kernel(int buf, const int* __restrict__ cidx) {
    extern __shared__ float sm[];
    float* Ws = sm;                // [64][128]
    float* As = sm + 64 * TWO_D;   // [64][64]
    __shared__ int cid_s[64];
    int t = threadIdx.x;
    int rb = blockIdx.x * 64;
    int co = blockIdx.y * 128;
    const float* x = g_x[buf];
    if (t < 64) cid_s[t] = cidx[rb + t];
    for (int e = t; e < 64 * TWO_D; e += 256) {
        int k = e >> 7, oc = e & 127;
        Ws[e] = g_bilT[k * 384 + co + oc];
    }
    __syncthreads();
    int warp = t >> 5, lane = t & 31;
    for (int m = warp; m < 64; m += 8) {
        int a = cid_s[m];
        As[m * 64 + lane]      = x[a * DIM + lane];
        As[m * 64 + 32 + lane] = x[a * DIM + 32 + lane];
    }
    __syncthreads();
    int ty = t >> 5, tx = t & 31;
    float acc[8][4];
#pragma unroll
    for (int i = 0; i < 8; i++)
#pragma unroll
        for (int c = 0; c < 4; c++) acc[i][c] = 0.f;
    for (int k = 0; k < 64; k++) {
        float4 b = *(const float4*)&Ws[k * TWO_D + tx * 4];
#pragma unroll
        for (int i = 0; i < 8; i++) {
            float a = As[(ty * 8 + i) * 64 + k];
            acc[i][0] = fmaf(a, b.x, acc[i][0]);
            acc[i][1] = fmaf(a, b.y, acc[i][1]);
            acc[i][2] = fmaf(a, b.z, acc[i][2]);
            acc[i][3] = fmaf(a, b.w, acc[i][3]);
        }
    }
#pragma unroll
    for (int i = 0; i < 8; i++)
        *(float4*)&g_G[(long)(rb + ty * 8 + i) * 384 + co + tx * 4] =
            make_float4(acc[i][0], acc[i][1], acc[i][2], acc[i][3]);
}

// ---------------- edge: per-pair bilinear dot + fc1 + log_softmax ----------------
__global__ __launch_bounds__(256) void edge_kernel(int buf, const int* __restrict__ cidx,
                                                   const float* __restrict__ bil_b,
                                                   const float* __restrict__ fc1_W,
                                                   const float* __restrict__ fc1_b,
                                                   float* __restrict__ out) {
    __shared__ float f_s[64][65];
    __shared__ float Gi[4][384];
    __shared__ int cid_s[64];
    __shared__ float s_fc1W[36], s_fc1b[6], s_bilb[6];
    int b = blockIdx.x, it = blockIdx.y, t = threadIdx.x;
    const float* x = g_x[buf];
    if (t < 64) cid_s[t] = cidx[b * 64 + t];
    if (t < 36) s_fc1W[t] = fc1_W[t];
    if (t >= 64 && t < 70) s_fc1b[t - 64] = fc1_b[t - 64];
    if (t >= 96 && t < 102) s_bilb[t - 96] = bil_b[t - 96];
    __syncthreads();
    for (int e = t; e < 4096; e += 256) {
        int m = e >> 6, k = e & 63;
        f_s[m][k] = x[cid_s[m] * DIM + k];
    }
    for (int e = t; e < 1536; e += 256) {
        int i4 = e / 384, ok = e % 384;
        Gi[i4][ok] = g_G[(long)(b * 64 + it * 4 + i4) * 384 + ok];
    }
    __syncthreads();
    int i4 = t >> 6, j = t & 63;
    float ev[6];
#pragma unroll
    for (int o = 0; o < 6; o++) {
        float a = s_bilb[o];
#pragma unroll 16
        for (int k = 0; k < 64; k++) a = fmaf(Gi[i4][o * 64 + k], f_s[j][k], a);
        ev[o] = a;
    }
    float tr[6];
#pragma unroll
    for (int r = 0; r < 6; r++) {
        float a = s_fc1b[r];
#pragma unroll
        for (int o = 0; o < 6; o++) a = fmaf(s_fc1W[r * 6 + o], ev[o], a);
        tr[r] = a;
    }
    float mx = tr[0];
#pragma unroll
    for (int r = 1; r < 6; r++) mx = fmaxf(mx, tr[r]);
    float se = 0.f;
#pragma unroll
    for (int r = 0; r < 6; r++) se += expf(tr[r] - mx);
    float lse = mx + logf(se);
    int pair = (it * 4 + i4) * 64 + j;
    float* op = out + ((long)b * 4096 + pair) * 6;
#pragma unroll
    for (int r = 0; r < 6; r++) op[r] = tr[r] - lse;
}

// ---------------- atom_out = f @ fca_W^T + fca_b ----------------
__global__ __launch_bounds__(96) void atomout_kernel(int buf, const int* __restrict__ cidx,
                                                     const float* __restrict__ fca_b,
                                                     float* __restrict__ out2) {
    __shared__ float xr[64];
    int t = threadIdx.x;
    int r = blockIdx.x;
    int atom = cidx[r];
    if (t < 64) xr[t] = g_x[buf][atom * DIM + t];
    __syncthreads();
    if (t < ORIG) {
        float a = fca_b[t];
#pragma unroll 16
        for (int k = 0; k < 64; k++) a = fmaf(xr[k], g_fcaT[k * ORIG + t], a);
        out2[(long)r * ORIG + t] = a;
    }
}

// ---------------- launch ----------------
#define ZS_SM ((64 * TWO_D + 64 * 64) * 4)

extern "C" void kernel_launch(void* const* d_in, const int* in_sizes, int n_in,
                              void* d_out, int out_size) {
    (void)in_sizes; (void)n_in; (void)out_size;
    const float* atom_fea = (const float*)d_in[0];
    const float* nbr_fea  = (const float*)d_in[1];
    const int*   nbr_idx  = (const int*)d_in[2];
    const int*   cidx     = (const int*)d_in[3];
    const float* embed_W  = (const float*)d_in[4];
    const float* conv_W   = (const float*)d_in[5];
    const float* conv_b   = (const float*)d_in[6];
    const float* bn1_g    = (const float*)d_in[7];
    const float* bn1_b    = (const float*)d_in[8];
    const float* bn2_g    = (const float*)d_in[9];
    const float* bn2_b    = (const float*)d_in[10];
    const float* bil_W    = (const float*)d_in[11];
    const float* bil_b    = (const float*)d_in[12];
    const float* fc1_W    = (const float*)d_in[13];
    const float* fc1_b    = (const float*)d_in[14];
    const float* fca_W    = (const float*)d_in[15];
    const float* fca_b    = (const float*)d_in[16];
    float* out = (float*)d_out;

    cudaFuncSetAttribute(convz_kernel, cudaFuncAttributeMaxDynamicSharedMemorySize, CZ_SMEM);
    cudaFuncSetAttribute(gmat_kernel,  cudaFuncAttributeMaxDynamicSharedMemorySize, ZS_SM);

    int prep_elems = 3 * TWO_D * K2N + ORIG * DIM + DIM * 384 + DIM * ORIG + TWO_D + DIM;
    prep_kernel<<<(prep_elems + 255) / 256, 256>>>(conv_W, conv_b, embed_W, bil_W, fca_W);
    embed_kernel<<<NATOM / 64, 256>>>(atom_fea);

    int buf = 0;
    for (int l = 0; l < 3; l++) {
        if (l > 0) zero_stats<<<1, 128>>>();
        convz_kernel<<<NATOM * MNBR / 64, 256, CZ_SMEM>>>(l, buf, nbr_fea, nbr_idx);
        reduce_kernel<<<NATOM / 16, 256>>>(l, bn1_g, bn1_b);
        bnres_kernel<<<(NATOM * DIM) / 256, 256>>>(l, buf, bn2_g, bn2_b);
        buf = 1 - buf;
    }

    gmat_kernel<<<dim3(NCRY * NA / 64, 3), 256, ZS_SM>>>(buf, cidx);
    edge_kernel<<<dim3(NCRY, 16), 256>>>(buf, cidx, bil_b, fc1_W, fc1_b, out);
    atomout_kernel<<<NCRY * NA, 96>>>(buf, cidx, fca_b, out + (long)NCRY * NA * NA * 6);
}

// round 9
// speedup vs baseline: 1.6897x; 1.0325x over previous
#include <cuda_runtime.h>
#include <cuda_fp16.h>
#include <math.h>
#include <stdint.h>

#define NATOM 32768
#define MNBR 12
#define DIM 64
#define FNBR 41
#define ORIG 92
#define TWO_D 128
#define KTOT 169
#define NCRY 512
#define NA 64
#define CNT1F (393216.0f)
#define CNT2F (32768.0f)
#define EPSBN 1e-5f

#define K2N 88          // u32 (half2) count per B row: K=170 padded to 176 halves
#define AP 92           // A smem pitch in u32
#define BP 92           // B smem pitch in u32
#define NKS 11          // k-steps of 16

// ---------------- scratch (device globals; no allocation) ----------------
__device__ float g_x[2][NATOM * DIM];
__device__ uint32_t g_z[NATOM * MNBR * 64];          // z as half2, 100 MB
__device__ float g_summed[NATOM * DIM];
__device__ float g_G[NCRY * NA * 384];               // 50 MB
__device__ uint32_t g_WnH[3 * TWO_D * K2N];          // fused W half2 [l][n][k2]
__device__ float g_embT[ORIG * DIM];                 // [k][d]
__device__ float g_bilT[DIM * 6 * DIM];              // [d][o*64+k]
__device__ float g_fcaT[DIM * ORIG];                 // [k][c]
__device__ float g_s1[TWO_D], g_ss1[TWO_D], g_s2[DIM], g_ss2[DIM];

__device__ __forceinline__ float softplusf(float v) {
    return v > 20.0f ? v : log1pf(expf(v));
}
// fast softplus * sigmoid gate (approx intrinsics; err ~1e-6 rel, far below fp16 z noise)
__device__ __forceinline__ float gatef(float fv, float cv) {
    float sp = (cv > 15.0f) ? cv : __logf(1.0f + __expf(cv));
    return __fdividef(sp, 1.0f + __expf(-fv));
}
__device__ __forceinline__ void mma_f16(float* c, const uint32_t* a, const uint32_t* b) {
    asm volatile(
        "mma.sync.aligned.m16n8k16.row.col.f32.f16.f16.f32 "
        "{%0,%1,%2,%3}, {%4,%5,%6,%7}, {%8,%9}, {%0,%1,%2,%3};"
        : "+f"(c[0]), "+f"(c[1]), "+f"(c[2]), "+f"(c[3])
        : "r"(a[0]), "r"(a[1]), "r"(a[2]), "r"(a[3]), "r"(b[0]), "r"(b[1]));
}
__device__ __forceinline__ void ldsm4(uint32_t* r, uint32_t addr) {
    asm volatile("ldmatrix.sync.aligned.m8n8.x4.shared.b16 {%0,%1,%2,%3}, [%4];"
                 : "=r"(r[0]), "=r"(r[1]), "=r"(r[2]), "=r"(r[3]) : "r"(addr));
}

// ---------------- prep: fused weight layout + stat zeroing ----------------
__global__ void prep_kernel(const float* __restrict__ conv_W,
                            const float* __restrict__ conv_b,
                            const float* __restrict__ embed_W,
                            const float* __restrict__ bil_W,
                            const float* __restrict__ fca_W) {
    int idx = blockIdx.x * blockDim.x + threadIdx.x;
    if (idx < 3 * TWO_D * K2N) {                      // g_WnH [l][n][j]
        int l = idx / (TWO_D * K2N), r = idx % (TWO_D * K2N);
        int n = r / K2N, j = r % K2N;
        int k0 = 2 * j, k1 = 2 * j + 1;
        const float* wr = conv_W + (l * TWO_D + n) * KTOT;
        float a = (k0 < KTOT) ? wr[k0] : (k0 == KTOT ? conv_b[l * TWO_D + n] : 0.f);
        float b = (k1 < KTOT) ? wr[k1] : (k1 == KTOT ? conv_b[l * TWO_D + n] : 0.f);
        __half2 h = __floats2half2_rn(a, b);
        g_WnH[idx] = *(uint32_t*)&h;
        return;
    }
    int i2 = idx - 3 * TWO_D * K2N;
    if (i2 < ORIG * DIM) {                            // g_embT [k][d]
        int k = i2 / DIM, d = i2 % DIM;
        g_embT[i2] = embed_W[d * ORIG + k];
        return;
    }
    int i3 = i2 - ORIG * DIM;
    if (i3 < DIM * 6 * DIM) {                         // g_bilT [d][o*64+k]
        int d = i3 / 384, ok = i3 % 384;
        int o = ok >> 6, k2 = ok & 63;
        g_bilT[i3] = bil_W[(o * DIM + d) * DIM + k2];
        return;
    }
    int i4 = i3 - DIM * 6 * DIM;
    if (i4 < DIM * ORIG) {
        int k = i4 / ORIG, c = i4 % ORIG;
        g_fcaT[i4] = fca_W[c * DIM + k];
        return;
    }
    int i5 = i4 - DIM * ORIG;
    if (i5 < TWO_D) { g_s1[i5] = 0.f; g_ss1[i5] = 0.f; return; }
    int i6 = i5 - TWO_D;
    if (i6 < DIM) { g_s2[i6] = 0.f; g_ss2[i6] = 0.f; }
}

// ---------------- embedding: x = atom_fea @ embed_W^T  (K=92) ----------------
__global__ __launch_bounds__(256) void embed_kernel(const float* __restrict__ atom_fea) {
    __shared__ float As[64 * ORIG];
    __shared__ float Ws[ORIG * DIM];
    int t = threadIdx.x;
    int rb = blockIdx.x * 64;
    for (int e = t; e < ORIG * DIM; e += 256) Ws[e] = g_embT[e];
    int warp = t >> 5, lane = t & 31;
    for (int m = warp; m < 64; m += 8) {
        const float* row = atom_fea + (rb + m) * ORIG;
        As[m * ORIG + lane] = row[lane];
        As[m * ORIG + 32 + lane] = row[32 + lane];
        if (lane < ORIG - 64) As[m * ORIG + 64 + lane] = row[64 + lane];
    }
    __syncthreads();
    int ty = t >> 5, tx = t & 31;
    float acc[8][2];
#pragma unroll
    for (int i = 0; i < 8; i++) { acc[i][0] = 0.f; acc[i][1] = 0.f; }
    for (int k = 0; k < ORIG; k++) {
        float2 b = *(const float2*)&Ws[k * DIM + tx * 2];
#pragma unroll
        for (int i = 0; i < 8; i++) {
            float a = As[(ty * 8 + i) * ORIG + k];
            acc[i][0] = fmaf(a, b.x, acc[i][0]);
            acc[i][1] = fmaf(a, b.y, acc[i][1]);
        }
    }
#pragma unroll
    for (int i = 0; i < 8; i++)
        *(float2*)&g_x[0][(rb + ty * 8 + i) * DIM + tx * 2] = make_float2(acc[i][0], acc[i][1]);
}

// ---------------- per-layer stat zeroing (layers 1,2) ----------------
__global__ void zero_stats() {
    int t = threadIdx.x;
    if (t < TWO_D) { g_s1[t] = 0.f; g_ss1[t] = 0.f; }
    if (t < DIM)   { g_s2[t] = 0.f; g_ss2[t] = 0.f; }
}

// ---------------- fused conv GEMM: z = [x_self|x_nbr|nbr_fea|1] @ Wfull, fp16 MMA ----------------
#define CZ_SMEM ((64 * AP + 128 * BP) * 4)

__global__ __launch_bounds__(256, 3) void convz_kernel(int l, int buf,
                                                       const float* __restrict__ nbr_fea,
                                                       const int* __restrict__ nbr_idx) {
    extern __shared__ uint32_t smu[];
    uint32_t* As2 = smu;               // [64][AP]
    uint32_t* Bs2 = smu + 64 * AP;     // [128][BP]
    __shared__ float redS[128], redQ[128];
    __shared__ int nbr_s[64];
    int t = threadIdx.x, w = t >> 5, lane = t & 31;
    int rb = blockIdx.x * 64;
    const float* x = g_x[buf];
    if (t < 64) nbr_s[t] = nbr_idx[rb + t];
    if (t < 128) { redS[t] = 0.f; redQ[t] = 0.f; }
    // B: copy fused weights [128][88] -> pitch BP
    {
        const uint32_t* src = g_WnH + l * TWO_D * K2N;
        for (int e = t; e < TWO_D * K2N; e += 256)
            Bs2[(e / K2N) * BP + (e % K2N)] = src[e];
    }
    __syncthreads();
    // A: gather [x_self | x_nbr | nbr_fea | 1 | pad] as half2
    for (int m = w; m < 64; m += 8) {
        uint32_t* Ar = As2 + m * AP;
        int nself = (rb + m) / MNBR;
        int nbr = nbr_s[m];
        float2 vs = ((const float2*)(x + nself * DIM))[lane];
        __half2 hs = __floats2half2_rn(vs.x, vs.y);
        Ar[lane] = *(uint32_t*)&hs;
        float2 vn = ((const float2*)(x + nbr * DIM))[lane];
        __half2 hn = __floats2half2_rn(vn.x, vn.y);
        Ar[32 + lane] = *(uint32_t*)&hn;
        if (lane < 20) {
            const float* nf = nbr_fea + (long)(rb + m) * FNBR;
            __half2 hh = __floats2half2_rn(nf[2 * lane], nf[2 * lane + 1]);
            Ar[64 + lane] = *(uint32_t*)&hh;
        } else if (lane == 20) {
            const float* nf = nbr_fea + (long)(rb + m) * FNBR;
            __half2 hh = __floats2half2_rn(nf[40], 1.0f);
            Ar[84] = *(uint32_t*)&hh;
        } else if (lane < 24) {
            Ar[64 + lane] = 0u;     // u32 85..87
        }
    }
    __syncthreads();

    int wm = w & 1, wn = w >> 1;             // wm 0..1 (32 rows), wn 0..3 (32 cols)
    int q = lane >> 2, r = lane & 3;

    uint32_t sAs = (uint32_t)__cvta_generic_to_shared(As2);
    uint32_t sBs = (uint32_t)__cvta_generic_to_shared(Bs2);
    uint32_t aAddr0 = sAs + (((wm * 32) + (lane & 7) + ((lane >> 3) & 1) * 8) * AP +
                             ((lane >> 4) & 1) * 4) * 4;
    uint32_t aAddr1 = aAddr0 + 16 * AP * 4;
    uint32_t bAddr0 = sBs + (((wn * 32) + (lane & 7) + ((lane >> 4) & 1) * 8) * BP +
                             ((lane >> 3) & 1) * 4) * 4;
    uint32_t bAddr1 = bAddr0 + 16 * BP * 4;

    float c[2][4][4];
#pragma unroll
    for (int mt = 0; mt < 2; mt++)
#pragma unroll
        for (int nf = 0; nf < 4; nf++)
#pragma unroll
            for (int e = 0; e < 4; e++) c[mt][nf][e] = 0.f;

#pragma unroll
    for (int ks = 0; ks < NKS; ks++) {
        uint32_t ko = ks * 32;               // 8 u32 per step
        uint32_t a[2][4], b01[4], b23[4];
        ldsm4(a[0], aAddr0 + ko);
        ldsm4(a[1], aAddr1 + ko);
        ldsm4(b01, bAddr0 + ko);
        ldsm4(b23, bAddr1 + ko);
        uint32_t bf[4][2] = {{b01[0], b01[1]}, {b01[2], b01[3]},
                             {b23[0], b23[1]}, {b23[2], b23[3]}};
#pragma unroll
        for (int mt = 0; mt < 2; mt++)
#pragma unroll
            for (int nf = 0; nf < 4; nf++)
                mma_f16(c[mt][nf], a[mt], bf[nf]);
    }

    // epilogue: half2 round-trip (stats on rounded values), store z fp16
#pragma unroll
    for (int nf = 0; nf < 4; nf++) {
        int cc = wn * 32 + nf * 8 + r * 2;
        float s0 = 0.f, s1 = 0.f, q0 = 0.f, q1 = 0.f;
#pragma unroll
        for (int mt = 0; mt < 2; mt++) {
            int m0 = wm * 32 + mt * 16 + q;
            int row0 = rb + m0, row1 = row0 + 8;
            __half2 h0 = __floats2half2_rn(c[mt][nf][0], c[mt][nf][1]);
            __half2 h1 = __floats2half2_rn(c[mt][nf][2], c[mt][nf][3]);
            g_z[(long)row0 * 64 + (cc >> 1)] = *(uint32_t*)&h0;
            g_z[(long)row1 * 64 + (cc >> 1)] = *(uint32_t*)&h1;
            float2 v0 = __half22float2(h0);
            float2 v1 = __half22float2(h1);
            s0 += v0.x + v1.x; q0 += v0.x * v0.x + v1.x * v1.x;
            s1 += v0.y + v1.y; q1 += v0.y * v0.y + v1.y * v1.y;
        }
#pragma unroll
        for (int off = 4; off < 32; off <<= 1) {
            s0 += __shfl_xor_sync(0xffffffffu, s0, off);
            s1 += __shfl_xor_sync(0xffffffffu, s1, off);
            q0 += __shfl_xor_sync(0xffffffffu, q0, off);
            q1 += __shfl_xor_sync(0xffffffffu, q1, off);
        }
        if (lane < 4) {
            atomicAdd(&redS[cc], s0);
            atomicAdd(&redS[cc + 1], s1);
            atomicAdd(&redQ[cc], q0);
            atomicAdd(&redQ[cc + 1], q1);
        }
    }
    __syncthreads();
    if (t < 128) {
        atomicAdd(&g_s1[t], redS[t]);
        atomicAdd(&g_ss1[t], redQ[t]);
    }
}

// ---------------- BN1 + gate + sum over neighbors (half2 z), BN2 stats ----------------
__global__ __launch_bounds__(256) void reduce_kernel(int l,
                                                     const float* __restrict__ bn1_g,
                                                     const float* __restrict__ bn1_b) {
    int c = threadIdx.x & 31, grp = threadIdx.x >> 5;
    int d0 = 2 * c;
    float inv = 1.0f / CNT1F;
    float mf0 = g_s1[d0] * inv, mf1 = g_s1[d0 + 1] * inv;
    float vf0 = g_ss1[d0] * inv - mf0 * mf0, vf1 = g_ss1[d0 + 1] * inv - mf1 * mf1;
    float scf0 = rsqrtf(vf0 + EPSBN) * bn1_g[l * TWO_D + d0];
    float scf1 = rsqrtf(vf1 + EPSBN) * bn1_g[l * TWO_D + d0 + 1];
    float shf0 = bn1_b[l * TWO_D + d0] - mf0 * scf0;
    float shf1 = bn1_b[l * TWO_D + d0 + 1] - mf1 * scf1;
    float mc0 = g_s1[64 + d0] * inv, mc1 = g_s1[64 + d0 + 1] * inv;
    float vc0 = g_ss1[64 + d0] * inv - mc0 * mc0, vc1 = g_ss1[64 + d0 + 1] * inv - mc1 * mc1;
    float scc0 = rsqrtf(vc0 + EPSBN) * bn1_g[l * TWO_D + 64 + d0];
    float scc1 = rsqrtf(vc1 + EPSBN) * bn1_g[l * TWO_D + 64 + d0 + 1];
    float shc0 = bn1_b[l * TWO_D + 64 + d0] - mc0 * scc0;
    float shc1 = bn1_b[l * TWO_D + 64 + d0 + 1] - mc1 * scc1;

    float ls0 = 0.f, ls1 = 0.f, lq0 = 0.f, lq1 = 0.f;
    int n0 = blockIdx.x * 16 + grp * 2;
    for (int a = 0; a < 2; a++) {
        int n = n0 + a;
        const uint32_t* zr = g_z + (long)n * MNBR * 64;
        float a0 = 0.f, a1 = 0.f;
#pragma unroll
        for (int m = 0; m < MNBR; m++) {
            uint32_t zfp = zr[m * 64 + c];
            uint32_t zcp = zr[m * 64 + 32 + c];
            float2 zf = __half22float2(*(__half2*)&zfp);
            float2 zc = __half22float2(*(__half2*)&zcp);
            a0 += gatef(zf.x * scf0 + shf0, zc.x * scc0 + shc0);
            a1 += gatef(zf.y * scf1 + shf1, zc.y * scc1 + shc1);
        }
        *(float2*)&g_summed[n * DIM + d0] = make_float2(a0, a1);
        ls0 += a0; lq0 += a0 * a0;
        ls1 += a1; lq1 += a1 * a1;
    }
    atomicAdd(&g_s2[d0], ls0);
    atomicAdd(&g_s2[d0 + 1], ls1);
    atomicAdd(&g_ss2[d0], lq0);
    atomicAdd(&g_ss2[d0 + 1], lq1);
}

// ---------------- BN2 + residual softplus -> x_out ----------------
__global__ __launch_bounds__(256) void bnres_kernel(int l, int buf,
                                                    const float* __restrict__ bn2_g,
                                                    const float* __restrict__ bn2_b) {
    int gid = blockIdx.x * 256 + threadIdx.x;
    int d = gid & 63;
    float inv = 1.0f / CNT2F;
    float m2 = g_s2[d] * inv;
    float v2 = g_ss2[d] * inv - m2 * m2;
    float sc = rsqrtf(v2 + EPSBN) * bn2_g[l * DIM + d];
    float sh = bn2_b[l * DIM + d] - m2 * sc;
    float v = g_x[buf][gid] + g_summed[gid] * sc + sh;
    g_x[1 - buf][gid] = (v > 15.0f) ? v : __logf(1.0f + __expf(v));
}

// ---------------- G[bi, o*64+k] = f[bi,:] @ bilT  (K=64, scalar) ----------------
__global__ __launch_bounds__(256) void gmat_kernel(int buf, const int* __restrict__ cidx) {
    extern __shared__ float sm[];
    float* Ws = sm;                // [64][128]
    float* As = sm + 64 * TWO_D;   // [64][64]
    __shared__ int cid_s[64];
    int t = threadIdx.x;
    int rb = blockIdx.x * 64;
    int co = blockIdx.y * 128;
    const float* x = g_x[buf];
    if (t < 64) cid_s[t] = cidx[rb + t];
    for (int e = t; e < 64 * TWO_D; e += 256) {
        int k = e >> 7, oc = e & 127;
        Ws[e] = g_bilT[k * 384 + co + oc];
    }
    __syncthreads();
    int warp = t >> 5, lane = t & 31;
    for (int m = warp; m < 64; m += 8) {
        int a = cid_s[m];
        As[m * 64 + lane]      = x[a * DIM + lane];
        As[m * 64 + 32 + lane] = x[a * DIM + 32 + lane];
    }
    __syncthreads();
    int ty = t >> 5, tx = t & 31;
    float acc[8][4];
#pragma unroll
    for (int i = 0; i < 8; i++)
#pragma unroll
        for (int c = 0; c < 4; c++) acc[i][c] = 0.f;
    for (int k = 0; k < 64; k++) {
        float4 b = *(const float4*)&Ws[k * TWO_D + tx * 4];
#pragma unroll
        for (int i = 0; i < 8; i++) {
            float a = As[(ty * 8 + i) * 64 + k];
            acc[i][0] = fmaf(a, b.x, acc[i][0]);
            acc[i][1] = fmaf(a, b.y, acc[i][1]);
            acc[i][2] = fmaf(a, b.z, acc[i][2]);
            acc[i][3] = fmaf(a, b.w, acc[i][3]);
        }
    }
#pragma unroll
    for (int i = 0; i < 8; i++)
        *(float4*)&g_G[(long)(rb + ty * 8 + i) * 384 + co + tx * 4] =
            make_float4(acc[i][0], acc[i][1], acc[i][2], acc[i][3]);
}

// ---------------- edge: per-pair bilinear dot + fc1 + log_softmax ----------------
__global__ __launch_bounds__(256) void edge_kernel(int buf, const int* __restrict__ cidx,
                                                   const float* __restrict__ bil_b,
                                                   const float* __restrict__ fc1_W,
                                                   const float* __restrict__ fc1_b,
                                                   float* __restrict__ out) {
    __shared__ float f_s[64][65];
    __shared__ float Gi[4][384];
    __shared__ int cid_s[64];
    __shared__ float s_fc1W[36], s_fc1b[6], s_bilb[6];
    int b = blockIdx.x, it = blockIdx.y, t = threadIdx.x;
    const float* x = g_x[buf];
    if (t < 64) cid_s[t] = cidx[b * 64 + t];
    if (t < 36) s_fc1W[t] = fc1_W[t];
    if (t >= 64 && t < 70) s_fc1b[t - 64] = fc1_b[t - 64];
    if (t >= 96 && t < 102) s_bilb[t - 96] = bil_b[t - 96];
    __syncthreads();
    for (int e = t; e < 4096; e += 256) {
        int m = e >> 6, k = e & 63;
        f_s[m][k] = x[cid_s[m] * DIM + k];
    }
    for (int e = t; e < 1536; e += 256) {
        int i4 = e / 384, ok = e % 384;
        Gi[i4][ok] = g_G[(long)(b * 64 + it * 4 + i4) * 384 + ok];
    }
    __syncthreads();
    int i4 = t >> 6, j = t & 63;
    float ev[6];
#pragma unroll
    for (int o = 0; o < 6; o++) {
        float a = s_bilb[o];
#pragma unroll 16
        for (int k = 0; k < 64; k++) a = fmaf(Gi[i4][o * 64 + k], f_s[j][k], a);
        ev[o] = a;
    }
    float tr[6];
#pragma unroll
    for (int r = 0; r < 6; r++) {
        float a = s_fc1b[r];
#pragma unroll
        for (int o = 0; o < 6; o++) a = fmaf(s_fc1W[r * 6 + o], ev[o], a);
        tr[r] = a;
    }
    float mx = tr[0];
#pragma unroll
    for (int r = 1; r < 6; r++) mx = fmaxf(mx, tr[r]);
    float se = 0.f;
#pragma unroll
    for (int r = 0; r < 6; r++) se += expf(tr[r] - mx);
    float lse = mx + logf(se);
    int pair = (it * 4 + i4) * 64 + j;
    float* op = out + ((long)b * 4096 + pair) * 6;
#pragma unroll
    for (int r = 0; r < 6; r++) op[r] = tr[r] - lse;
}

// ---------------- atom_out = f @ fca_W^T + fca_b ----------------
__global__ __launch_bounds__(96) void atomout_kernel(int buf, const int* __restrict__ cidx,
                                                     const float* __restrict__ fca_b,
                                                     float* __restrict__ out2) {
    __shared__ float xr[64];
    int t = threadIdx.x;
    int r = blockIdx.x;
    int atom = cidx[r];
    if (t < 64) xr[t] = g_x[buf][atom * DIM + t];
    __syncthreads();
    if (t < ORIG) {
        float a = fca_b[t];
#pragma unroll 16
        for (int k = 0; k < 64; k++) a = fmaf(xr[k], g_fcaT[k * ORIG + t], a);
        out2[(long)r * ORIG + t] = a;
    }
}

// ---------------- launch ----------------
#define ZS_SM ((64 * TWO_D + 64 * 64) * 4)

extern "C" void kernel_launch(void* const* d_in, const int* in_sizes, int n_in,
                              void* d_out, int out_size) {
    (void)in_sizes; (void)n_in; (void)out_size;
    const float* atom_fea = (const float*)d_in[0];
    const float* nbr_fea  = (const float*)d_in[1];
    const int*   nbr_idx  = (const int*)d_in[2];
    const int*   cidx     = (const int*)d_in[3];
    const float* embed_W  = (const float*)d_in[4];
    const float* conv_W   = (const float*)d_in[5];
    const float* conv_b   = (const float*)d_in[6];
    const float* bn1_g    = (const float*)d_in[7];
    const float* bn1_b    = (const float*)d_in[8];
    const float* bn2_g    = (const float*)d_in[9];
    const float* bn2_b    = (const float*)d_in[10];
    const float* bil_W    = (const float*)d_in[11];
    const float* bil_b    = (const float*)d_in[12];
    const float* fc1_W    = (const float*)d_in[13];
    const float* fc1_b    = (const float*)d_in[14];
    const float* fca_W    = (const float*)d_in[15];
    const float* fca_b    = (const float*)d_in[16];
    float* out = (float*)d_out;

    cudaFuncSetAttribute(convz_kernel, cudaFuncAttributeMaxDynamicSharedMemorySize, CZ_SMEM);
    cudaFuncSetAttribute(gmat_kernel,  cudaFuncAttributeMaxDynamicSharedMemorySize, ZS_SM);

    int prep_elems = 3 * TWO_D * K2N + ORIG * DIM + DIM * 384 + DIM * ORIG + TWO_D + DIM;
    prep_kernel<<<(prep_elems + 255) / 256, 256>>>(conv_W, conv_b, embed_W, bil_W, fca_W);
    embed_kernel<<<NATOM / 64, 256>>>(atom_fea);

    int buf = 0;
    for (int l = 0; l < 3; l++) {
        if (l > 0) zero_stats<<<1, 128>>>();
        convz_kernel<<<NATOM * MNBR / 64, 256, CZ_SMEM>>>(l, buf, nbr_fea, nbr_idx);
        reduce_kernel<<<NATOM / 16, 256>>>(l, bn1_g, bn1_b);
        bnres_kernel<<<(NATOM * DIM) / 256, 256>>>(l, buf, bn2_g, bn2_b);
        buf = 1 - buf;
    }

    gmat_kernel<<<dim3(NCRY * NA / 64, 3), 256, ZS_SM>>>(buf, cidx);
    edge_kernel<<<dim3(NCRY, 16), 256>>>(buf, cidx, bil_b, fc1_W, fc1_b, out);
    atomout_kernel<<<NCRY * NA, 96>>>(buf, cidx, fca_b, out + (long)NCRY * NA * NA * 6);
}

// round 10
// speedup vs baseline: 1.7073x; 1.0104x over previous
#include <cuda_runtime.h>
#include <cuda_fp16.h>
#include <math.h>
#include <stdint.h>

#define NATOM 32768
#define MNBR 12
#define DIM 64
#define FNBR 41
#define ORIG 92
#define TWO_D 128
#define KTOT 169
#define NCRY 512
#define NA 64
#define CNT1F (393216.0f)
#define CNT2F (32768.0f)
#define EPSBN 1e-5f

#define K2N 88          // u32 (half2) count per B row: K=170 padded to 176 halves
#define AP 92           // A smem pitch in u32
#define BP 92           // B smem pitch in u32
#define NKS 11          // k-steps of 16

// ---------------- scratch (device globals; no allocation) ----------------
__device__ float g_x[2][NATOM * DIM];
__device__ uint32_t g_z[NATOM * MNBR * 64];          // z as half2, 100 MB
__device__ float g_summed[NATOM * DIM];
__device__ float g_G[NCRY * NA * 384];               // 50 MB
__device__ uint32_t g_WnH[3 * TWO_D * K2N];          // fused W half2 [l][n][k2]
__device__ float g_embT[ORIG * DIM];                 // [k][d]
__device__ float g_bilT[DIM * 6 * DIM];              // [d][o*64+k]
__device__ float g_fcaT[DIM * ORIG];                 // [k][c]
__device__ float g_s1[TWO_D], g_ss1[TWO_D], g_s2[DIM], g_ss2[DIM];

__device__ __forceinline__ float softplusf(float v) {
    return v > 20.0f ? v : log1pf(expf(v));
}
// fast softplus * sigmoid gate (approx intrinsics; err ~1e-6 rel, far below fp16 z noise)
__device__ __forceinline__ float gatef(float fv, float cv) {
    float sp = (cv > 15.0f) ? cv : __logf(1.0f + __expf(cv));
    return __fdividef(sp, 1.0f + __expf(-fv));
}
__device__ __forceinline__ void mma_f16(float* c, const uint32_t* a, const uint32_t* b) {
    asm volatile(
        "mma.sync.aligned.m16n8k16.row.col.f32.f16.f16.f32 "
        "{%0,%1,%2,%3}, {%4,%5,%6,%7}, {%8,%9}, {%0,%1,%2,%3};"
        : "+f"(c[0]), "+f"(c[1]), "+f"(c[2]), "+f"(c[3])
        : "r"(a[0]), "r"(a[1]), "r"(a[2]), "r"(a[3]), "r"(b[0]), "r"(b[1]));
}
__device__ __forceinline__ void ldsm4(uint32_t* r, uint32_t addr) {
    asm volatile("ldmatrix.sync.aligned.m8n8.x4.shared.b16 {%0,%1,%2,%3}, [%4];"
                 : "=r"(r[0]), "=r"(r[1]), "=r"(r[2]), "=r"(r[3]) : "r"(addr));
}

// ---------------- prep: fused weight layout + stat zeroing ----------------
__global__ void prep_kernel(const float* __restrict__ conv_W,
                            const float* __restrict__ conv_b,
                            const float* __restrict__ embed_W,
                            const float* __restrict__ bil_W,
                            const float* __restrict__ fca_W) {
    int idx = blockIdx.x * blockDim.x + threadIdx.x;
    if (idx < 3 * TWO_D * K2N) {                      // g_WnH [l][n][j]
        int l = idx / (TWO_D * K2N), r = idx % (TWO_D * K2N);
        int n = r / K2N, j = r % K2N;
        int k0 = 2 * j, k1 = 2 * j + 1;
        const float* wr = conv_W + (l * TWO_D + n) * KTOT;
        float a = (k0 < KTOT) ? wr[k0] : (k0 == KTOT ? conv_b[l * TWO_D + n] : 0.f);
        float b = (k1 < KTOT) ? wr[k1] : (k1 == KTOT ? conv_b[l * TWO_D + n] : 0.f);
        __half2 h = __floats2half2_rn(a, b);
        g_WnH[idx] = *(uint32_t*)&h;
        return;
    }
    int i2 = idx - 3 * TWO_D * K2N;
    if (i2 < ORIG * DIM) {                            // g_embT [k][d]
        int k = i2 / DIM, d = i2 % DIM;
        g_embT[i2] = embed_W[d * ORIG + k];
        return;
    }
    int i3 = i2 - ORIG * DIM;
    if (i3 < DIM * 6 * DIM) {                         // g_bilT [d][o*64+k]
        int d = i3 / 384, ok = i3 % 384;
        int o = ok >> 6, k2 = ok & 63;
        g_bilT[i3] = bil_W[(o * DIM + d) * DIM + k2];
        return;
    }
    int i4 = i3 - DIM * 6 * DIM;
    if (i4 < DIM * ORIG) {
        int k = i4 / ORIG, c = i4 % ORIG;
        g_fcaT[i4] = fca_W[c * DIM + k];
        return;
    }
    int i5 = i4 - DIM * ORIG;
    if (i5 < TWO_D) { g_s1[i5] = 0.f; g_ss1[i5] = 0.f; return; }
    int i6 = i5 - TWO_D;
    if (i6 < DIM) { g_s2[i6] = 0.f; g_ss2[i6] = 0.f; }
}

// ---------------- embedding: x = atom_fea @ embed_W^T  (K=92) ----------------
__global__ __launch_bounds__(256) void embed_kernel(const float* __restrict__ atom_fea) {
    __shared__ float As[64 * ORIG];
    __shared__ float Ws[ORIG * DIM];
    int t = threadIdx.x;
    int rb = blockIdx.x * 64;
    for (int e = t; e < ORIG * DIM; e += 256) Ws[e] = g_embT[e];
    int warp = t >> 5, lane = t & 31;
    for (int m = warp; m < 64; m += 8) {
        const float* row = atom_fea + (rb + m) * ORIG;
        As[m * ORIG + lane] = row[lane];
        As[m * ORIG + 32 + lane] = row[32 + lane];
        if (lane < ORIG - 64) As[m * ORIG + 64 + lane] = row[64 + lane];
    }
    __syncthreads();
    int ty = t >> 5, tx = t & 31;
    float acc[8][2];
#pragma unroll
    for (int i = 0; i < 8; i++) { acc[i][0] = 0.f; acc[i][1] = 0.f; }
    for (int k = 0; k < ORIG; k++) {
        float2 b = *(const float2*)&Ws[k * DIM + tx * 2];
#pragma unroll
        for (int i = 0; i < 8; i++) {
            float a = As[(ty * 8 + i) * ORIG + k];
            acc[i][0] = fmaf(a, b.x, acc[i][0]);
            acc[i][1] = fmaf(a, b.y, acc[i][1]);
        }
    }
#pragma unroll
    for (int i = 0; i < 8; i++)
        *(float2*)&g_x[0][(rb + ty * 8 + i) * DIM + tx * 2] = make_float2(acc[i][0], acc[i][1]);
}

// ---------------- per-layer stat zeroing (layers 1,2) ----------------
__global__ void zero_stats() {
    int t = threadIdx.x;
    if (t < TWO_D) { g_s1[t] = 0.f; g_ss1[t] = 0.f; }
    if (t < DIM)   { g_s2[t] = 0.f; g_ss2[t] = 0.f; }
}

// ---------------- fused conv GEMM: z = [x_self|x_nbr|nbr_fea|1] @ Wfull, fp16 MMA ----------------
#define CZ_SMEM ((64 * AP + 128 * BP) * 4)

__global__ __launch_bounds__(256, 3) void convz_kernel(int l, int buf,
                                                       const float* __restrict__ nbr_fea,
                                                       const int* __restrict__ nbr_idx) {
    extern __shared__ uint32_t smu[];
    uint32_t* As2 = smu;               // [64][AP]
    uint32_t* Bs2 = smu + 64 * AP;     // [128][BP]
    __shared__ float redS[128], redQ[128];
    __shared__ int nbr_s[64];
    int t = threadIdx.x, w = t >> 5, lane = t & 31;
    int rb = blockIdx.x * 64;
    const float* x = g_x[buf];
    if (t < 64) nbr_s[t] = nbr_idx[rb + t];
    if (t < 128) { redS[t] = 0.f; redQ[t] = 0.f; }
    // B: copy fused weights [128][88] -> pitch BP
    {
        const uint32_t* src = g_WnH + l * TWO_D * K2N;
        for (int e = t; e < TWO_D * K2N; e += 256)
            Bs2[(e / K2N) * BP + (e % K2N)] = src[e];
    }
    __syncthreads();
    // A: gather [x_self | x_nbr | nbr_fea | 1 | pad] as half2
    for (int m = w; m < 64; m += 8) {
        uint32_t* Ar = As2 + m * AP;
        int nself = (rb + m) / MNBR;
        int nbr = nbr_s[m];
        float2 vs = ((const float2*)(x + nself * DIM))[lane];
        __half2 hs = __floats2half2_rn(vs.x, vs.y);
        Ar[lane] = *(uint32_t*)&hs;
        float2 vn = ((const float2*)(x + nbr * DIM))[lane];
        __half2 hn = __floats2half2_rn(vn.x, vn.y);
        Ar[32 + lane] = *(uint32_t*)&hn;
        if (lane < 20) {
            const float* nf = nbr_fea + (long)(rb + m) * FNBR;
            __half2 hh = __floats2half2_rn(nf[2 * lane], nf[2 * lane + 1]);
            Ar[64 + lane] = *(uint32_t*)&hh;
        } else if (lane == 20) {
            const float* nf = nbr_fea + (long)(rb + m) * FNBR;
            __half2 hh = __floats2half2_rn(nf[40], 1.0f);
            Ar[84] = *(uint32_t*)&hh;
        } else if (lane < 24) {
            Ar[64 + lane] = 0u;     // u32 85..87
        }
    }
    __syncthreads();

    int wm = w & 1, wn = w >> 1;             // wm 0..1 (32 rows), wn 0..3 (32 cols)
    int q = lane >> 2, r = lane & 3;

    uint32_t sAs = (uint32_t)__cvta_generic_to_shared(As2);
    uint32_t sBs = (uint32_t)__cvta_generic_to_shared(Bs2);
    uint32_t aAddr0 = sAs + (((wm * 32) + (lane & 7) + ((lane >> 3) & 1) * 8) * AP +
                             ((lane >> 4) & 1) * 4) * 4;
    uint32_t aAddr1 = aAddr0 + 16 * AP * 4;
    uint32_t bAddr0 = sBs + (((wn * 32) + (lane & 7) + ((lane >> 4) & 1) * 8) * BP +
                             ((lane >> 3) & 1) * 4) * 4;
    uint32_t bAddr1 = bAddr0 + 16 * BP * 4;

    float c[2][4][4];
#pragma unroll
    for (int mt = 0; mt < 2; mt++)
#pragma unroll
        for (int nf = 0; nf < 4; nf++)
#pragma unroll
            for (int e = 0; e < 4; e++) c[mt][nf][e] = 0.f;

#pragma unroll
    for (int ks = 0; ks < NKS; ks++) {
        uint32_t ko = ks * 32;               // 8 u32 per step
        uint32_t a[2][4], b01[4], b23[4];
        ldsm4(a[0], aAddr0 + ko);
        ldsm4(a[1], aAddr1 + ko);
        ldsm4(b01, bAddr0 + ko);
        ldsm4(b23, bAddr1 + ko);
        uint32_t bf[4][2] = {{b01[0], b01[1]}, {b01[2], b01[3]},
                             {b23[0], b23[1]}, {b23[2], b23[3]}};
#pragma unroll
        for (int mt = 0; mt < 2; mt++)
#pragma unroll
            for (int nf = 0; nf < 4; nf++)
                mma_f16(c[mt][nf], a[mt], bf[nf]);
    }

    // epilogue: half2 round-trip (stats on rounded values), store z fp16
#pragma unroll
    for (int nf = 0; nf < 4; nf++) {
        int cc = wn * 32 + nf * 8 + r * 2;
        float s0 = 0.f, s1 = 0.f, q0 = 0.f, q1 = 0.f;
#pragma unroll
        for (int mt = 0; mt < 2; mt++) {
            int m0 = wm * 32 + mt * 16 + q;
            int row0 = rb + m0, row1 = row0 + 8;
            __half2 h0 = __floats2half2_rn(c[mt][nf][0], c[mt][nf][1]);
            __half2 h1 = __floats2half2_rn(c[mt][nf][2], c[mt][nf][3]);
            g_z[(long)row0 * 64 + (cc >> 1)] = *(uint32_t*)&h0;
            g_z[(long)row1 * 64 + (cc >> 1)] = *(uint32_t*)&h1;
            float2 v0 = __half22float2(h0);
            float2 v1 = __half22float2(h1);
            s0 += v0.x + v1.x; q0 += v0.x * v0.x + v1.x * v1.x;
            s1 += v0.y + v1.y; q1 += v0.y * v0.y + v1.y * v1.y;
        }
#pragma unroll
        for (int off = 4; off < 32; off <<= 1) {
            s0 += __shfl_xor_sync(0xffffffffu, s0, off);
            s1 += __shfl_xor_sync(0xffffffffu, s1, off);
            q0 += __shfl_xor_sync(0xffffffffu, q0, off);
            q1 += __shfl_xor_sync(0xffffffffu, q1, off);
        }
        if (lane < 4) {
            atomicAdd(&redS[cc], s0);
            atomicAdd(&redS[cc + 1], s1);
            atomicAdd(&redQ[cc], q0);
            atomicAdd(&redQ[cc + 1], q1);
        }
    }
    __syncthreads();
    if (t < 128) {
        atomicAdd(&g_s1[t], redS[t]);
        atomicAdd(&g_ss1[t], redQ[t]);
    }
}

// ---------------- BN1 + gate + sum over neighbors (half2 z), BN2 stats ----------------
// One atom per (thread-pair-channel, grp); all 24 z-words batched into registers
// BEFORE any gate math to force MLP ~24 (was ~2, latency-bound at 586 GB/s).
__global__ __launch_bounds__(256) void reduce_kernel(int l,
                                                     const float* __restrict__ bn1_g,
                                                     const float* __restrict__ bn1_b) {
    int c = threadIdx.x & 31, grp = threadIdx.x >> 5;
    int d0 = 2 * c;
    float inv = 1.0f / CNT1F;
    float mf0 = g_s1[d0] * inv, mf1 = g_s1[d0 + 1] * inv;
    float vf0 = g_ss1[d0] * inv - mf0 * mf0, vf1 = g_ss1[d0 + 1] * inv - mf1 * mf1;
    float scf0 = rsqrtf(vf0 + EPSBN) * bn1_g[l * TWO_D + d0];
    float scf1 = rsqrtf(vf1 + EPSBN) * bn1_g[l * TWO_D + d0 + 1];
    float shf0 = bn1_b[l * TWO_D + d0] - mf0 * scf0;
    float shf1 = bn1_b[l * TWO_D + d0 + 1] - mf1 * scf1;
    float mc0 = g_s1[64 + d0] * inv, mc1 = g_s1[64 + d0 + 1] * inv;
    float vc0 = g_ss1[64 + d0] * inv - mc0 * mc0, vc1 = g_ss1[64 + d0 + 1] * inv - mc1 * mc1;
    float scc0 = rsqrtf(vc0 + EPSBN) * bn1_g[l * TWO_D + 64 + d0];
    float scc1 = rsqrtf(vc1 + EPSBN) * bn1_g[l * TWO_D + 64 + d0 + 1];
    float shc0 = bn1_b[l * TWO_D + 64 + d0] - mc0 * scc0;
    float shc1 = bn1_b[l * TWO_D + 64 + d0 + 1] - mc1 * scc1;

    float ls0 = 0.f, ls1 = 0.f, lq0 = 0.f, lq1 = 0.f;
    int n0 = blockIdx.x * 16 + grp * 2;
#pragma unroll
    for (int a = 0; a < 2; a++) {
        int n = n0 + a;
        const uint32_t* zr = g_z + (long)n * MNBR * 64;
        uint32_t zfp[MNBR], zcp[MNBR];
#pragma unroll
        for (int m = 0; m < MNBR; m++) zfp[m] = __ldg(&zr[m * 64 + c]);
#pragma unroll
        for (int m = 0; m < MNBR; m++) zcp[m] = __ldg(&zr[m * 64 + 32 + c]);
        float a0 = 0.f, a1 = 0.f;
#pragma unroll
        for (int m = 0; m < MNBR; m++) {
            float2 zf = __half22float2(*(__half2*)&zfp[m]);
            float2 zc = __half22float2(*(__half2*)&zcp[m]);
            a0 += gatef(zf.x * scf0 + shf0, zc.x * scc0 + shc0);
            a1 += gatef(zf.y * scf1 + shf1, zc.y * scc1 + shc1);
        }
        *(float2*)&g_summed[n * DIM + d0] = make_float2(a0, a1);
        ls0 += a0; lq0 += a0 * a0;
        ls1 += a1; lq1 += a1 * a1;
    }
    atomicAdd(&g_s2[d0], ls0);
    atomicAdd(&g_s2[d0 + 1], ls1);
    atomicAdd(&g_ss2[d0], lq0);
    atomicAdd(&g_ss2[d0 + 1], lq1);
}

// ---------------- BN2 + residual softplus -> x_out ----------------
__global__ __launch_bounds__(256) void bnres_kernel(int l, int buf,
                                                    const float* __restrict__ bn2_g,
                                                    const float* __restrict__ bn2_b) {
    int gid = blockIdx.x * 256 + threadIdx.x;
    int d = gid & 63;
    float inv = 1.0f / CNT2F;
    float m2 = g_s2[d] * inv;
    float v2 = g_ss2[d] * inv - m2 * m2;
    float sc = rsqrtf(v2 + EPSBN) * bn2_g[l * DIM + d];
    float sh = bn2_b[l * DIM + d] - m2 * sc;
    float v = g_x[buf][gid] + g_summed[gid] * sc + sh;
    g_x[1 - buf][gid] = (v > 15.0f) ? v : __logf(1.0f + __expf(v));
}

// ---------------- G[bi, o*64+k] = f[bi,:] @ bilT  (K=64, scalar) ----------------
__global__ __launch_bounds__(256) void gmat_kernel(int buf, const int* __restrict__ cidx) {
    extern __shared__ float sm[];
    float* Ws = sm;                // [64][128]
    float* As = sm + 64 * TWO_D;   // [64][64]
    __shared__ int cid_s[64];
    int t = threadIdx.x;
    int rb = blockIdx.x * 64;
    int co = blockIdx.y * 128;
    const float* x = g_x[buf];
    if (t < 64) cid_s[t] = cidx[rb + t];
    for (int e = t; e < 64 * TWO_D; e += 256) {
        int k = e >> 7, oc = e & 127;
        Ws[e] = g_bilT[k * 384 + co + oc];
    }
    __syncthreads();
    int warp = t >> 5, lane = t & 31;
    for (int m = warp; m < 64; m += 8) {
        int a = cid_s[m];
        As[m * 64 + lane]      = x[a * DIM + lane];
        As[m * 64 + 32 + lane] = x[a * DIM + 32 + lane];
    }
    __syncthreads();
    int ty = t >> 5, tx = t & 31;
    float acc[8][4];
#pragma unroll
    for (int i = 0; i < 8; i++)
#pragma unroll
        for (int c = 0; c < 4; c++) acc[i][c] = 0.f;
    for (int k = 0; k < 64; k++) {
        float4 b = *(const float4*)&Ws[k * TWO_D + tx * 4];
#pragma unroll
        for (int i = 0; i < 8; i++) {
            float a = As[(ty * 8 + i) * 64 + k];
            acc[i][0] = fmaf(a, b.x, acc[i][0]);
            acc[i][1] = fmaf(a, b.y, acc[i][1]);
            acc[i][2] = fmaf(a, b.z, acc[i][2]);
            acc[i][3] = fmaf(a, b.w, acc[i][3]);
        }
    }
#pragma unroll
    for (int i = 0; i < 8; i++)
        *(float4*)&g_G[(long)(rb + ty * 8 + i) * 384 + co + tx * 4] =
            make_float4(acc[i][0], acc[i][1], acc[i][2], acc[i][3]);
}

// ---------------- edge: per-pair bilinear dot + fc1 + log_softmax ----------------
__global__ __launch_bounds__(256) void edge_kernel(int buf, const int* __restrict__ cidx,
                                                   const float* __restrict__ bil_b,
                                                   const float* __restrict__ fc1_W,
                                                   const float* __restrict__ fc1_b,
                                                   float* __restrict__ out) {
    __shared__ float f_s[64][65];
    __shared__ float Gi[4][384];
    __shared__ int cid_s[64];
    __shared__ float s_fc1W[36], s_fc1b[6], s_bilb[6];
    int b = blockIdx.x, it = blockIdx.y, t = threadIdx.x;
    const float* x = g_x[buf];
    if (t < 64) cid_s[t] = cidx[b * 64 + t];
    if (t < 36) s_fc1W[t] = fc1_W[t];
    if (t >= 64 && t < 70) s_fc1b[t - 64] = fc1_b[t - 64];
    if (t >= 96 && t < 102) s_bilb[t - 96] = bil_b[t - 96];
    __syncthreads();
    for (int e = t; e < 4096; e += 256) {
        int m = e >> 6, k = e & 63;
        f_s[m][k] = x[cid_s[m] * DIM + k];
    }
    for (int e = t; e < 1536; e += 256) {
        int i4 = e / 384, ok = e % 384;
        Gi[i4][ok] = g_G[(long)(b * 64 + it * 4 + i4) * 384 + ok];
    }
    __syncthreads();
    int i4 = t >> 6, j = t & 63;
    float ev[6];
#pragma unroll
    for (int o = 0; o < 6; o++) {
        float a = s_bilb[o];
#pragma unroll 16
        for (int k = 0; k < 64; k++) a = fmaf(Gi[i4][o * 64 + k], f_s[j][k], a);
        ev[o] = a;
    }
    float tr[6];
#pragma unroll
    for (int r = 0; r < 6; r++) {
        float a = s_fc1b[r];
#pragma unroll
        for (int o = 0; o < 6; o++) a = fmaf(s_fc1W[r * 6 + o], ev[o], a);
        tr[r] = a;
    }
    float mx = tr[0];
#pragma unroll
    for (int r = 1; r < 6; r++) mx = fmaxf(mx, tr[r]);
    float se = 0.f;
#pragma unroll
    for (int r = 0; r < 6; r++) se += expf(tr[r] - mx);
    float lse = mx + logf(se);
    int pair = (it * 4 + i4) * 64 + j;
    float* op = out + ((long)b * 4096 + pair) * 6;
#pragma unroll
    for (int r = 0; r < 6; r++) op[r] = tr[r] - lse;
}

// ---------------- atom_out = f @ fca_W^T + fca_b ----------------
__global__ __launch_bounds__(96) void atomout_kernel(int buf, const int* __restrict__ cidx,
                                                     const float* __restrict__ fca_b,
                                                     float* __restrict__ out2) {
    __shared__ float xr[64];
    int t = threadIdx.x;
    int r = blockIdx.x;
    int atom = cidx[r];
    if (t < 64) xr[t] = g_x[buf][atom * DIM + t];
    __syncthreads();
    if (t < ORIG) {
        float a = fca_b[t];
#pragma unroll 16
        for (int k = 0; k < 64; k++) a = fmaf(xr[k], g_fcaT[k * ORIG + t], a);
        out2[(long)r * ORIG + t] = a;
    }
}

// ---------------- launch ----------------
#define ZS_SM ((64 * TWO_D + 64 * 64) * 4)

extern "C" void kernel_launch(void* const* d_in, const int* in_sizes, int n_in,
                              void* d_out, int out_size) {
    (void)in_sizes; (void)n_in; (void)out_size;
    const float* atom_fea = (const float*)d_in[0];
    const float* nbr_fea  = (const float*)d_in[1];
    const int*   nbr_idx  = (const int*)d_in[2];
    const int*   cidx     = (const int*)d_in[3];
    const float* embed_W  = (const float*)d_in[4];
    const float* conv_W   = (const float*)d_in[5];
    const float* conv_b   = (const float*)d_in[6];
    const float* bn1_g    = (const float*)d_in[7];
    const float* bn1_b    = (const float*)d_in[8];
    const float* bn2_g    = (const float*)d_in[9];
    const float* bn2_b    = (const float*)d_in[10];
    const float* bil_W    = (const float*)d_in[11];
    const float* bil_b    = (const float*)d_in[12];
    const float* fc1_W    = (const float*)d_in[13];
    const float* fc1_b    = (const float*)d_in[14];
    const float* fca_W    = (const float*)d_in[15];
    const float* fca_b    = (const float*)d_in[16];
    float* out = (float*)d_out;

    cudaFuncSetAttribute(convz_kernel, cudaFuncAttributeMaxDynamicSharedMemorySize, CZ_SMEM);
    cudaFuncSetAttribute(gmat_kernel,  cudaFuncAttributeMaxDynamicSharedMemorySize, ZS_SM);

    int prep_elems = 3 * TWO_D * K2N + ORIG * DIM + DIM * 384 + DIM * ORIG + TWO_D + DIM;
    prep_kernel<<<(prep_elems + 255) / 256, 256>>>(conv_W, conv_b, embed_W, bil_W, fca_W);
    embed_kernel<<<NATOM / 64, 256>>>(atom_fea);

    int buf = 0;
    for (int l = 0; l < 3; l++) {
        if (l > 0) zero_stats<<<1, 128>>>();
        convz_kernel<<<NATOM * MNBR / 64, 256, CZ_SMEM>>>(l, buf, nbr_fea, nbr_idx);
        reduce_kernel<<<NATOM / 16, 256>>>(l, bn1_g, bn1_b);
        bnres_kernel<<<(NATOM * DIM) / 256, 256>>>(l, buf, bn2_g, bn2_b);
        buf = 1 - buf;
    }

    gmat_kernel<<<dim3(NCRY * NA / 64, 3), 256, ZS_SM>>>(buf, cidx);
    edge_kernel<<<dim3(NCRY, 16), 256>>>(buf, cidx, bil_b, fc1_W, fc1_b, out);
    atomout_kernel<<<NCRY * NA, 96>>>(buf, cidx, fca_b, out + (long)NCRY * NA * NA * 6);
}

// round 11
// speedup vs baseline: 2.3219x; 1.3599x over previous
#include <cuda_runtime.h>
#include <cuda_fp16.h>
#include <math.h>
#include <stdint.h>

#define NATOM 32768
#define MNBR 12
#define DIM 64
#define FNBR 41
#define ORIG 92
#define TWO_D 128
#define KTOT 169
#define NCRY 512
#define NA 64
#define CNT1F (393216.0f)
#define CNT2F (32768.0f)
#define EPSBN 1e-5f

#define K2N 88          // u32 (half2) count per B row: K=170 padded to 176 halves
#define AP 92           // A smem pitch in u32
#define BP 92           // B smem pitch in u32
#define NKS 11          // k-steps of 16
#define SPAD 32         // stat array stride (32 floats = 128B) to spread LTS slices

// ---------------- scratch (device globals; no allocation) ----------------
__device__ float g_x[2][NATOM * DIM];
__device__ uint32_t g_z[NATOM * MNBR * 64];          // z as half2, 100 MB
__device__ float g_summed[NATOM * DIM];
__device__ float g_G[NCRY * NA * 384];               // 50 MB
__device__ uint32_t g_WnH[3 * TWO_D * K2N];          // fused W half2 [l][n][k2]
__device__ float g_embT[ORIG * DIM];                 // [k][d]
__device__ float g_bilT[DIM * 6 * DIM];              // [d][o*64+k]
__device__ float g_fcaT[DIM * ORIG];                 // [k][c]
// padded stat arrays: one 128B line per channel -> many LTS slices
__device__ float g_s1[TWO_D * SPAD], g_ss1[TWO_D * SPAD];
__device__ float g_s2[DIM * SPAD], g_ss2[DIM * SPAD];

__device__ __forceinline__ float softplusf(float v) {
    return v > 20.0f ? v : log1pf(expf(v));
}
// fast softplus * sigmoid gate (approx intrinsics; err ~1e-6 rel, far below fp16 z noise)
__device__ __forceinline__ float gatef(float fv, float cv) {
    float sp = (cv > 15.0f) ? cv : __logf(1.0f + __expf(cv));
    return __fdividef(sp, 1.0f + __expf(-fv));
}
__device__ __forceinline__ void mma_f16(float* c, const uint32_t* a, const uint32_t* b) {
    asm volatile(
        "mma.sync.aligned.m16n8k16.row.col.f32.f16.f16.f32 "
        "{%0,%1,%2,%3}, {%4,%5,%6,%7}, {%8,%9}, {%0,%1,%2,%3};"
        : "+f"(c[0]), "+f"(c[1]), "+f"(c[2]), "+f"(c[3])
        : "r"(a[0]), "r"(a[1]), "r"(a[2]), "r"(a[3]), "r"(b[0]), "r"(b[1]));
}
__device__ __forceinline__ void ldsm4(uint32_t* r, uint32_t addr) {
    asm volatile("ldmatrix.sync.aligned.m8n8.x4.shared.b16 {%0,%1,%2,%3}, [%4];"
                 : "=r"(r[0]), "=r"(r[1]), "=r"(r[2]), "=r"(r[3]) : "r"(addr));
}

// ---------------- prep: fused weight layout ----------------
__global__ void prep_kernel(const float* __restrict__ conv_W,
                            const float* __restrict__ conv_b,
                            const float* __restrict__ embed_W,
                            const float* __restrict__ bil_W,
                            const float* __restrict__ fca_W) {
    int idx = blockIdx.x * blockDim.x + threadIdx.x;
    if (idx < 3 * TWO_D * K2N) {                      // g_WnH [l][n][j]
        int l = idx / (TWO_D * K2N), r = idx % (TWO_D * K2N);
        int n = r / K2N, j = r % K2N;
        int k0 = 2 * j, k1 = 2 * j + 1;
        const float* wr = conv_W + (l * TWO_D + n) * KTOT;
        float a = (k0 < KTOT) ? wr[k0] : (k0 == KTOT ? conv_b[l * TWO_D + n] : 0.f);
        float b = (k1 < KTOT) ? wr[k1] : (k1 == KTOT ? conv_b[l * TWO_D + n] : 0.f);
        __half2 h = __floats2half2_rn(a, b);
        g_WnH[idx] = *(uint32_t*)&h;
        return;
    }
    int i2 = idx - 3 * TWO_D * K2N;
    if (i2 < ORIG * DIM) {                            // g_embT [k][d]
        int k = i2 / DIM, d = i2 % DIM;
        g_embT[i2] = embed_W[d * ORIG + k];
        return;
    }
    int i3 = i2 - ORIG * DIM;
    if (i3 < DIM * 6 * DIM) {                         // g_bilT [d][o*64+k]
        int d = i3 / 384, ok = i3 % 384;
        int o = ok >> 6, k2 = ok & 63;
        g_bilT[i3] = bil_W[(o * DIM + d) * DIM + k2];
        return;
    }
    int i4 = i3 - DIM * 6 * DIM;
    if (i4 < DIM * ORIG) {
        int k = i4 / ORIG, c = i4 % ORIG;
        g_fcaT[i4] = fca_W[c * DIM + k];
    }
}

// ---------------- embedding: x = atom_fea @ embed_W^T  (K=92) ----------------
__global__ __launch_bounds__(256) void embed_kernel(const float* __restrict__ atom_fea) {
    __shared__ float As[64 * ORIG];
    __shared__ float Ws[ORIG * DIM];
    int t = threadIdx.x;
    int rb = blockIdx.x * 64;
    for (int e = t; e < ORIG * DIM; e += 256) Ws[e] = g_embT[e];
    int warp = t >> 5, lane = t & 31;
    for (int m = warp; m < 64; m += 8) {
        const float* row = atom_fea + (rb + m) * ORIG;
        As[m * ORIG + lane] = row[lane];
        As[m * ORIG + 32 + lane] = row[32 + lane];
        if (lane < ORIG - 64) As[m * ORIG + 64 + lane] = row[64 + lane];
    }
    __syncthreads();
    int ty = t >> 5, tx = t & 31;
    float acc[8][2];
#pragma unroll
    for (int i = 0; i < 8; i++) { acc[i][0] = 0.f; acc[i][1] = 0.f; }
    for (int k = 0; k < ORIG; k++) {
        float2 b = *(const float2*)&Ws[k * DIM + tx * 2];
#pragma unroll
        for (int i = 0; i < 8; i++) {
            float a = As[(ty * 8 + i) * ORIG + k];
            acc[i][0] = fmaf(a, b.x, acc[i][0]);
            acc[i][1] = fmaf(a, b.y, acc[i][1]);
        }
    }
#pragma unroll
    for (int i = 0; i < 8; i++)
        *(float2*)&g_x[0][(rb + ty * 8 + i) * DIM + tx * 2] = make_float2(acc[i][0], acc[i][1]);
}

// ---------------- stat zeroing (padded arrays; every layer) ----------------
__global__ void zero_stats() {
    int t = blockIdx.x * 256 + threadIdx.x;
    if (t < TWO_D * SPAD) { g_s1[t] = 0.f; g_ss1[t] = 0.f; }
    int u = t - TWO_D * SPAD;
    if (u >= 0 && u < DIM * SPAD) { g_s2[u] = 0.f; g_ss2[u] = 0.f; }
}

// ---------------- fused conv GEMM: z = [x_self|x_nbr|nbr_fea|1] @ Wfull, fp16 MMA ----------------
#define CZ_SMEM ((64 * AP + 128 * BP) * 4)

__global__ __launch_bounds__(256, 3) void convz_kernel(int l, int buf,
                                                       const float* __restrict__ nbr_fea,
                                                       const int* __restrict__ nbr_idx) {
    extern __shared__ uint32_t smu[];
    uint32_t* As2 = smu;               // [64][AP]
    uint32_t* Bs2 = smu + 64 * AP;     // [128][BP]
    __shared__ float redS[128], redQ[128];
    __shared__ int nbr_s[64];
    int t = threadIdx.x, w = t >> 5, lane = t & 31;
    int rb = blockIdx.x * 64;
    const float* x = g_x[buf];
    if (t < 64) nbr_s[t] = nbr_idx[rb + t];
    if (t < 128) { redS[t] = 0.f; redQ[t] = 0.f; }
    // B: copy fused weights [128][88] -> pitch BP
    {
        const uint32_t* src = g_WnH + l * TWO_D * K2N;
        for (int e = t; e < TWO_D * K2N; e += 256)
            Bs2[(e / K2N) * BP + (e % K2N)] = src[e];
    }
    __syncthreads();
    // A: gather [x_self | x_nbr | nbr_fea | 1 | pad] as half2
    for (int m = w; m < 64; m += 8) {
        uint32_t* Ar = As2 + m * AP;
        int nself = (rb + m) / MNBR;
        int nbr = nbr_s[m];
        float2 vs = ((const float2*)(x + nself * DIM))[lane];
        __half2 hs = __floats2half2_rn(vs.x, vs.y);
        Ar[lane] = *(uint32_t*)&hs;
        float2 vn = ((const float2*)(x + nbr * DIM))[lane];
        __half2 hn = __floats2half2_rn(vn.x, vn.y);
        Ar[32 + lane] = *(uint32_t*)&hn;
        if (lane < 20) {
            const float* nf = nbr_fea + (long)(rb + m) * FNBR;
            __half2 hh = __floats2half2_rn(nf[2 * lane], nf[2 * lane + 1]);
            Ar[64 + lane] = *(uint32_t*)&hh;
        } else if (lane == 20) {
            const float* nf = nbr_fea + (long)(rb + m) * FNBR;
            __half2 hh = __floats2half2_rn(nf[40], 1.0f);
            Ar[84] = *(uint32_t*)&hh;
        } else if (lane < 24) {
            Ar[64 + lane] = 0u;     // u32 85..87
        }
    }
    __syncthreads();

    int wm = w & 1, wn = w >> 1;             // wm 0..1 (32 rows), wn 0..3 (32 cols)
    int q = lane >> 2, r = lane & 3;

    uint32_t sAs = (uint32_t)__cvta_generic_to_shared(As2);
    uint32_t sBs = (uint32_t)__cvta_generic_to_shared(Bs2);
    uint32_t aAddr0 = sAs + (((wm * 32) + (lane & 7) + ((lane >> 3) & 1) * 8) * AP +
                             ((lane >> 4) & 1) * 4) * 4;
    uint32_t aAddr1 = aAddr0 + 16 * AP * 4;
    uint32_t bAddr0 = sBs + (((wn * 32) + (lane & 7) + ((lane >> 4) & 1) * 8) * BP +
                             ((lane >> 3) & 1) * 4) * 4;
    uint32_t bAddr1 = bAddr0 + 16 * BP * 4;

    float c[2][4][4];
#pragma unroll
    for (int mt = 0; mt < 2; mt++)
#pragma unroll
        for (int nf = 0; nf < 4; nf++)
#pragma unroll
            for (int e = 0; e < 4; e++) c[mt][nf][e] = 0.f;

#pragma unroll
    for (int ks = 0; ks < NKS; ks++) {
        uint32_t ko = ks * 32;               // 8 u32 per step
        uint32_t a[2][4], b01[4], b23[4];
        ldsm4(a[0], aAddr0 + ko);
        ldsm4(a[1], aAddr1 + ko);
        ldsm4(b01, bAddr0 + ko);
        ldsm4(b23, bAddr1 + ko);
        uint32_t bf[4][2] = {{b01[0], b01[1]}, {b01[2], b01[3]},
                             {b23[0], b23[1]}, {b23[2], b23[3]}};
#pragma unroll
        for (int mt = 0; mt < 2; mt++)
#pragma unroll
            for (int nf = 0; nf < 4; nf++)
                mma_f16(c[mt][nf], a[mt], bf[nf]);
    }

    // epilogue: half2 round-trip (stats on rounded values), store z fp16
#pragma unroll
    for (int nf = 0; nf < 4; nf++) {
        int cc = wn * 32 + nf * 8 + r * 2;
        float s0 = 0.f, s1 = 0.f, q0 = 0.f, q1 = 0.f;
#pragma unroll
        for (int mt = 0; mt < 2; mt++) {
            int m0 = wm * 32 + mt * 16 + q;
            int row0 = rb + m0, row1 = row0 + 8;
            __half2 h0 = __floats2half2_rn(c[mt][nf][0], c[mt][nf][1]);
            __half2 h1 = __floats2half2_rn(c[mt][nf][2], c[mt][nf][3]);
            g_z[(long)row0 * 64 + (cc >> 1)] = *(uint32_t*)&h0;
            g_z[(long)row1 * 64 + (cc >> 1)] = *(uint32_t*)&h1;
            float2 v0 = __half22float2(h0);
            float2 v1 = __half22float2(h1);
            s0 += v0.x + v1.x; q0 += v0.x * v0.x + v1.x * v1.x;
            s1 += v0.y + v1.y; q1 += v0.y * v0.y + v1.y * v1.y;
        }
#pragma unroll
        for (int off = 4; off < 32; off <<= 1) {
            s0 += __shfl_xor_sync(0xffffffffu, s0, off);
            s1 += __shfl_xor_sync(0xffffffffu, s1, off);
            q0 += __shfl_xor_sync(0xffffffffu, q0, off);
            q1 += __shfl_xor_sync(0xffffffffu, q1, off);
        }
        if (lane < 4) {
            atomicAdd(&redS[cc], s0);
            atomicAdd(&redS[cc + 1], s1);
            atomicAdd(&redQ[cc], q0);
            atomicAdd(&redQ[cc + 1], q1);
        }
    }
    __syncthreads();
    if (t < 128) {
        atomicAdd(&g_s1[t * SPAD], redS[t]);
        atomicAdd(&g_ss1[t * SPAD], redQ[t]);
    }
}

// ---------------- BN1 + gate + sum over neighbors (half2 z), BN2 stats ----------------
__global__ __launch_bounds__(256) void reduce_kernel(int l,
                                                     const float* __restrict__ bn1_g,
                                                     const float* __restrict__ bn1_b) {
    __shared__ float r2S[64], r2Q[64];
    int c = threadIdx.x & 31, grp = threadIdx.x >> 5;
    int d0 = 2 * c;
    if (threadIdx.x < 64) { r2S[threadIdx.x] = 0.f; r2Q[threadIdx.x] = 0.f; }
    __syncthreads();
    float inv = 1.0f / CNT1F;
    float mf0 = g_s1[d0 * SPAD] * inv, mf1 = g_s1[(d0 + 1) * SPAD] * inv;
    float vf0 = g_ss1[d0 * SPAD] * inv - mf0 * mf0;
    float vf1 = g_ss1[(d0 + 1) * SPAD] * inv - mf1 * mf1;
    float scf0 = rsqrtf(vf0 + EPSBN) * bn1_g[l * TWO_D + d0];
    float scf1 = rsqrtf(vf1 + EPSBN) * bn1_g[l * TWO_D + d0 + 1];
    float shf0 = bn1_b[l * TWO_D + d0] - mf0 * scf0;
    float shf1 = bn1_b[l * TWO_D + d0 + 1] - mf1 * scf1;
    float mc0 = g_s1[(64 + d0) * SPAD] * inv, mc1 = g_s1[(64 + d0 + 1) * SPAD] * inv;
    float vc0 = g_ss1[(64 + d0) * SPAD] * inv - mc0 * mc0;
    float vc1 = g_ss1[(64 + d0 + 1) * SPAD] * inv - mc1 * mc1;
    float scc0 = rsqrtf(vc0 + EPSBN) * bn1_g[l * TWO_D + 64 + d0];
    float scc1 = rsqrtf(vc1 + EPSBN) * bn1_g[l * TWO_D + 64 + d0 + 1];
    float shc0 = bn1_b[l * TWO_D + 64 + d0] - mc0 * scc0;
    float shc1 = bn1_b[l * TWO_D + 64 + d0 + 1] - mc1 * scc1;

    float ls0 = 0.f, ls1 = 0.f, lq0 = 0.f, lq1 = 0.f;
    int n0 = blockIdx.x * 16 + grp * 2;
#pragma unroll
    for (int a = 0; a < 2; a++) {
        int n = n0 + a;
        const uint32_t* zr = g_z + (long)n * MNBR * 64;
        uint32_t zfp[MNBR], zcp[MNBR];
#pragma unroll
        for (int m = 0; m < MNBR; m++) zfp[m] = __ldg(&zr[m * 64 + c]);
#pragma unroll
        for (int m = 0; m < MNBR; m++) zcp[m] = __ldg(&zr[m * 64 + 32 + c]);
        float a0 = 0.f, a1 = 0.f;
#pragma unroll
        for (int m = 0; m < MNBR; m++) {
            float2 zf = __half22float2(*(__half2*)&zfp[m]);
            float2 zc = __half22float2(*(__half2*)&zcp[m]);
            a0 += gatef(zf.x * scf0 + shf0, zc.x * scc0 + shc0);
            a1 += gatef(zf.y * scf1 + shf1, zc.y * scc1 + shc1);
        }
        *(float2*)&g_summed[n * DIM + d0] = make_float2(a0, a1);
        ls0 += a0; lq0 += a0 * a0;
        ls1 += a1; lq1 += a1 * a1;
    }
    // stage BN2 stats in smem (8 warps share channels), then 1 global atomic/ch/block
    atomicAdd(&r2S[d0], ls0);
    atomicAdd(&r2S[d0 + 1], ls1);
    atomicAdd(&r2Q[d0], lq0);
    atomicAdd(&r2Q[d0 + 1], lq1);
    __syncthreads();
    if (threadIdx.x < 64) {
        atomicAdd(&g_s2[threadIdx.x * SPAD], r2S[threadIdx.x]);
        atomicAdd(&g_ss2[threadIdx.x * SPAD], r2Q[threadIdx.x]);
    }
}

// ---------------- BN2 + residual softplus -> x_out ----------------
__global__ __launch_bounds__(256) void bnres_kernel(int l, int buf,
                                                    const float* __restrict__ bn2_g,
                                                    const float* __restrict__ bn2_b) {
    int gid = blockIdx.x * 256 + threadIdx.x;
    int d = gid & 63;
    float inv = 1.0f / CNT2F;
    float m2 = g_s2[d * SPAD] * inv;
    float v2 = g_ss2[d * SPAD] * inv - m2 * m2;
    float sc = rsqrtf(v2 + EPSBN) * bn2_g[l * DIM + d];
    float sh = bn2_b[l * DIM + d] - m2 * sc;
    float v = g_x[buf][gid] + g_summed[gid] * sc + sh;
    g_x[1 - buf][gid] = (v > 15.0f) ? v : __logf(1.0f + __expf(v));
}

// ---------------- G[bi, o*64+k] = f[bi,:] @ bilT  (K=64, scalar) ----------------
__global__ __launch_bounds__(256) void gmat_kernel(int buf, const int* __restrict__ cidx) {
    extern __shared__ float sm[];
    float* Ws = sm;                // [64][128]
    float* As = sm + 64 * TWO_D;   // [64][64]
    __shared__ int cid_s[64];
    int t = threadIdx.x;
    int rb = blockIdx.x * 64;
    int co = blockIdx.y * 128;
    const float* x = g_x[buf];
    if (t < 64) cid_s[t] = cidx[rb + t];
    for (int e = t; e < 64 * TWO_D; e += 256) {
        int k = e >> 7, oc = e & 127;
        Ws[e] = g_bilT[k * 384 + co + oc];
    }
    __syncthreads();
    int warp = t >> 5, lane = t & 31;
    for (int m = warp; m < 64; m += 8) {
        int a = cid_s[m];
        As[m * 64 + lane]      = x[a * DIM + lane];
        As[m * 64 + 32 + lane] = x[a * DIM + 32 + lane];
    }
    __syncthreads();
    int ty = t >> 5, tx = t & 31;
    float acc[8][4];
#pragma unroll
    for (int i = 0; i < 8; i++)
#pragma unroll
        for (int c = 0; c < 4; c++) acc[i][c] = 0.f;
    for (int k = 0; k < 64; k++) {
        float4 b = *(const float4*)&Ws[k * TWO_D + tx * 4];
#pragma unroll
        for (int i = 0; i < 8; i++) {
            float a = As[(ty * 8 + i) * 64 + k];
            acc[i][0] = fmaf(a, b.x, acc[i][0]);
            acc[i][1] = fmaf(a, b.y, acc[i][1]);
            acc[i][2] = fmaf(a, b.z, acc[i][2]);
            acc[i][3] = fmaf(a, b.w, acc[i][3]);
        }
    }
#pragma unroll
    for (int i = 0; i < 8; i++)
        *(float4*)&g_G[(long)(rb + ty * 8 + i) * 384 + co + tx * 4] =
            make_float4(acc[i][0], acc[i][1], acc[i][2], acc[i][3]);
}

// ---------------- edge: per-pair bilinear dot + fc1 + log_softmax ----------------
__global__ __launch_bounds__(256) void edge_kernel(int buf, const int* __restrict__ cidx,
                                                   const float* __restrict__ bil_b,
                                                   const float* __restrict__ fc1_W,
                                                   const float* __restrict__ fc1_b,
                                                   float* __restrict__ out) {
    __shared__ float f_s[64][65];
    __shared__ float Gi[4][384];
    __shared__ int cid_s[64];
    __shared__ float s_fc1W[36], s_fc1b[6], s_bilb[6];
    int b = blockIdx.x, it = blockIdx.y, t = threadIdx.x;
    const float* x = g_x[buf];
    if (t < 64) cid_s[t] = cidx[b * 64 + t];
    if (t < 36) s_fc1W[t] = fc1_W[t];
    if (t >= 64 && t < 70) s_fc1b[t - 64] = fc1_b[t - 64];
    if (t >= 96 && t < 102) s_bilb[t - 96] = bil_b[t - 96];
    __syncthreads();
    for (int e = t; e < 4096; e += 256) {
        int m = e >> 6, k = e & 63;
        f_s[m][k] = x[cid_s[m] * DIM + k];
    }
    for (int e = t; e < 1536; e += 256) {
        int i4 = e / 384, ok = e % 384;
        Gi[i4][ok] = g_G[(long)(b * 64 + it * 4 + i4) * 384 + ok];
    }
    __syncthreads();
    int i4 = t >> 6, j = t & 63;
    float ev[6];
#pragma unroll
    for (int o = 0; o < 6; o++) {
        float a = s_bilb[o];
#pragma unroll 16
        for (int k = 0; k < 64; k++) a = fmaf(Gi[i4][o * 64 + k], f_s[j][k], a);
        ev[o] = a;
    }
    float tr[6];
#pragma unroll
    for (int r = 0; r < 6; r++) {
        float a = s_fc1b[r];
#pragma unroll
        for (int o = 0; o < 6; o++) a = fmaf(s_fc1W[r * 6 + o], ev[o], a);
        tr[r] = a;
    }
    float mx = tr[0];
#pragma unroll
    for (int r = 1; r < 6; r++) mx = fmaxf(mx, tr[r]);
    float se = 0.f;
#pragma unroll
    for (int r = 0; r < 6; r++) se += expf(tr[r] - mx);
    float lse = mx + logf(se);
    int pair = (it * 4 + i4) * 64 + j;
    float* op = out + ((long)b * 4096 + pair) * 6;
#pragma unroll
    for (int r = 0; r < 6; r++) op[r] = tr[r] - lse;
}

// ---------------- atom_out = f @ fca_W^T + fca_b ----------------
__global__ __launch_bounds__(96) void atomout_kernel(int buf, const int* __restrict__ cidx,
                                                     const float* __restrict__ fca_b,
                                                     float* __restrict__ out2) {
    __shared__ float xr[64];
    int t = threadIdx.x;
    int r = blockIdx.x;
    int atom = cidx[r];
    if (t < 64) xr[t] = g_x[buf][atom * DIM + t];
    __syncthreads();
    if (t < ORIG) {
        float a = fca_b[t];
#pragma unroll 16
        for (int k = 0; k < 64; k++) a = fmaf(xr[k], g_fcaT[k * ORIG + t], a);
        out2[(long)r * ORIG + t] = a;
    }
}

// ---------------- launch ----------------
#define ZS_SM ((64 * TWO_D + 64 * 64) * 4)

extern "C" void kernel_launch(void* const* d_in, const int* in_sizes, int n_in,
                              void* d_out, int out_size) {
    (void)in_sizes; (void)n_in; (void)out_size;
    const float* atom_fea = (const float*)d_in[0];
    const float* nbr_fea  = (const float*)d_in[1];
    const int*   nbr_idx  = (const int*)d_in[2];
    const int*   cidx     = (const int*)d_in[3];
    const float* embed_W  = (const float*)d_in[4];
    const float* conv_W   = (const float*)d_in[5];
    const float* conv_b   = (const float*)d_in[6];
    const float* bn1_g    = (const float*)d_in[7];
    const float* bn1_b    = (const float*)d_in[8];
    const float* bn2_g    = (const float*)d_in[9];
    const float* bn2_b    = (const float*)d_in[10];
    const float* bil_W    = (const float*)d_in[11];
    const float* bil_b    = (const float*)d_in[12];
    const float* fc1_W    = (const float*)d_in[13];
    const float* fc1_b    = (const float*)d_in[14];
    const float* fca_W    = (const float*)d_in[15];
    const float* fca_b    = (const float*)d_in[16];
    float* out = (float*)d_out;

    cudaFuncSetAttribute(convz_kernel, cudaFuncAttributeMaxDynamicSharedMemorySize, CZ_SMEM);
    cudaFuncSetAttribute(gmat_kernel,  cudaFuncAttributeMaxDynamicSharedMemorySize, ZS_SM);

    int prep_elems = 3 * TWO_D * K2N + ORIG * DIM + DIM * 384 + DIM * ORIG;
    prep_kernel<<<(prep_elems + 255) / 256, 256>>>(conv_W, conv_b, embed_W, bil_W, fca_W);
    embed_kernel<<<NATOM / 64, 256>>>(atom_fea);

    int zs_blocks = (TWO_D * SPAD + DIM * SPAD + 255) / 256;
    int buf = 0;
    for (int l = 0; l < 3; l++) {
        zero_stats<<<zs_blocks, 256>>>();
        convz_kernel<<<NATOM * MNBR / 64, 256, CZ_SMEM>>>(l, buf, nbr_fea, nbr_idx);
        reduce_kernel<<<NATOM / 16, 256>>>(l, bn1_g, bn1_b);
        bnres_kernel<<<(NATOM * DIM) / 256, 256>>>(l, buf, bn2_g, bn2_b);
        buf = 1 - buf;
    }

    gmat_kernel<<<dim3(NCRY * NA / 64, 3), 256, ZS_SM>>>(buf, cidx);
    edge_kernel<<<dim3(NCRY, 16), 256>>>(buf, cidx, bil_b, fc1_W, fc1_b, out);
    atomout_kernel<<<NCRY * NA, 96>>>(buf, cidx, fca_b, out + (long)NCRY * NA * NA * 6);
}

// round 12
// speedup vs baseline: 2.4136x; 1.0395x over previous
#include <cuda_runtime.h>
#include <cuda_fp16.h>
#include <math.h>
#include <stdint.h>

#define NATOM 32768
#define MNBR 12
#define DIM 64
#define FNBR 41
#define ORIG 92
#define TWO_D 128
#define KTOT 169
#define NCRY 512
#define NA 64
#define CNT1F (393216.0f)
#define CNT2F (32768.0f)
#define EPSBN 1e-5f

#define K2N 88          // u32 (half2) count per B row: K=170 padded to 176 halves
#define AP 92           // A smem pitch in u32
#define BP 92           // B smem pitch in u32
#define NKS 11          // k-steps of 16
#define SPAD 32         // stat array stride (32 floats = 128B) to spread LTS slices
#define NTILE (NATOM * MNBR / 64)   // 6144 output tiles
#define CZGRID 444                   // persistent CTAs (3/SM x 148)

// ---------------- scratch (device globals; no allocation) ----------------
__device__ float g_x[2][NATOM * DIM];
__device__ uint32_t g_z[NATOM * MNBR * 64];          // z as half2, 100 MB
__device__ float g_summed[NATOM * DIM];
__device__ float g_G[NCRY * NA * 384];               // 50 MB
__device__ uint32_t g_WnH[3 * TWO_D * K2N];          // fused W half2 [l][n][k2]
__device__ float g_embT[ORIG * DIM];                 // [k][d]
__device__ float g_bilT[DIM * 6 * DIM];              // [d][o*64+k]
__device__ float g_fcaT[DIM * ORIG];                 // [k][c]
// padded stat arrays: one 128B line per channel -> many LTS slices
__device__ float g_s1[TWO_D * SPAD], g_ss1[TWO_D * SPAD];
__device__ float g_s2[DIM * SPAD], g_ss2[DIM * SPAD];

__device__ __forceinline__ float softplusf(float v) {
    return v > 20.0f ? v : log1pf(expf(v));
}
// fast softplus * sigmoid gate (approx intrinsics; err ~1e-6 rel, far below fp16 z noise)
__device__ __forceinline__ float gatef(float fv, float cv) {
    float sp = (cv > 15.0f) ? cv : __logf(1.0f + __expf(cv));
    return __fdividef(sp, 1.0f + __expf(-fv));
}
__device__ __forceinline__ void mma_f16(float* c, const uint32_t* a, const uint32_t* b) {
    asm volatile(
        "mma.sync.aligned.m16n8k16.row.col.f32.f16.f16.f32 "
        "{%0,%1,%2,%3}, {%4,%5,%6,%7}, {%8,%9}, {%0,%1,%2,%3};"
        : "+f"(c[0]), "+f"(c[1]), "+f"(c[2]), "+f"(c[3])
        : "r"(a[0]), "r"(a[1]), "r"(a[2]), "r"(a[3]), "r"(b[0]), "r"(b[1]));
}
__device__ __forceinline__ void ldsm4(uint32_t* r, uint32_t addr) {
    asm volatile("ldmatrix.sync.aligned.m8n8.x4.shared.b16 {%0,%1,%2,%3}, [%4];"
                 : "=r"(r[0]), "=r"(r[1]), "=r"(r[2]), "=r"(r[3]) : "r"(addr));
}

// ---------------- prep: fused weight layout ----------------
__global__ void prep_kernel(const float* __restrict__ conv_W,
                            const float* __restrict__ conv_b,
                            const float* __restrict__ embed_W,
                            const float* __restrict__ bil_W,
                            const float* __restrict__ fca_W) {
    int idx = blockIdx.x * blockDim.x + threadIdx.x;
    if (idx < 3 * TWO_D * K2N) {                      // g_WnH [l][n][j]
        int l = idx / (TWO_D * K2N), r = idx % (TWO_D * K2N);
        int n = r / K2N, j = r % K2N;
        int k0 = 2 * j, k1 = 2 * j + 1;
        const float* wr = conv_W + (l * TWO_D + n) * KTOT;
        float a = (k0 < KTOT) ? wr[k0] : (k0 == KTOT ? conv_b[l * TWO_D + n] : 0.f);
        float b = (k1 < KTOT) ? wr[k1] : (k1 == KTOT ? conv_b[l * TWO_D + n] : 0.f);
        __half2 h = __floats2half2_rn(a, b);
        g_WnH[idx] = *(uint32_t*)&h;
        return;
    }
    int i2 = idx - 3 * TWO_D * K2N;
    if (i2 < ORIG * DIM) {                            // g_embT [k][d]
        int k = i2 / DIM, d = i2 % DIM;
        g_embT[i2] = embed_W[d * ORIG + k];
        return;
    }
    int i3 = i2 - ORIG * DIM;
    if (i3 < DIM * 6 * DIM) {                         // g_bilT [d][o*64+k]
        int d = i3 / 384, ok = i3 % 384;
        int o = ok >> 6, k2 = ok & 63;
        g_bilT[i3] = bil_W[(o * DIM + d) * DIM + k2];
        return;
    }
    int i4 = i3 - DIM * 6 * DIM;
    if (i4 < DIM * ORIG) {
        int k = i4 / ORIG, c = i4 % ORIG;
        g_fcaT[i4] = fca_W[c * DIM + k];
    }
}

// ---------------- embedding: x = atom_fea @ embed_W^T  (K=92) ----------------
__global__ __launch_bounds__(256) void embed_kernel(const float* __restrict__ atom_fea) {
    __shared__ float As[64 * ORIG];
    __shared__ float Ws[ORIG * DIM];
    int t = threadIdx.x;
    int rb = blockIdx.x * 64;
    for (int e = t; e < ORIG * DIM; e += 256) Ws[e] = g_embT[e];
    int warp = t >> 5, lane = t & 31;
    for (int m = warp; m < 64; m += 8) {
        const float* row = atom_fea + (rb + m) * ORIG;
        As[m * ORIG + lane] = row[lane];
        As[m * ORIG + 32 + lane] = row[32 + lane];
        if (lane < ORIG - 64) As[m * ORIG + 64 + lane] = row[64 + lane];
    }
    __syncthreads();
    int ty = t >> 5, tx = t & 31;
    float acc[8][2];
#pragma unroll
    for (int i = 0; i < 8; i++) { acc[i][0] = 0.f; acc[i][1] = 0.f; }
    for (int k = 0; k < ORIG; k++) {
        float2 b = *(const float2*)&Ws[k * DIM + tx * 2];
#pragma unroll
        for (int i = 0; i < 8; i++) {
            float a = As[(ty * 8 + i) * ORIG + k];
            acc[i][0] = fmaf(a, b.x, acc[i][0]);
            acc[i][1] = fmaf(a, b.y, acc[i][1]);
        }
    }
#pragma unroll
    for (int i = 0; i < 8; i++)
        *(float2*)&g_x[0][(rb + ty * 8 + i) * DIM + tx * 2] = make_float2(acc[i][0], acc[i][1]);
}

// ---------------- stat zeroing (padded arrays; every layer) ----------------
__global__ void zero_stats() {
    int t = blockIdx.x * 256 + threadIdx.x;
    if (t < TWO_D * SPAD) { g_s1[t] = 0.f; g_ss1[t] = 0.f; }
    int u = t - TWO_D * SPAD;
    if (u >= 0 && u < DIM * SPAD) { g_s2[u] = 0.f; g_ss2[u] = 0.f; }
}

// ---------------- fused conv GEMM (persistent CTAs, B resident in smem) ----------------
#define CZ_SMEM ((64 * AP + 128 * BP) * 4)

__global__ __launch_bounds__(256, 3) void convz_kernel(int l, int buf,
                                                       const float* __restrict__ nbr_fea,
                                                       const int* __restrict__ nbr_idx) {
    extern __shared__ uint32_t smu[];
    uint32_t* As2 = smu;               // [64][AP]
    uint32_t* Bs2 = smu + 64 * AP;     // [128][BP]
    __shared__ float redS[128], redQ[128];
    __shared__ int nbr_s[64];
    int t = threadIdx.x, w = t >> 5, lane = t & 31;
    const float* x = g_x[buf];
    if (t < 128) { redS[t] = 0.f; redQ[t] = 0.f; }
    // B: load fused weights ONCE per persistent CTA
    {
        const uint32_t* src = g_WnH + l * TWO_D * K2N;
        for (int e = t; e < TWO_D * K2N; e += 256)
            Bs2[(e / K2N) * BP + (e % K2N)] = src[e];
    }

    int wm = w & 1, wn = w >> 1;             // wm 0..1 (32 rows), wn 0..3 (32 cols)
    int q = lane >> 2, r = lane & 3;
    uint32_t sAs = (uint32_t)__cvta_generic_to_shared(As2);
    uint32_t sBs = (uint32_t)__cvta_generic_to_shared(Bs2);
    uint32_t aAddr0 = sAs + (((wm * 32) + (lane & 7) + ((lane >> 3) & 1) * 8) * AP +
                             ((lane >> 4) & 1) * 4) * 4;
    uint32_t aAddr1 = aAddr0 + 16 * AP * 4;
    uint32_t bAddr0 = sBs + (((wn * 32) + (lane & 7) + ((lane >> 4) & 1) * 8) * BP +
                             ((lane >> 3) & 1) * 4) * 4;
    uint32_t bAddr1 = bAddr0 + 16 * BP * 4;

    for (int tile = blockIdx.x; tile < NTILE; tile += CZGRID) {
        int rb = tile * 64;
        if (t < 64) nbr_s[t] = nbr_idx[rb + t];
        __syncthreads();   // prev tile's mainloop done with As; nbr_s visible
        // A: gather [x_self | x_nbr | nbr_fea | 1 | pad] as half2
        for (int m = w; m < 64; m += 8) {
            uint32_t* Ar = As2 + m * AP;
            int nself = (rb + m) / MNBR;
            int nbr = nbr_s[m];
            float2 vs = ((const float2*)(x + nself * DIM))[lane];
            __half2 hs = __floats2half2_rn(vs.x, vs.y);
            Ar[lane] = *(uint32_t*)&hs;
            float2 vn = ((const float2*)(x + nbr * DIM))[lane];
            __half2 hn = __floats2half2_rn(vn.x, vn.y);
            Ar[32 + lane] = *(uint32_t*)&hn;
            if (lane < 20) {
                const float* nf = nbr_fea + (long)(rb + m) * FNBR;
                __half2 hh = __floats2half2_rn(nf[2 * lane], nf[2 * lane + 1]);
                Ar[64 + lane] = *(uint32_t*)&hh;
            } else if (lane == 20) {
                const float* nf = nbr_fea + (long)(rb + m) * FNBR;
                __half2 hh = __floats2half2_rn(nf[40], 1.0f);
                Ar[84] = *(uint32_t*)&hh;
            } else if (lane < 24) {
                Ar[64 + lane] = 0u;     // u32 85..87
            }
        }
        __syncthreads();

        float c[2][4][4];
#pragma unroll
        for (int mt = 0; mt < 2; mt++)
#pragma unroll
            for (int nf = 0; nf < 4; nf++)
#pragma unroll
                for (int e = 0; e < 4; e++) c[mt][nf][e] = 0.f;

#pragma unroll
        for (int ks = 0; ks < NKS; ks++) {
            uint32_t ko = ks * 32;               // 8 u32 per step
            uint32_t a[2][4], b01[4], b23[4];
            ldsm4(a[0], aAddr0 + ko);
            ldsm4(a[1], aAddr1 + ko);
            ldsm4(b01, bAddr0 + ko);
            ldsm4(b23, bAddr1 + ko);
            uint32_t bf[4][2] = {{b01[0], b01[1]}, {b01[2], b01[3]},
                                 {b23[0], b23[1]}, {b23[2], b23[3]}};
#pragma unroll
            for (int mt = 0; mt < 2; mt++)
#pragma unroll
                for (int nf = 0; nf < 4; nf++)
                    mma_f16(c[mt][nf], a[mt], bf[nf]);
        }

        // epilogue: half2 round-trip (stats on rounded values), store z fp16
#pragma unroll
        for (int nf = 0; nf < 4; nf++) {
            int cc = wn * 32 + nf * 8 + r * 2;
            float s0 = 0.f, s1 = 0.f, q0 = 0.f, q1 = 0.f;
#pragma unroll
            for (int mt = 0; mt < 2; mt++) {
                int m0 = wm * 32 + mt * 16 + q;
                int row0 = rb + m0, row1 = row0 + 8;
                __half2 h0 = __floats2half2_rn(c[mt][nf][0], c[mt][nf][1]);
                __half2 h1 = __floats2half2_rn(c[mt][nf][2], c[mt][nf][3]);
                g_z[(long)row0 * 64 + (cc >> 1)] = *(uint32_t*)&h0;
                g_z[(long)row1 * 64 + (cc >> 1)] = *(uint32_t*)&h1;
                float2 v0 = __half22float2(h0);
                float2 v1 = __half22float2(h1);
                s0 += v0.x + v1.x; q0 += v0.x * v0.x + v1.x * v1.x;
                s1 += v0.y + v1.y; q1 += v0.y * v0.y + v1.y * v1.y;
            }
#pragma unroll
            for (int off = 4; off < 32; off <<= 1) {
                s0 += __shfl_xor_sync(0xffffffffu, s0, off);
                s1 += __shfl_xor_sync(0xffffffffu, s1, off);
                q0 += __shfl_xor_sync(0xffffffffu, q0, off);
                q1 += __shfl_xor_sync(0xffffffffu, q1, off);
            }
            if (lane < 4) {
                atomicAdd(&redS[cc], s0);
                atomicAdd(&redS[cc + 1], s1);
                atomicAdd(&redQ[cc], q0);
                atomicAdd(&redQ[cc + 1], q1);
            }
        }
    }
    // one global-atomic flush per persistent CTA
    __syncthreads();
    if (t < 128) {
        atomicAdd(&g_s1[t * SPAD], redS[t]);
        atomicAdd(&g_ss1[t * SPAD], redQ[t]);
    }
}

// ---------------- BN1 + gate + sum over neighbors (half2 z), BN2 stats ----------------
__global__ __launch_bounds__(256) void reduce_kernel(int l,
                                                     const float* __restrict__ bn1_g,
                                                     const float* __restrict__ bn1_b) {
    __shared__ float r2S[64], r2Q[64];
    int c = threadIdx.x & 31, grp = threadIdx.x >> 5;
    int d0 = 2 * c;
    if (threadIdx.x < 64) { r2S[threadIdx.x] = 0.f; r2Q[threadIdx.x] = 0.f; }
    __syncthreads();
    float inv = 1.0f / CNT1F;
    float mf0 = g_s1[d0 * SPAD] * inv, mf1 = g_s1[(d0 + 1) * SPAD] * inv;
    float vf0 = g_ss1[d0 * SPAD] * inv - mf0 * mf0;
    float vf1 = g_ss1[(d0 + 1) * SPAD] * inv - mf1 * mf1;
    float scf0 = rsqrtf(vf0 + EPSBN) * bn1_g[l * TWO_D + d0];
    float scf1 = rsqrtf(vf1 + EPSBN) * bn1_g[l * TWO_D + d0 + 1];
    float shf0 = bn1_b[l * TWO_D + d0] - mf0 * scf0;
    float shf1 = bn1_b[l * TWO_D + d0 + 1] - mf1 * scf1;
    float mc0 = g_s1[(64 + d0) * SPAD] * inv, mc1 = g_s1[(64 + d0 + 1) * SPAD] * inv;
    float vc0 = g_ss1[(64 + d0) * SPAD] * inv - mc0 * mc0;
    float vc1 = g_ss1[(64 + d0 + 1) * SPAD] * inv - mc1 * mc1;
    float scc0 = rsqrtf(vc0 + EPSBN) * bn1_g[l * TWO_D + 64 + d0];
    float scc1 = rsqrtf(vc1 + EPSBN) * bn1_g[l * TWO_D + 64 + d0 + 1];
    float shc0 = bn1_b[l * TWO_D + 64 + d0] - mc0 * scc0;
    float shc1 = bn1_b[l * TWO_D + 64 + d0 + 1] - mc1 * scc1;

    float ls0 = 0.f, ls1 = 0.f, lq0 = 0.f, lq1 = 0.f;
    int n0 = blockIdx.x * 16 + grp * 2;
#pragma unroll
    for (int a = 0; a < 2; a++) {
        int n = n0 + a;
        const uint32_t* zr = g_z + (long)n * MNBR * 64;
        uint32_t zfp[MNBR], zcp[MNBR];
#pragma unroll
        for (int m = 0; m < MNBR; m++) zfp[m] = __ldg(&zr[m * 64 + c]);
#pragma unroll
        for (int m = 0; m < MNBR; m++) zcp[m] = __ldg(&zr[m * 64 + 32 + c]);
        float a0 = 0.f, a1 = 0.f;
#pragma unroll
        for (int m = 0; m < MNBR; m++) {
            float2 zf = __half22float2(*(__half2*)&zfp[m]);
            float2 zc = __half22float2(*(__half2*)&zcp[m]);
            a0 += gatef(zf.x * scf0 + shf0, zc.x * scc0 + shc0);
            a1 += gatef(zf.y * scf1 + shf1, zc.y * scc1 + shc1);
        }
        *(float2*)&g_summed[n * DIM + d0] = make_float2(a0, a1);
        ls0 += a0; lq0 += a0 * a0;
        ls1 += a1; lq1 += a1 * a1;
    }
    // stage BN2 stats in smem (8 warps share channels), then 1 global atomic/ch/block
    atomicAdd(&r2S[d0], ls0);
    atomicAdd(&r2S[d0 + 1], ls1);
    atomicAdd(&r2Q[d0], lq0);
    atomicAdd(&r2Q[d0 + 1], lq1);
    __syncthreads();
    if (threadIdx.x < 64) {
        atomicAdd(&g_s2[threadIdx.x * SPAD], r2S[threadIdx.x]);
        atomicAdd(&g_ss2[threadIdx.x * SPAD], r2Q[threadIdx.x]);
    }
}

// ---------------- BN2 + residual softplus -> x_out ----------------
__global__ __launch_bounds__(256) void bnres_kernel(int l, int buf,
                                                    const float* __restrict__ bn2_g,
                                                    const float* __restrict__ bn2_b) {
    int gid = blockIdx.x * 256 + threadIdx.x;
    int d = gid & 63;
    float inv = 1.0f / CNT2F;
    float m2 = g_s2[d * SPAD] * inv;
    float v2 = g_ss2[d * SPAD] * inv - m2 * m2;
    float sc = rsqrtf(v2 + EPSBN) * bn2_g[l * DIM + d];
    float sh = bn2_b[l * DIM + d] - m2 * sc;
    float v = g_x[buf][gid] + g_summed[gid] * sc + sh;
    g_x[1 - buf][gid] = (v > 15.0f) ? v : __logf(1.0f + __expf(v));
}

// ---------------- G[bi, o*64+k] = f[bi,:] @ bilT  (K=64, scalar) ----------------
__global__ __launch_bounds__(256) void gmat_kernel(int buf, const int* __restrict__ cidx) {
    extern __shared__ float sm[];
    float* Ws = sm;                // [64][128]
    float* As = sm + 64 * TWO_D;   // [64][64]
    __shared__ int cid_s[64];
    int t = threadIdx.x;
    int rb = blockIdx.x * 64;
    int co = blockIdx.y * 128;
    const float* x = g_x[buf];
    if (t < 64) cid_s[t] = cidx[rb + t];
    for (int e = t; e < 64 * TWO_D; e += 256) {
        int k = e >> 7, oc = e & 127;
        Ws[e] = g_bilT[k * 384 + co + oc];
    }
    __syncthreads();
    int warp = t >> 5, lane = t & 31;
    for (int m = warp; m < 64; m += 8) {
        int a = cid_s[m];
        As[m * 64 + lane]      = x[a * DIM + lane];
        As[m * 64 + 32 + lane] = x[a * DIM + 32 + lane];
    }
    __syncthreads();
    int ty = t >> 5, tx = t & 31;
    float acc[8][4];
#pragma unroll
    for (int i = 0; i < 8; i++)
#pragma unroll
        for (int c = 0; c < 4; c++) acc[i][c] = 0.f;
    for (int k = 0; k < 64; k++) {
        float4 b = *(const float4*)&Ws[k * TWO_D + tx * 4];
#pragma unroll
        for (int i = 0; i < 8; i++) {
            float a = As[(ty * 8 + i) * 64 + k];
            acc[i][0] = fmaf(a, b.x, acc[i][0]);
            acc[i][1] = fmaf(a, b.y, acc[i][1]);
            acc[i][2] = fmaf(a, b.z, acc[i][2]);
            acc[i][3] = fmaf(a, b.w, acc[i][3]);
        }
    }
#pragma unroll
    for (int i = 0; i < 8; i++)
        *(float4*)&g_G[(long)(rb + ty * 8 + i) * 384 + co + tx * 4] =
            make_float4(acc[i][0], acc[i][1], acc[i][2], acc[i][3]);
}

// ---------------- edge: per-pair bilinear dot + fc1 + log_softmax ----------------
__global__ __launch_bounds__(256) void edge_kernel(int buf, const int* __restrict__ cidx,
                                                   const float* __restrict__ bil_b,
                                                   const float* __restrict__ fc1_W,
                                                   const float* __restrict__ fc1_b,
                                                   float* __restrict__ out) {
    __shared__ float f_s[64][65];
    __shared__ float Gi[4][384];
    __shared__ int cid_s[64];
    __shared__ float s_fc1W[36], s_fc1b[6], s_bilb[6];
    int b = blockIdx.x, it = blockIdx.y, t = threadIdx.x;
    const float* x = g_x[buf];
    if (t < 64) cid_s[t] = cidx[b * 64 + t];
    if (t < 36) s_fc1W[t] = fc1_W[t];
    if (t >= 64 && t < 70) s_fc1b[t - 64] = fc1_b[t - 64];
    if (t >= 96 && t < 102) s_bilb[t - 96] = bil_b[t - 96];
    __syncthreads();
    for (int e = t; e < 4096; e += 256) {
        int m = e >> 6, k = e & 63;
        f_s[m][k] = x[cid_s[m] * DIM + k];
    }
    for (int e = t; e < 1536; e += 256) {
        int i4 = e / 384, ok = e % 384;
        Gi[i4][ok] = g_G[(long)(b * 64 + it * 4 + i4) * 384 + ok];
    }
    __syncthreads();
    int i4 = t >> 6, j = t & 63;
    float ev[6];
#pragma unroll
    for (int o = 0; o < 6; o++) {
        float a = s_bilb[o];
#pragma unroll 16
        for (int k = 0; k < 64; k++) a = fmaf(Gi[i4][o * 64 + k], f_s[j][k], a);
        ev[o] = a;
    }
    float tr[6];
#pragma unroll
    for (int r = 0; r < 6; r++) {
        float a = s_fc1b[r];
#pragma unroll
        for (int o = 0; o < 6; o++) a = fmaf(s_fc1W[r * 6 + o], ev[o], a);
        tr[r] = a;
    }
    float mx = tr[0];
#pragma unroll
    for (int r = 1; r < 6; r++) mx = fmaxf(mx, tr[r]);
    float se = 0.f;
#pragma unroll
    for (int r = 0; r < 6; r++) se += expf(tr[r] - mx);
    float lse = mx + logf(se);
    int pair = (it * 4 + i4) * 64 + j;
    float* op = out + ((long)b * 4096 + pair) * 6;
#pragma unroll
    for (int r = 0; r < 6; r++) op[r] = tr[r] - lse;
}

// ---------------- atom_out = f @ fca_W^T + fca_b ----------------
__global__ __launch_bounds__(96) void atomout_kernel(int buf, const int* __restrict__ cidx,
                                                     const float* __restrict__ fca_b,
                                                     float* __restrict__ out2) {
    __shared__ float xr[64];
    int t = threadIdx.x;
    int r = blockIdx.x;
    int atom = cidx[r];
    if (t < 64) xr[t] = g_x[buf][atom * DIM + t];
    __syncthreads();
    if (t < ORIG) {
        float a = fca_b[t];
#pragma unroll 16
        for (int k = 0; k < 64; k++) a = fmaf(xr[k], g_fcaT[k * ORIG + t], a);
        out2[(long)r * ORIG + t] = a;
    }
}

// ---------------- launch ----------------
#define ZS_SM ((64 * TWO_D + 64 * 64) * 4)

extern "C" void kernel_launch(void* const* d_in, const int* in_sizes, int n_in,
                              void* d_out, int out_size) {
    (void)in_sizes; (void)n_in; (void)out_size;
    const float* atom_fea = (const float*)d_in[0];
    const float* nbr_fea  = (const float*)d_in[1];
    const int*   nbr_idx  = (const int*)d_in[2];
    const int*   cidx     = (const int*)d_in[3];
    const float* embed_W  = (const float*)d_in[4];
    const float* conv_W   = (const float*)d_in[5];
    const float* conv_b   = (const float*)d_in[6];
    const float* bn1_g    = (const float*)d_in[7];
    const float* bn1_b    = (const float*)d_in[8];
    const float* bn2_g    = (const float*)d_in[9];
    const float* bn2_b    = (const float*)d_in[10];
    const float* bil_W    = (const float*)d_in[11];
    const float* bil_b    = (const float*)d_in[12];
    const float* fc1_W    = (const float*)d_in[13];
    const float* fc1_b    = (const float*)d_in[14];
    const float* fca_W    = (const float*)d_in[15];
    const float* fca_b    = (const float*)d_in[16];
    float* out = (float*)d_out;

    cudaFuncSetAttribute(convz_kernel, cudaFuncAttributeMaxDynamicSharedMemorySize, CZ_SMEM);
    cudaFuncSetAttribute(gmat_kernel,  cudaFuncAttributeMaxDynamicSharedMemorySize, ZS_SM);

    int prep_elems = 3 * TWO_D * K2N + ORIG * DIM + DIM * 384 + DIM * ORIG;
    prep_kernel<<<(prep_elems + 255) / 256, 256>>>(conv_W, conv_b, embed_W, bil_W, fca_W);
    embed_kernel<<<NATOM / 64, 256>>>(atom_fea);

    int zs_blocks = (TWO_D * SPAD + DIM * SPAD + 255) / 256;
    int buf = 0;
    for (int l = 0; l < 3; l++) {
        zero_stats<<<zs_blocks, 256>>>();
        convz_kernel<<<CZGRID, 256, CZ_SMEM>>>(l, buf, nbr_fea, nbr_idx);
        reduce_kernel<<<NATOM / 16, 256>>>(l, bn1_g, bn1_b);
        bnres_kernel<<<(NATOM * DIM) / 256, 256>>>(l, buf, bn2_g, bn2_b);
        buf = 1 - buf;
    }

    gmat_kernel<<<dim3(NCRY * NA / 64, 3), 256, ZS_SM>>>(buf, cidx);
    edge_kernel<<<dim3(NCRY, 16), 256>>>(buf, cidx, bil_b, fc1_W, fc1_b, out);
    atomout_kernel<<<NCRY * NA, 96>>>(buf, cidx, fca_b, out + (long)NCRY * NA * NA * 6);
}

// round 13
// speedup vs baseline: 2.4807x; 1.0278x over previous
#include <cuda_runtime.h>
#include <cuda_fp16.h>
#include <math.h>
#include <stdint.h>

#define NATOM 32768
#define MNBR 12
#define DIM 64
#define FNBR 41
#define ORIG 92
#define TWO_D 128
#define KTOT 169
#define NCRY 512
#define NA 64
#define CNT1F (393216.0f)
#define CNT2F (32768.0f)
#define EPSBN 1e-5f

#define K2N 88          // u32 (half2) count per B row: K=170 padded to 176 halves
#define AP 92           // A smem pitch in u32
#define BP 92           // B smem pitch in u32
#define NKS 11          // k-steps of 16
#define SPAD 32         // stat array stride (32 floats = 128B) to spread LTS slices
#define NTILE (NATOM * MNBR / 64)   // 6144 output tiles
#define CZGRID 444                   // persistent CTAs (3/SM x 148)
#define ZBP 68          // z staging pitch in u32 (4q+r covers all banks)

// ---------------- scratch (device globals; no allocation) ----------------
__device__ float g_x[2][NATOM * DIM];
__device__ uint32_t g_z[NATOM * MNBR * 64];          // z as half2, 100 MB
__device__ float g_summed[NATOM * DIM];
__device__ float g_G[NCRY * NA * 384];               // 50 MB
__device__ uint32_t g_WnH[3 * TWO_D * K2N];          // fused W half2 [l][n][k2]
__device__ float g_embT[ORIG * DIM];                 // [k][d]
__device__ float g_bilT[DIM * 6 * DIM];              // [d][o*64+k]
__device__ float g_fcaT[DIM * ORIG];                 // [k][c]
// padded stat arrays: one 128B line per channel -> many LTS slices
__device__ float g_s1[TWO_D * SPAD], g_ss1[TWO_D * SPAD];
__device__ float g_s2[DIM * SPAD], g_ss2[DIM * SPAD];

__device__ __forceinline__ float softplusf(float v) {
    return v > 20.0f ? v : log1pf(expf(v));
}
// fast softplus * sigmoid gate (approx intrinsics; err ~1e-6 rel, far below fp16 z noise)
__device__ __forceinline__ float gatef(float fv, float cv) {
    float sp = (cv > 15.0f) ? cv : __logf(1.0f + __expf(cv));
    return __fdividef(sp, 1.0f + __expf(-fv));
}
__device__ __forceinline__ void mma_f16(float* c, const uint32_t* a, const uint32_t* b) {
    asm volatile(
        "mma.sync.aligned.m16n8k16.row.col.f32.f16.f16.f32 "
        "{%0,%1,%2,%3}, {%4,%5,%6,%7}, {%8,%9}, {%0,%1,%2,%3};"
        : "+f"(c[0]), "+f"(c[1]), "+f"(c[2]), "+f"(c[3])
        : "r"(a[0]), "r"(a[1]), "r"(a[2]), "r"(a[3]), "r"(b[0]), "r"(b[1]));
}
__device__ __forceinline__ void ldsm4(uint32_t* r, uint32_t addr) {
    asm volatile("ldmatrix.sync.aligned.m8n8.x4.shared.b16 {%0,%1,%2,%3}, [%4];"
                 : "=r"(r[0]), "=r"(r[1]), "=r"(r[2]), "=r"(r[3]) : "r"(addr));
}

// ---------------- prep: fused weight layout ----------------
__global__ void prep_kernel(const float* __restrict__ conv_W,
                            const float* __restrict__ conv_b,
                            const float* __restrict__ embed_W,
                            const float* __restrict__ bil_W,
                            const float* __restrict__ fca_W) {
    int idx = blockIdx.x * blockDim.x + threadIdx.x;
    if (idx < 3 * TWO_D * K2N) {                      // g_WnH [l][n][j]
        int l = idx / (TWO_D * K2N), r = idx % (TWO_D * K2N);
        int n = r / K2N, j = r % K2N;
        int k0 = 2 * j, k1 = 2 * j + 1;
        const float* wr = conv_W + (l * TWO_D + n) * KTOT;
        float a = (k0 < KTOT) ? wr[k0] : (k0 == KTOT ? conv_b[l * TWO_D + n] : 0.f);
        float b = (k1 < KTOT) ? wr[k1] : (k1 == KTOT ? conv_b[l * TWO_D + n] : 0.f);
        __half2 h = __floats2half2_rn(a, b);
        g_WnH[idx] = *(uint32_t*)&h;
        return;
    }
    int i2 = idx - 3 * TWO_D * K2N;
    if (i2 < ORIG * DIM) {                            // g_embT [k][d]
        int k = i2 / DIM, d = i2 % DIM;
        g_embT[i2] = embed_W[d * ORIG + k];
        return;
    }
    int i3 = i2 - ORIG * DIM;
    if (i3 < DIM * 6 * DIM) {                         // g_bilT [d][o*64+k]
        int d = i3 / 384, ok = i3 % 384;
        int o = ok >> 6, k2 = ok & 63;
        g_bilT[i3] = bil_W[(o * DIM + d) * DIM + k2];
        return;
    }
    int i4 = i3 - DIM * 6 * DIM;
    if (i4 < DIM * ORIG) {
        int k = i4 / ORIG, c = i4 % ORIG;
        g_fcaT[i4] = fca_W[c * DIM + k];
    }
}

// ---------------- embedding: x = atom_fea @ embed_W^T  (K=92) ----------------
__global__ __launch_bounds__(256) void embed_kernel(const float* __restrict__ atom_fea) {
    __shared__ float As[64 * ORIG];
    __shared__ float Ws[ORIG * DIM];
    int t = threadIdx.x;
    int rb = blockIdx.x * 64;
    for (int e = t; e < ORIG * DIM; e += 256) Ws[e] = g_embT[e];
    int warp = t >> 5, lane = t & 31;
    for (int m = warp; m < 64; m += 8) {
        const float* row = atom_fea + (rb + m) * ORIG;
        As[m * ORIG + lane] = row[lane];
        As[m * ORIG + 32 + lane] = row[32 + lane];
        if (lane < ORIG - 64) As[m * ORIG + 64 + lane] = row[64 + lane];
    }
    __syncthreads();
    int ty = t >> 5, tx = t & 31;
    float acc[8][2];
#pragma unroll
    for (int i = 0; i < 8; i++) { acc[i][0] = 0.f; acc[i][1] = 0.f; }
    for (int k = 0; k < ORIG; k++) {
        float2 b = *(const float2*)&Ws[k * DIM + tx * 2];
#pragma unroll
        for (int i = 0; i < 8; i++) {
            float a = As[(ty * 8 + i) * ORIG + k];
            acc[i][0] = fmaf(a, b.x, acc[i][0]);
            acc[i][1] = fmaf(a, b.y, acc[i][1]);
        }
    }
#pragma unroll
    for (int i = 0; i < 8; i++)
        *(float2*)&g_x[0][(rb + ty * 8 + i) * DIM + tx * 2] = make_float2(acc[i][0], acc[i][1]);
}

// ---------------- stat zeroing (padded arrays; every layer) ----------------
__global__ void zero_stats() {
    int t = blockIdx.x * 256 + threadIdx.x;
    if (t < TWO_D * SPAD) { g_s1[t] = 0.f; g_ss1[t] = 0.f; }
    int u = t - TWO_D * SPAD;
    if (u >= 0 && u < DIM * SPAD) { g_s2[u] = 0.f; g_ss2[u] = 0.f; }
}

// ---------------- fused conv GEMM (persistent CTAs, staged coalesced z-store) ----------------
#define CZ_SMEM ((64 * AP + 128 * BP) * 4)

__global__ __launch_bounds__(256, 3) void convz_kernel(int l, int buf,
                                                       const float* __restrict__ nbr_fea,
                                                       const int* __restrict__ nbr_idx) {
    extern __shared__ uint32_t smu[];
    uint32_t* As2 = smu;               // [64][AP]; reused as z staging [64][ZBP]
    uint32_t* Bs2 = smu + 64 * AP;     // [128][BP]
    __shared__ float redS[128], redQ[128];
    __shared__ int nbr_s[64];
    int t = threadIdx.x, w = t >> 5, lane = t & 31;
    const float* x = g_x[buf];
    if (t < 128) { redS[t] = 0.f; redQ[t] = 0.f; }
    // B: load fused weights ONCE per persistent CTA
    {
        const uint32_t* src = g_WnH + l * TWO_D * K2N;
        for (int e = t; e < TWO_D * K2N; e += 256)
            Bs2[(e / K2N) * BP + (e % K2N)] = src[e];
    }

    int wm = w & 1, wn = w >> 1;             // wm 0..1 (32 rows), wn 0..3 (32 cols)
    int q = lane >> 2, r = lane & 3;
    uint32_t sAs = (uint32_t)__cvta_generic_to_shared(As2);
    uint32_t sBs = (uint32_t)__cvta_generic_to_shared(Bs2);
    uint32_t aAddr0 = sAs + (((wm * 32) + (lane & 7) + ((lane >> 3) & 1) * 8) * AP +
                             ((lane >> 4) & 1) * 4) * 4;
    uint32_t aAddr1 = aAddr0 + 16 * AP * 4;
    uint32_t bAddr0 = sBs + (((wn * 32) + (lane & 7) + ((lane >> 4) & 1) * 8) * BP +
                             ((lane >> 3) & 1) * 4) * 4;
    uint32_t bAddr1 = bAddr0 + 16 * BP * 4;

    for (int tile = blockIdx.x; tile < NTILE; tile += CZGRID) {
        int rb = tile * 64;
        if (t < 64) nbr_s[t] = nbr_idx[rb + t];
        __syncthreads();   // prior tile's z-staging reads done; nbr_s visible
        // A: gather [x_self | x_nbr | nbr_fea | 1 | pad] as half2
        for (int m = w; m < 64; m += 8) {
            uint32_t* Ar = As2 + m * AP;
            int nself = (rb + m) / MNBR;
            int nbr = nbr_s[m];
            float2 vs = ((const float2*)(x + nself * DIM))[lane];
            __half2 hs = __floats2half2_rn(vs.x, vs.y);
            Ar[lane] = *(uint32_t*)&hs;
            float2 vn = ((const float2*)(x + nbr * DIM))[lane];
            __half2 hn = __floats2half2_rn(vn.x, vn.y);
            Ar[32 + lane] = *(uint32_t*)&hn;
            if (lane < 20) {
                const float* nf = nbr_fea + (long)(rb + m) * FNBR;
                __half2 hh = __floats2half2_rn(nf[2 * lane], nf[2 * lane + 1]);
                Ar[64 + lane] = *(uint32_t*)&hh;
            } else if (lane == 20) {
                const float* nf = nbr_fea + (long)(rb + m) * FNBR;
                __half2 hh = __floats2half2_rn(nf[40], 1.0f);
                Ar[84] = *(uint32_t*)&hh;
            } else if (lane < 24) {
                Ar[64 + lane] = 0u;     // u32 85..87
            }
        }
        __syncthreads();

        float c[2][4][4];
#pragma unroll
        for (int mt = 0; mt < 2; mt++)
#pragma unroll
            for (int nf = 0; nf < 4; nf++)
#pragma unroll
                for (int e = 0; e < 4; e++) c[mt][nf][e] = 0.f;

#pragma unroll
        for (int ks = 0; ks < NKS; ks++) {
            uint32_t ko = ks * 32;               // 8 u32 per step
            uint32_t a[2][4], b01[4], b23[4];
            ldsm4(a[0], aAddr0 + ko);
            ldsm4(a[1], aAddr1 + ko);
            ldsm4(b01, bAddr0 + ko);
            ldsm4(b23, bAddr1 + ko);
            uint32_t bf[4][2] = {{b01[0], b01[1]}, {b01[2], b01[3]},
                                 {b23[0], b23[1]}, {b23[2], b23[3]}};
#pragma unroll
            for (int mt = 0; mt < 2; mt++)
#pragma unroll
                for (int nf = 0; nf < 4; nf++)
                    mma_f16(c[mt][nf], a[mt], bf[nf]);
        }
        __syncthreads();   // all warps done reading As via ldmatrix

        // epilogue: half2 round-trip, stats in registers, stage z in smem (bank-clean)
        uint32_t* zbuf = As2;   // [64][ZBP]
#pragma unroll
        for (int nf = 0; nf < 4; nf++) {
            int cc = wn * 32 + nf * 8 + r * 2;
            int cu = cc >> 1;
            float s0 = 0.f, s1 = 0.f, q0 = 0.f, q1 = 0.f;
#pragma unroll
            for (int mt = 0; mt < 2; mt++) {
                int m0 = wm * 32 + mt * 16 + q;
                __half2 h0 = __floats2half2_rn(c[mt][nf][0], c[mt][nf][1]);
                __half2 h1 = __floats2half2_rn(c[mt][nf][2], c[mt][nf][3]);
                zbuf[m0 * ZBP + cu] = *(uint32_t*)&h0;
                zbuf[(m0 + 8) * ZBP + cu] = *(uint32_t*)&h1;
                float2 v0 = __half22float2(h0);
                float2 v1 = __half22float2(h1);
                s0 += v0.x + v1.x; q0 += v0.x * v0.x + v1.x * v1.x;
                s1 += v0.y + v1.y; q1 += v0.y * v0.y + v1.y * v1.y;
            }
#pragma unroll
            for (int off = 4; off < 32; off <<= 1) {
                s0 += __shfl_xor_sync(0xffffffffu, s0, off);
                s1 += __shfl_xor_sync(0xffffffffu, s1, off);
                q0 += __shfl_xor_sync(0xffffffffu, q0, off);
                q1 += __shfl_xor_sync(0xffffffffu, q1, off);
            }
            if (lane < 4) {
                atomicAdd(&redS[cc], s0);
                atomicAdd(&redS[cc + 1], s1);
                atomicAdd(&redQ[cc], q0);
                atomicAdd(&redQ[cc + 1], q1);
            }
        }
        __syncthreads();   // zbuf complete
        // coalesced z store: 4 x uint4 per thread (128B sectors)
#pragma unroll
        for (int e = 0; e < 4; e++) {
            int idx = e * 256 + t;          // 0..1023 uint4 slots
            int row = idx >> 4;             // 64 rows
            int c4 = (idx & 15) * 4;        // 16 uint4 per row
            uint4 v = *(uint4*)&zbuf[row * ZBP + c4];
            *(uint4*)&g_z[((long)(rb + row)) * 64 + c4] = v;
        }
    }
    // one global-atomic flush per persistent CTA
    __syncthreads();
    if (t < 128) {
        atomicAdd(&g_s1[t * SPAD], redS[t]);
        atomicAdd(&g_ss1[t * SPAD], redQ[t]);
    }
}

// ---------------- BN1 + gate + sum over neighbors (half2 z), BN2 stats ----------------
__global__ __launch_bounds__(256) void reduce_kernel(int l,
                                                     const float* __restrict__ bn1_g,
                                                     const float* __restrict__ bn1_b) {
    __shared__ float r2S[64], r2Q[64];
    int c = threadIdx.x & 31, grp = threadIdx.x >> 5;
    int d0 = 2 * c;
    if (threadIdx.x < 64) { r2S[threadIdx.x] = 0.f; r2Q[threadIdx.x] = 0.f; }
    __syncthreads();
    float inv = 1.0f / CNT1F;
    float mf0 = g_s1[d0 * SPAD] * inv, mf1 = g_s1[(d0 + 1) * SPAD] * inv;
    float vf0 = g_ss1[d0 * SPAD] * inv - mf0 * mf0;
    float vf1 = g_ss1[(d0 + 1) * SPAD] * inv - mf1 * mf1;
    float scf0 = rsqrtf(vf0 + EPSBN) * bn1_g[l * TWO_D + d0];
    float scf1 = rsqrtf(vf1 + EPSBN) * bn1_g[l * TWO_D + d0 + 1];
    float shf0 = bn1_b[l * TWO_D + d0] - mf0 * scf0;
    float shf1 = bn1_b[l * TWO_D + d0 + 1] - mf1 * scf1;
    float mc0 = g_s1[(64 + d0) * SPAD] * inv, mc1 = g_s1[(64 + d0 + 1) * SPAD] * inv;
    float vc0 = g_ss1[(64 + d0) * SPAD] * inv - mc0 * mc0;
    float vc1 = g_ss1[(64 + d0 + 1) * SPAD] * inv - mc1 * mc1;
    float scc0 = rsqrtf(vc0 + EPSBN) * bn1_g[l * TWO_D + 64 + d0];
    float scc1 = rsqrtf(vc1 + EPSBN) * bn1_g[l * TWO_D + 64 + d0 + 1];
    float shc0 = bn1_b[l * TWO_D + 64 + d0] - mc0 * scc0;
    float shc1 = bn1_b[l * TWO_D + 64 + d0 + 1] - mc1 * scc1;

    float ls0 = 0.f, ls1 = 0.f, lq0 = 0.f, lq1 = 0.f;
    int n0 = blockIdx.x * 16 + grp * 2;
#pragma unroll
    for (int a = 0; a < 2; a++) {
        int n = n0 + a;
        const uint32_t* zr = g_z + (long)n * MNBR * 64;
        uint32_t zfp[MNBR], zcp[MNBR];
#pragma unroll
        for (int m = 0; m < MNBR; m++) zfp[m] = __ldg(&zr[m * 64 + c]);
#pragma unroll
        for (int m = 0; m < MNBR; m++) zcp[m] = __ldg(&zr[m * 64 + 32 + c]);
        float a0 = 0.f, a1 = 0.f;
#pragma unroll
        for (int m = 0; m < MNBR; m++) {
            float2 zf = __half22float2(*(__half2*)&zfp[m]);
            float2 zc = __half22float2(*(__half2*)&zcp[m]);
            a0 += gatef(zf.x * scf0 + shf0, zc.x * scc0 + shc0);
            a1 += gatef(zf.y * scf1 + shf1, zc.y * scc1 + shc1);
        }
        *(float2*)&g_summed[n * DIM + d0] = make_float2(a0, a1);
        ls0 += a0; lq0 += a0 * a0;
        ls1 += a1; lq1 += a1 * a1;
    }
    // stage BN2 stats in smem (8 warps share channels), then 1 global atomic/ch/block
    atomicAdd(&r2S[d0], ls0);
    atomicAdd(&r2S[d0 + 1], ls1);
    atomicAdd(&r2Q[d0], lq0);
    atomicAdd(&r2Q[d0 + 1], lq1);
    __syncthreads();
    if (threadIdx.x < 64) {
        atomicAdd(&g_s2[threadIdx.x * SPAD], r2S[threadIdx.x]);
        atomicAdd(&g_ss2[threadIdx.x * SPAD], r2Q[threadIdx.x]);
    }
}

// ---------------- BN2 + residual softplus -> x_out ----------------
__global__ __launch_bounds__(256) void bnres_kernel(int l, int buf,
                                                    const float* __restrict__ bn2_g,
                                                    const float* __restrict__ bn2_b) {
    int gid = blockIdx.x * 256 + threadIdx.x;
    int d = gid & 63;
    float inv = 1.0f / CNT2F;
    float m2 = g_s2[d * SPAD] * inv;
    float v2 = g_ss2[d * SPAD] * inv - m2 * m2;
    float sc = rsqrtf(v2 + EPSBN) * bn2_g[l * DIM + d];
    float sh = bn2_b[l * DIM + d] - m2 * sc;
    float v = g_x[buf][gid] + g_summed[gid] * sc + sh;
    g_x[1 - buf][gid] = (v > 15.0f) ? v : __logf(1.0f + __expf(v));
}

// ---------------- G[bi, o*64+k] = f[bi,:] @ bilT  (K=64, scalar) ----------------
__global__ __launch_bounds__(256) void gmat_kernel(int buf, const int* __restrict__ cidx) {
    extern __shared__ float sm[];
    float* Ws = sm;                // [64][128]
    float* As = sm + 64 * TWO_D;   // [64][64]
    __shared__ int cid_s[64];
    int t = threadIdx.x;
    int rb = blockIdx.x * 64;
    int co = blockIdx.y * 128;
    const float* x = g_x[buf];
    if (t < 64) cid_s[t] = cidx[rb + t];
    for (int e = t; e < 64 * TWO_D; e += 256) {
        int k = e >> 7, oc = e & 127;
        Ws[e] = g_bilT[k * 384 + co + oc];
    }
    __syncthreads();
    int warp = t >> 5, lane = t & 31;
    for (int m = warp; m < 64; m += 8) {
        int a = cid_s[m];
        As[m * 64 + lane]      = x[a * DIM + lane];
        As[m * 64 + 32 + lane] = x[a * DIM + 32 + lane];
    }
    __syncthreads();
    int ty = t >> 5, tx = t & 31;
    float acc[8][4];
#pragma unroll
    for (int i = 0; i < 8; i++)
#pragma unroll
        for (int c = 0; c < 4; c++) acc[i][c] = 0.f;
    for (int k = 0; k < 64; k++) {
        float4 b = *(const float4*)&Ws[k * TWO_D + tx * 4];
#pragma unroll
        for (int i = 0; i < 8; i++) {
            float a = As[(ty * 8 + i) * 64 + k];
            acc[i][0] = fmaf(a, b.x, acc[i][0]);
            acc[i][1] = fmaf(a, b.y, acc[i][1]);
            acc[i][2] = fmaf(a, b.z, acc[i][2]);
            acc[i][3] = fmaf(a, b.w, acc[i][3]);
        }
    }
#pragma unroll
    for (int i = 0; i < 8; i++)
        *(float4*)&g_G[(long)(rb + ty * 8 + i) * 384 + co + tx * 4] =
            make_float4(acc[i][0], acc[i][1], acc[i][2], acc[i][3]);
}

// ---------------- edge: per-pair bilinear dot + fc1 + log_softmax ----------------
__global__ __launch_bounds__(256) void edge_kernel(int buf, const int* __restrict__ cidx,
                                                   const float* __restrict__ bil_b,
                                                   const float* __restrict__ fc1_W,
                                                   const float* __restrict__ fc1_b,
                                                   float* __restrict__ out) {
    __shared__ float f_s[64][65];
    __shared__ float Gi[4][384];
    __shared__ int cid_s[64];
    __shared__ float s_fc1W[36], s_fc1b[6], s_bilb[6];
    int b = blockIdx.x, it = blockIdx.y, t = threadIdx.x;
    const float* x = g_x[buf];
    if (t < 64) cid_s[t] = cidx[b * 64 + t];
    if (t < 36) s_fc1W[t] = fc1_W[t];
    if (t >= 64 && t < 70) s_fc1b[t - 64] = fc1_b[t - 64];
    if (t >= 96 && t < 102) s_bilb[t - 96] = bil_b[t - 96];
    __syncthreads();
    for (int e = t; e < 4096; e += 256) {
        int m = e >> 6, k = e & 63;
        f_s[m][k] = x[cid_s[m] * DIM + k];
    }
    for (int e = t; e < 1536; e += 256) {
        int i4 = e / 384, ok = e % 384;
        Gi[i4][ok] = g_G[(long)(b * 64 + it * 4 + i4) * 384 + ok];
    }
    __syncthreads();
    int i4 = t >> 6, j = t & 63;
    float ev[6];
#pragma unroll
    for (int o = 0; o < 6; o++) {
        float a = s_bilb[o];
#pragma unroll 16
        for (int k = 0; k < 64; k++) a = fmaf(Gi[i4][o * 64 + k], f_s[j][k], a);
        ev[o] = a;
    }
    float tr[6];
#pragma unroll
    for (int r = 0; r < 6; r++) {
        float a = s_fc1b[r];
#pragma unroll
        for (int o = 0; o < 6; o++) a = fmaf(s_fc1W[r * 6 + o], ev[o], a);
        tr[r] = a;
    }
    float mx = tr[0];
#pragma unroll
    for (int r = 1; r < 6; r++) mx = fmaxf(mx, tr[r]);
    float se = 0.f;
#pragma unroll
    for (int r = 0; r < 6; r++) se += expf(tr[r] - mx);
    float lse = mx + logf(se);
    int pair = (it * 4 + i4) * 64 + j;
    float* op = out + ((long)b * 4096 + pair) * 6;
#pragma unroll
    for (int r = 0; r < 6; r++) op[r] = tr[r] - lse;
}

// ---------------- atom_out = f @ fca_W^T + fca_b ----------------
__global__ __launch_bounds__(96) void atomout_kernel(int buf, const int* __restrict__ cidx,
                                                     const float* __restrict__ fca_b,
                                                     float* __restrict__ out2) {
    __shared__ float xr[64];
    int t = threadIdx.x;
    int r = blockIdx.x;
    int atom = cidx[r];
    if (t < 64) xr[t] = g_x[buf][atom * DIM + t];
    __syncthreads();
    if (t < ORIG) {
        float a = fca_b[t];
#pragma unroll 16
        for (int k = 0; k < 64; k++) a = fmaf(xr[k], g_fcaT[k * ORIG + t], a);
        out2[(long)r * ORIG + t] = a;
    }
}

// ---------------- launch ----------------
#define ZS_SM ((64 * TWO_D + 64 * 64) * 4)

extern "C" void kernel_launch(void* const* d_in, const int* in_sizes, int n_in,
                              void* d_out, int out_size) {
    (void)in_sizes; (void)n_in; (void)out_size;
    const float* atom_fea = (const float*)d_in[0];
    const float* nbr_fea  = (const float*)d_in[1];
    const int*   nbr_idx  = (const int*)d_in[2];
    const int*   cidx     = (const int*)d_in[3];
    const float* embed_W  = (const float*)d_in[4];
    const float* conv_W   = (const float*)d_in[5];
    const float* conv_b   = (const float*)d_in[6];
    const float* bn1_g    = (const float*)d_in[7];
    const float* bn1_b    = (const float*)d_in[8];
    const float* bn2_g    = (const float*)d_in[9];
    const float* bn2_b    = (const float*)d_in[10];
    const float* bil_W    = (const float*)d_in[11];
    const float* bil_b    = (const float*)d_in[12];
    const float* fc1_W    = (const float*)d_in[13];
    const float* fc1_b    = (const float*)d_in[14];
    const float* fca_W    = (const float*)d_in[15];
    const float* fca_b    = (const float*)d_in[16];
    float* out = (float*)d_out;

    cudaFuncSetAttribute(convz_kernel, cudaFuncAttributeMaxDynamicSharedMemorySize, CZ_SMEM);
    cudaFuncSetAttribute(gmat_kernel,  cudaFuncAttributeMaxDynamicSharedMemorySize, ZS_SM);

    int prep_elems = 3 * TWO_D * K2N + ORIG * DIM + DIM * 384 + DIM * ORIG;
    prep_kernel<<<(prep_elems + 255) / 256, 256>>>(conv_W, conv_b, embed_W, bil_W, fca_W);
    embed_kernel<<<NATOM / 64, 256>>>(atom_fea);

    int zs_blocks = (TWO_D * SPAD + DIM * SPAD + 255) / 256;
    int buf = 0;
    for (int l = 0; l < 3; l++) {
        zero_stats<<<zs_blocks, 256>>>();
        convz_kernel<<<CZGRID, 256, CZ_SMEM>>>(l, buf, nbr_fea, nbr_idx);
        reduce_kernel<<<NATOM / 16, 256>>>(l, bn1_g, bn1_b);
        bnres_kernel<<<(NATOM * DIM) / 256, 256>>>(l, buf, bn2_g, bn2_b);
        buf = 1 - buf;
    }

    gmat_kernel<<<dim3(NCRY * NA / 64, 3), 256, ZS_SM>>>(buf, cidx);
    edge_kernel<<<dim3(NCRY, 16), 256>>>(buf, cidx, bil_b, fc1_W, fc1_b, out);
    atomout_kernel<<<NCRY * NA, 96>>>(buf, cidx, fca_b, out + (long)NCRY * NA * NA * 6);
}

// round 14
// speedup vs baseline: 2.6673x; 1.0752x over previous
#include <cuda_runtime.h>
#include <cuda_fp16.h>
#include <math.h>
#include <stdint.h>

#define NATOM 32768
#define MNBR 12
#define DIM 64
#define FNBR 41
#define ORIG 92
#define TWO_D 128
#define KTOT 169
#define NCRY 512
#define NA 64
#define CNT1F (393216.0f)
#define CNT2F (32768.0f)
#define EPSBN 1e-5f

#define K2N 88          // u32 (half2) count per B row: K=170 padded to 176 halves
#define AP 92           // A smem pitch in u32
#define BP 92           // B smem pitch in u32
#define NKS 11          // k-steps of 16
#define SPAD 32         // stat array stride (32 floats = 128B) to spread LTS slices
#define NTILE (NATOM * MNBR / 64)   // 6144 output tiles
#define CZGRID 444                   // persistent CTAs (3/SM x 148)
#define ZBP 68          // z staging pitch in u32 (4q+r covers all banks)

// ---------------- scratch (device globals; no allocation) ----------------
__device__ float g_x[2][NATOM * DIM];
__device__ uint32_t g_xh[2][NATOM * 32];             // half2 mirror of x
__device__ uint32_t g_nfH[NATOM * MNBR * 24];        // [nbr_fea|1|pad] as half2, 37.7 MB
__device__ uint32_t g_z[NATOM * MNBR * 64];          // z as half2, 100 MB
__device__ float g_summed[NATOM * DIM];
__device__ float g_G[NCRY * NA * 384];               // 50 MB
__device__ uint32_t g_WnH[3 * TWO_D * K2N];          // fused W half2 [l][n][k2]
__device__ float g_embT[ORIG * DIM];                 // [k][d]
__device__ float g_bilT[DIM * 6 * DIM];              // [d][o*64+k]
__device__ float g_fcaT[DIM * ORIG];                 // [k][c]
// padded stat arrays: one 128B line per channel -> many LTS slices
__device__ float g_s1[TWO_D * SPAD], g_ss1[TWO_D * SPAD];
__device__ float g_s2[DIM * SPAD], g_ss2[DIM * SPAD];

__device__ __forceinline__ float softplusf(float v) {
    return v > 20.0f ? v : log1pf(expf(v));
}
// fast softplus * sigmoid gate (approx intrinsics; err ~1e-6 rel, far below fp16 z noise)
__device__ __forceinline__ float gatef(float fv, float cv) {
    float sp = (cv > 15.0f) ? cv : __logf(1.0f + __expf(cv));
    return __fdividef(sp, 1.0f + __expf(-fv));
}
__device__ __forceinline__ void mma_f16(float* c, const uint32_t* a, const uint32_t* b) {
    asm volatile(
        "mma.sync.aligned.m16n8k16.row.col.f32.f16.f16.f32 "
        "{%0,%1,%2,%3}, {%4,%5,%6,%7}, {%8,%9}, {%0,%1,%2,%3};"
        : "+f"(c[0]), "+f"(c[1]), "+f"(c[2]), "+f"(c[3])
        : "r"(a[0]), "r"(a[1]), "r"(a[2]), "r"(a[3]), "r"(b[0]), "r"(b[1]));
}
__device__ __forceinline__ void ldsm4(uint32_t* r, uint32_t addr) {
    asm volatile("ldmatrix.sync.aligned.m8n8.x4.shared.b16 {%0,%1,%2,%3}, [%4];"
                 : "=r"(r[0]), "=r"(r[1]), "=r"(r[2]), "=r"(r[3]) : "r"(addr));
}

// ---------------- prep: fused weight layout + half nbr_fea ----------------
__global__ void prep_kernel(const float* __restrict__ conv_W,
                            const float* __restrict__ conv_b,
                            const float* __restrict__ embed_W,
                            const float* __restrict__ bil_W,
                            const float* __restrict__ fca_W,
                            const float* __restrict__ nbr_fea) {
    int idx = blockIdx.x * blockDim.x + threadIdx.x;
    if (idx < 3 * TWO_D * K2N) {                      // g_WnH [l][n][j]
        int l = idx / (TWO_D * K2N), r = idx % (TWO_D * K2N);
        int n = r / K2N, j = r % K2N;
        int k0 = 2 * j, k1 = 2 * j + 1;
        const float* wr = conv_W + (l * TWO_D + n) * KTOT;
        float a = (k0 < KTOT) ? wr[k0] : (k0 == KTOT ? conv_b[l * TWO_D + n] : 0.f);
        float b = (k1 < KTOT) ? wr[k1] : (k1 == KTOT ? conv_b[l * TWO_D + n] : 0.f);
        __half2 h = __floats2half2_rn(a, b);
        g_WnH[idx] = *(uint32_t*)&h;
        return;
    }
    int i2 = idx - 3 * TWO_D * K2N;
    if (i2 < ORIG * DIM) {                            // g_embT [k][d]
        int k = i2 / DIM, d = i2 % DIM;
        g_embT[i2] = embed_W[d * ORIG + k];
        return;
    }
    int i3 = i2 - ORIG * DIM;
    if (i3 < DIM * 6 * DIM) {                         // g_bilT [d][o*64+k]
        int d = i3 / 384, ok = i3 % 384;
        int o = ok >> 6, k2 = ok & 63;
        g_bilT[i3] = bil_W[(o * DIM + d) * DIM + k2];
        return;
    }
    int i4 = i3 - DIM * 6 * DIM;
    if (i4 < DIM * ORIG) {
        int k = i4 / ORIG, c = i4 % ORIG;
        g_fcaT[i4] = fca_W[c * DIM + k];
        return;
    }
    int i5 = i4 - DIM * ORIG;
    if (i5 < NATOM * MNBR * 24) {                     // g_nfH [row][j]
        int row = i5 / 24, j = i5 % 24;
        int h0 = 2 * j, h1 = 2 * j + 1;
        const float* nf = nbr_fea + (long)row * FNBR;
        float a = (h0 < FNBR) ? nf[h0] : (h0 == FNBR ? 1.0f : 0.f);
        float b = (h1 < FNBR) ? nf[h1] : (h1 == FNBR ? 1.0f : 0.f);
        __half2 h = __floats2half2_rn(a, b);
        g_nfH[i5] = *(uint32_t*)&h;
    }
}

// ---------------- embedding: x = atom_fea @ embed_W^T  (K=92); also writes half mirror ----------------
__global__ __launch_bounds__(256) void embed_kernel(const float* __restrict__ atom_fea) {
    __shared__ float As[64 * ORIG];
    __shared__ float Ws[ORIG * DIM];
    int t = threadIdx.x;
    int rb = blockIdx.x * 64;
    for (int e = t; e < ORIG * DIM; e += 256) Ws[e] = g_embT[e];
    int warp = t >> 5, lane = t & 31;
    for (int m = warp; m < 64; m += 8) {
        const float* row = atom_fea + (rb + m) * ORIG;
        As[m * ORIG + lane] = row[lane];
        As[m * ORIG + 32 + lane] = row[32 + lane];
        if (lane < ORIG - 64) As[m * ORIG + 64 + lane] = row[64 + lane];
    }
    __syncthreads();
    int ty = t >> 5, tx = t & 31;
    float acc[8][2];
#pragma unroll
    for (int i = 0; i < 8; i++) { acc[i][0] = 0.f; acc[i][1] = 0.f; }
    for (int k = 0; k < ORIG; k++) {
        float2 b = *(const float2*)&Ws[k * DIM + tx * 2];
#pragma unroll
        for (int i = 0; i < 8; i++) {
            float a = As[(ty * 8 + i) * ORIG + k];
            acc[i][0] = fmaf(a, b.x, acc[i][0]);
            acc[i][1] = fmaf(a, b.y, acc[i][1]);
        }
    }
#pragma unroll
    for (int i = 0; i < 8; i++) {
        int row = rb + ty * 8 + i;
        *(float2*)&g_x[0][row * DIM + tx * 2] = make_float2(acc[i][0], acc[i][1]);
        __half2 h = __floats2half2_rn(acc[i][0], acc[i][1]);
        g_xh[0][row * 32 + tx] = *(uint32_t*)&h;
    }
}

// ---------------- stat zeroing (padded arrays; every layer) ----------------
__global__ void zero_stats() {
    int t = blockIdx.x * 256 + threadIdx.x;
    if (t < TWO_D * SPAD) { g_s1[t] = 0.f; g_ss1[t] = 0.f; }
    int u = t - TWO_D * SPAD;
    if (u >= 0 && u < DIM * SPAD) { g_s2[u] = 0.f; g_ss2[u] = 0.f; }
}

// ---------------- fused conv GEMM (persistent CTAs, pre-halved operands) ----------------
#define CZ_SMEM ((64 * AP + 128 * BP) * 4)

__global__ __launch_bounds__(256, 3) void convz_kernel(int l, int buf,
                                                       const int* __restrict__ nbr_idx) {
    extern __shared__ uint32_t smu[];
    uint32_t* As2 = smu;               // [64][AP]; reused as z staging [64][ZBP]
    uint32_t* Bs2 = smu + 64 * AP;     // [128][BP]
    __shared__ float redS[128], redQ[128];
    __shared__ int nbr_s[64];
    int t = threadIdx.x, w = t >> 5, lane = t & 31;
    const uint32_t* xh = g_xh[buf];
    if (t < 128) { redS[t] = 0.f; redQ[t] = 0.f; }
    // B: load fused weights ONCE per persistent CTA
    {
        const uint32_t* src = g_WnH + l * TWO_D * K2N;
        for (int e = t; e < TWO_D * K2N; e += 256)
            Bs2[(e / K2N) * BP + (e % K2N)] = src[e];
    }

    int wm = w & 1, wn = w >> 1;             // wm 0..1 (32 rows), wn 0..3 (32 cols)
    int q = lane >> 2, r = lane & 3;
    uint32_t sAs = (uint32_t)__cvta_generic_to_shared(As2);
    uint32_t sBs = (uint32_t)__cvta_generic_to_shared(Bs2);
    uint32_t aAddr0 = sAs + (((wm * 32) + (lane & 7) + ((lane >> 3) & 1) * 8) * AP +
                             ((lane >> 4) & 1) * 4) * 4;
    uint32_t aAddr1 = aAddr0 + 16 * AP * 4;
    uint32_t bAddr0 = sBs + (((wn * 32) + (lane & 7) + ((lane >> 4) & 1) * 8) * BP +
                             ((lane >> 3) & 1) * 4) * 4;
    uint32_t bAddr1 = bAddr0 + 16 * BP * 4;

    for (int tile = blockIdx.x; tile < NTILE; tile += CZGRID) {
        int rb = tile * 64;
        if (t < 64) nbr_s[t] = nbr_idx[rb + t];
        __syncthreads();   // prior tile's z-staging reads done; nbr_s visible
        // A: pure u32 copies of pre-halved [x_self | x_nbr | nf+bias]
        for (int m = w; m < 64; m += 8) {
            uint32_t* Ar = As2 + m * AP;
            int nself = (rb + m) / MNBR;
            int nbr = nbr_s[m];
            Ar[lane]      = xh[nself * 32 + lane];
            Ar[32 + lane] = xh[nbr * 32 + lane];
            if (lane < 24) Ar[64 + lane] = g_nfH[(long)(rb + m) * 24 + lane];
        }
        __syncthreads();

        float c[2][4][4];
#pragma unroll
        for (int mt = 0; mt < 2; mt++)
#pragma unroll
            for (int nf = 0; nf < 4; nf++)
#pragma unroll
                for (int e = 0; e < 4; e++) c[mt][nf][e] = 0.f;

#pragma unroll
        for (int ks = 0; ks < NKS; ks++) {
            uint32_t ko = ks * 32;               // 8 u32 per step
            uint32_t a[2][4], b01[4], b23[4];
            ldsm4(a[0], aAddr0 + ko);
            ldsm4(a[1], aAddr1 + ko);
            ldsm4(b01, bAddr0 + ko);
            ldsm4(b23, bAddr1 + ko);
            uint32_t bf[4][2] = {{b01[0], b01[1]}, {b01[2], b01[3]},
                                 {b23[0], b23[1]}, {b23[2], b23[3]}};
#pragma unroll
            for (int mt = 0; mt < 2; mt++)
#pragma unroll
                for (int nf = 0; nf < 4; nf++)
                    mma_f16(c[mt][nf], a[mt], bf[nf]);
        }
        __syncthreads();   // all warps done reading As via ldmatrix

        // epilogue: half2 round-trip, stats in registers, stage z in smem (bank-clean)
        uint32_t* zbuf = As2;   // [64][ZBP]
#pragma unroll
        for (int nf = 0; nf < 4; nf++) {
            int cc = wn * 32 + nf * 8 + r * 2;
            int cu = cc >> 1;
            float s0 = 0.f, s1 = 0.f, q0 = 0.f, q1 = 0.f;
#pragma unroll
            for (int mt = 0; mt < 2; mt++) {
                int m0 = wm * 32 + mt * 16 + q;
                __half2 h0 = __floats2half2_rn(c[mt][nf][0], c[mt][nf][1]);
                __half2 h1 = __floats2half2_rn(c[mt][nf][2], c[mt][nf][3]);
                zbuf[m0 * ZBP + cu] = *(uint32_t*)&h0;
                zbuf[(m0 + 8) * ZBP + cu] = *(uint32_t*)&h1;
                float2 v0 = __half22float2(h0);
                float2 v1 = __half22float2(h1);
                s0 += v0.x + v1.x; q0 += v0.x * v0.x + v1.x * v1.x;
                s1 += v0.y + v1.y; q1 += v0.y * v0.y + v1.y * v1.y;
            }
#pragma unroll
            for (int off = 4; off < 32; off <<= 1) {
                s0 += __shfl_xor_sync(0xffffffffu, s0, off);
                s1 += __shfl_xor_sync(0xffffffffu, s1, off);
                q0 += __shfl_xor_sync(0xffffffffu, q0, off);
                q1 += __shfl_xor_sync(0xffffffffu, q1, off);
            }
            if (lane < 4) {
                atomicAdd(&redS[cc], s0);
                atomicAdd(&redS[cc + 1], s1);
                atomicAdd(&redQ[cc], q0);
                atomicAdd(&redQ[cc + 1], q1);
            }
        }
        __syncthreads();   // zbuf complete
        // coalesced z store: 4 x uint4 per thread (128B sectors)
#pragma unroll
        for (int e = 0; e < 4; e++) {
            int idx = e * 256 + t;          // 0..1023 uint4 slots
            int row = idx >> 4;             // 64 rows
            int c4 = (idx & 15) * 4;        // 16 uint4 per row
            uint4 v = *(uint4*)&zbuf[row * ZBP + c4];
            *(uint4*)&g_z[((long)(rb + row)) * 64 + c4] = v;
        }
    }
    // one global-atomic flush per persistent CTA
    __syncthreads();
    if (t < 128) {
        atomicAdd(&g_s1[t * SPAD], redS[t]);
        atomicAdd(&g_ss1[t * SPAD], redQ[t]);
    }
}

// ---------------- BN1 + gate + sum over neighbors (half2 z), BN2 stats ----------------
__global__ __launch_bounds__(256) void reduce_kernel(int l,
                                                     const float* __restrict__ bn1_g,
                                                     const float* __restrict__ bn1_b) {
    __shared__ float r2S[64], r2Q[64];
    int c = threadIdx.x & 31, grp = threadIdx.x >> 5;
    int d0 = 2 * c;
    if (threadIdx.x < 64) { r2S[threadIdx.x] = 0.f; r2Q[threadIdx.x] = 0.f; }
    __syncthreads();
    float inv = 1.0f / CNT1F;
    float mf0 = g_s1[d0 * SPAD] * inv, mf1 = g_s1[(d0 + 1) * SPAD] * inv;
    float vf0 = g_ss1[d0 * SPAD] * inv - mf0 * mf0;
    float vf1 = g_ss1[(d0 + 1) * SPAD] * inv - mf1 * mf1;
    float scf0 = rsqrtf(vf0 + EPSBN) * bn1_g[l * TWO_D + d0];
    float scf1 = rsqrtf(vf1 + EPSBN) * bn1_g[l * TWO_D + d0 + 1];
    float shf0 = bn1_b[l * TWO_D + d0] - mf0 * scf0;
    float shf1 = bn1_b[l * TWO_D + d0 + 1] - mf1 * scf1;
    float mc0 = g_s1[(64 + d0) * SPAD] * inv, mc1 = g_s1[(64 + d0 + 1) * SPAD] * inv;
    float vc0 = g_ss1[(64 + d0) * SPAD] * inv - mc0 * mc0;
    float vc1 = g_ss1[(64 + d0 + 1) * SPAD] * inv - mc1 * mc1;
    float scc0 = rsqrtf(vc0 + EPSBN) * bn1_g[l * TWO_D + 64 + d0];
    float scc1 = rsqrtf(vc1 + EPSBN) * bn1_g[l * TWO_D + 64 + d0 + 1];
    float shc0 = bn1_b[l * TWO_D + 64 + d0] - mc0 * scc0;
    float shc1 = bn1_b[l * TWO_D + 64 + d0 + 1] - mc1 * scc1;

    float ls0 = 0.f, ls1 = 0.f, lq0 = 0.f, lq1 = 0.f;
    int n0 = blockIdx.x * 16 + grp * 2;
#pragma unroll
    for (int a = 0; a < 2; a++) {
        int n = n0 + a;
        const uint32_t* zr = g_z + (long)n * MNBR * 64;
        uint32_t zfp[MNBR], zcp[MNBR];
#pragma unroll
        for (int m = 0; m < MNBR; m++) zfp[m] = __ldg(&zr[m * 64 + c]);
#pragma unroll
        for (int m = 0; m < MNBR; m++) zcp[m] = __ldg(&zr[m * 64 + 32 + c]);
        float a0 = 0.f, a1 = 0.f;
#pragma unroll
        for (int m = 0; m < MNBR; m++) {
            float2 zf = __half22float2(*(__half2*)&zfp[m]);
            float2 zc = __half22float2(*(__half2*)&zcp[m]);
            a0 += gatef(zf.x * scf0 + shf0, zc.x * scc0 + shc0);
            a1 += gatef(zf.y * scf1 + shf1, zc.y * scc1 + shc1);
        }
        *(float2*)&g_summed[n * DIM + d0] = make_float2(a0, a1);
        ls0 += a0; lq0 += a0 * a0;
        ls1 += a1; lq1 += a1 * a1;
    }
    // stage BN2 stats in smem (8 warps share channels), then 1 global atomic/ch/block
    atomicAdd(&r2S[d0], ls0);
    atomicAdd(&r2S[d0 + 1], ls1);
    atomicAdd(&r2Q[d0], lq0);
    atomicAdd(&r2Q[d0 + 1], lq1);
    __syncthreads();
    if (threadIdx.x < 64) {
        atomicAdd(&g_s2[threadIdx.x * SPAD], r2S[threadIdx.x]);
        atomicAdd(&g_ss2[threadIdx.x * SPAD], r2Q[threadIdx.x]);
    }
}

// ---------------- BN2 + residual softplus -> x_out (fp32 + half mirror) ----------------
__global__ __launch_bounds__(256) void bnres_kernel(int l, int buf,
                                                    const float* __restrict__ bn2_g,
                                                    const float* __restrict__ bn2_b) {
    int gid2 = blockIdx.x * 256 + threadIdx.x;       // one per 2 elements
    int n = gid2 >> 5;
    int d0 = (gid2 & 31) * 2;
    float inv = 1.0f / CNT2F;
    float m0 = g_s2[d0 * SPAD] * inv, m1 = g_s2[(d0 + 1) * SPAD] * inv;
    float v0 = g_ss2[d0 * SPAD] * inv - m0 * m0;
    float v1 = g_ss2[(d0 + 1) * SPAD] * inv - m1 * m1;
    float sc0 = rsqrtf(v0 + EPSBN) * bn2_g[l * DIM + d0];
    float sc1 = rsqrtf(v1 + EPSBN) * bn2_g[l * DIM + d0 + 1];
    float sh0 = bn2_b[l * DIM + d0] - m0 * sc0;
    float sh1 = bn2_b[l * DIM + d0 + 1] - m1 * sc1;
    float2 xo = *(const float2*)&g_x[buf][n * DIM + d0];
    float2 sm = *(const float2*)&g_summed[n * DIM + d0];
    float a = xo.x + sm.x * sc0 + sh0;
    float b = xo.y + sm.y * sc1 + sh1;
    a = (a > 15.0f) ? a : __logf(1.0f + __expf(a));
    b = (b > 15.0f) ? b : __logf(1.0f + __expf(b));
    *(float2*)&g_x[1 - buf][n * DIM + d0] = make_float2(a, b);
    __half2 h = __floats2half2_rn(a, b);
    g_xh[1 - buf][n * 32 + (d0 >> 1)] = *(uint32_t*)&h;
}

// ---------------- G[bi, o*64+k] = f[bi,:] @ bilT  (K=64, scalar) ----------------
__global__ __launch_bounds__(256) void gmat_kernel(int buf, const int* __restrict__ cidx) {
    extern __shared__ float sm[];
    float* Ws = sm;                // [64][128]
    float* As = sm + 64 * TWO_D;   // [64][64]
    __shared__ int cid_s[64];
    int t = threadIdx.x;
    int rb = blockIdx.x * 64;
    int co = blockIdx.y * 128;
    const float* x = g_x[buf];
    if (t < 64) cid_s[t] = cidx[rb + t];
    for (int e = t; e < 64 * TWO_D; e += 256) {
        int k = e >> 7, oc = e & 127;
        Ws[e] = g_bilT[k * 384 + co + oc];
    }
    __syncthreads();
    int warp = t >> 5, lane = t & 31;
    for (int m = warp; m < 64; m += 8) {
        int a = cid_s[m];
        As[m * 64 + lane]      = x[a * DIM + lane];
        As[m * 64 + 32 + lane] = x[a * DIM + 32 + lane];
    }
    __syncthreads();
    int ty = t >> 5, tx = t & 31;
    float acc[8][4];
#pragma unroll
    for (int i = 0; i < 8; i++)
#pragma unroll
        for (int c = 0; c < 4; c++) acc[i][c] = 0.f;
    for (int k = 0; k < 64; k++) {
        float4 b = *(const float4*)&Ws[k * TWO_D + tx * 4];
#pragma unroll
        for (int i = 0; i < 8; i++) {
            float a = As[(ty * 8 + i) * 64 + k];
            acc[i][0] = fmaf(a, b.x, acc[i][0]);
            acc[i][1] = fmaf(a, b.y, acc[i][1]);
            acc[i][2] = fmaf(a, b.z, acc[i][2]);
            acc[i][3] = fmaf(a, b.w, acc[i][3]);
        }
    }
#pragma unroll
    for (int i = 0; i < 8; i++)
        *(float4*)&g_G[(long)(rb + ty * 8 + i) * 384 + co + tx * 4] =
            make_float4(acc[i][0], acc[i][1], acc[i][2], acc[i][3]);
}

// ---------------- edge: per-pair bilinear dot + fc1 + log_softmax ----------------
__global__ __launch_bounds__(256) void edge_kernel(int buf, const int* __restrict__ cidx,
                                                   const float* __restrict__ bil_b,
                                                   const float* __restrict__ fc1_W,
                                                   const float* __restrict__ fc1_b,
                                                   float* __restrict__ out) {
    __shared__ float f_s[64][65];
    __shared__ float Gi[4][384];
    __shared__ int cid_s[64];
    __shared__ float s_fc1W[36], s_fc1b[6], s_bilb[6];
    int b = blockIdx.x, it = blockIdx.y, t = threadIdx.x;
    const float* x = g_x[buf];
    if (t < 64) cid_s[t] = cidx[b * 64 + t];
    if (t < 36) s_fc1W[t] = fc1_W[t];
    if (t >= 64 && t < 70) s_fc1b[t - 64] = fc1_b[t - 64];
    if (t >= 96 && t < 102) s_bilb[t - 96] = bil_b[t - 96];
    __syncthreads();
    for (int e = t; e < 4096; e += 256) {
        int m = e >> 6, k = e & 63;
        f_s[m][k] = x[cid_s[m] * DIM + k];
    }
    for (int e = t; e < 1536; e += 256) {
        int i4 = e / 384, ok = e % 384;
        Gi[i4][ok] = g_G[(long)(b * 64 + it * 4 + i4) * 384 + ok];
    }
    __syncthreads();
    int i4 = t >> 6, j = t & 63;
    float ev[6];
#pragma unroll
    for (int o = 0; o < 6; o++) {
        float a = s_bilb[o];
#pragma unroll 16
        for (int k = 0; k < 64; k++) a = fmaf(Gi[i4][o * 64 + k], f_s[j][k], a);
        ev[o] = a;
    }
    float tr[6];
#pragma unroll
    for (int r = 0; r < 6; r++) {
        float a = s_fc1b[r];
#pragma unroll
        for (int o = 0; o < 6; o++) a = fmaf(s_fc1W[r * 6 + o], ev[o], a);
        tr[r] = a;
    }
    float mx = tr[0];
#pragma unroll
    for (int r = 1; r < 6; r++) mx = fmaxf(mx, tr[r]);
    float se = 0.f;
#pragma unroll
    for (int r = 0; r < 6; r++) se += expf(tr[r] - mx);
    float lse = mx + logf(se);
    int pair = (it * 4 + i4) * 64 + j;
    float* op = out + ((long)b * 4096 + pair) * 6;
#pragma unroll
    for (int r = 0; r < 6; r++) op[r] = tr[r] - lse;
}

// ---------------- atom_out = f @ fca_W^T + fca_b ----------------
__global__ __launch_bounds__(96) void atomout_kernel(int buf, const int* __restrict__ cidx,
                                                     const float* __restrict__ fca_b,
                                                     float* __restrict__ out2) {
    __shared__ float xr[64];
    int t = threadIdx.x;
    int r = blockIdx.x;
    int atom = cidx[r];
    if (t < 64) xr[t] = g_x[buf][atom * DIM + t];
    __syncthreads();
    if (t < ORIG) {
        float a = fca_b[t];
#pragma unroll 16
        for (int k = 0; k < 64; k++) a = fmaf(xr[k], g_fcaT[k * ORIG + t], a);
        out2[(long)r * ORIG + t] = a;
    }
}

// ---------------- launch ----------------
#define ZS_SM ((64 * TWO_D + 64 * 64) * 4)

extern "C" void kernel_launch(void* const* d_in, const int* in_sizes, int n_in,
                              void* d_out, int out_size) {
    (void)in_sizes; (void)n_in; (void)out_size;
    const float* atom_fea = (const float*)d_in[0];
    const float* nbr_fea  = (const float*)d_in[1];
    const int*   nbr_idx  = (const int*)d_in[2];
    const int*   cidx     = (const int*)d_in[3];
    const float* embed_W  = (const float*)d_in[4];
    const float* conv_W   = (const float*)d_in[5];
    const float* conv_b   = (const float*)d_in[6];
    const float* bn1_g    = (const float*)d_in[7];
    const float* bn1_b    = (const float*)d_in[8];
    const float* bn2_g    = (const float*)d_in[9];
    const float* bn2_b    = (const float*)d_in[10];
    const float* bil_W    = (const float*)d_in[11];
    const float* bil_b    = (const float*)d_in[12];
    const float* fc1_W    = (const float*)d_in[13];
    const float* fc1_b    = (const float*)d_in[14];
    const float* fca_W    = (const float*)d_in[15];
    const float* fca_b    = (const float*)d_in[16];
    float* out = (float*)d_out;

    cudaFuncSetAttribute(convz_kernel, cudaFuncAttributeMaxDynamicSharedMemorySize, CZ_SMEM);
    cudaFuncSetAttribute(gmat_kernel,  cudaFuncAttributeMaxDynamicSharedMemorySize, ZS_SM);

    long prep_elems = (long)3 * TWO_D * K2N + ORIG * DIM + DIM * 384 + DIM * ORIG +
                      (long)NATOM * MNBR * 24;
    prep_kernel<<<(int)((prep_elems + 255) / 256), 256>>>(conv_W, conv_b, embed_W, bil_W,
                                                          fca_W, nbr_fea);
    embed_kernel<<<NATOM / 64, 256>>>(atom_fea);

    int zs_blocks = (TWO_D * SPAD + DIM * SPAD + 255) / 256;
    int buf = 0;
    for (int l = 0; l < 3; l++) {
        zero_stats<<<zs_blocks, 256>>>();
        convz_kernel<<<CZGRID, 256, CZ_SMEM>>>(l, buf, nbr_idx);
        reduce_kernel<<<NATOM / 16, 256>>>(l, bn1_g, bn1_b);
        bnres_kernel<<<(NATOM * DIM / 2) / 256, 256>>>(l, buf, bn2_g, bn2_b);
        buf = 1 - buf;
    }

    gmat_kernel<<<dim3(NCRY * NA / 64, 3), 256, ZS_SM>>>(buf, cidx);
    edge_kernel<<<dim3(NCRY, 16), 256>>>(buf, cidx, bil_b, fc1_W, fc1_b, out);
    atomout_kernel<<<NCRY * NA, 96>>>(buf, cidx, fca_b, out + (long)NCRY * NA * NA * 6);
}

// round 15
// speedup vs baseline: 2.7985x; 1.0492x over previous
#include <cuda_runtime.h>
#include <cuda_fp16.h>
#include <math.h>
#include <stdint.h>

#define NATOM 32768
#define MNBR 12
#define DIM 64
#define FNBR 41
#define ORIG 92
#define TWO_D 128
#define KTOT 169
#define NCRY 512
#define NA 64
#define CNT1F (393216.0f)
#define CNT2F (32768.0f)
#define EPSBN 1e-5f

#define K2N 88          // u32 (half2) count per B row: K=170 padded to 176 halves
#define AP 92           // A smem pitch in u32
#define BP 92           // B smem pitch in u32
#define NKS 11          // k-steps of 16
#define SPAD 32         // stat array stride (32 floats = 128B) to spread LTS slices
#define NTILE (NATOM * MNBR / 64)   // 6144 output tiles
#define CZGRID 444                   // persistent CTAs (3/SM x 148)
#define ZBP 68          // z staging pitch in u32 (4q+r covers all banks)

// ---------------- scratch (device globals; no allocation) ----------------
__device__ float g_x[2][NATOM * DIM];
__device__ __align__(16) uint32_t g_xh[2][NATOM * 32];      // half2 mirror of x
__device__ __align__(16) uint32_t g_nfH[NATOM * MNBR * 24]; // [nbr_fea|1|pad] half2
__device__ uint32_t g_z[NATOM * MNBR * 64];          // z as half2, 100 MB
__device__ float g_summed[NATOM * DIM];
__device__ float g_G[NCRY * NA * 384];               // 50 MB
__device__ uint32_t g_WnH[3 * TWO_D * K2N];          // fused W half2 [l][n][k2]
__device__ float g_embT[ORIG * DIM];                 // [k][d]
__device__ float g_bilT[DIM * 6 * DIM];              // [d][o*64+k]
__device__ float g_fcaT[DIM * ORIG];                 // [k][c]
// padded stat arrays: one 128B line per channel -> many LTS slices
__device__ float g_s1[TWO_D * SPAD], g_ss1[TWO_D * SPAD];
__device__ float g_s2[DIM * SPAD], g_ss2[DIM * SPAD];

__device__ __forceinline__ float softplusf(float v) {
    return v > 20.0f ? v : log1pf(expf(v));
}
// fast softplus * sigmoid gate (approx intrinsics; err ~1e-6 rel, far below fp16 z noise)
__device__ __forceinline__ float gatef(float fv, float cv) {
    float sp = (cv > 15.0f) ? cv : __logf(1.0f + __expf(cv));
    return __fdividef(sp, 1.0f + __expf(-fv));
}
__device__ __forceinline__ void mma_f16(float* c, const uint32_t* a, const uint32_t* b) {
    asm volatile(
        "mma.sync.aligned.m16n8k16.row.col.f32.f16.f16.f32 "
        "{%0,%1,%2,%3}, {%4,%5,%6,%7}, {%8,%9}, {%0,%1,%2,%3};"
        : "+f"(c[0]), "+f"(c[1]), "+f"(c[2]), "+f"(c[3])
        : "r"(a[0]), "r"(a[1]), "r"(a[2]), "r"(a[3]), "r"(b[0]), "r"(b[1]));
}
__device__ __forceinline__ void ldsm4(uint32_t* r, uint32_t addr) {
    asm volatile("ldmatrix.sync.aligned.m8n8.x4.shared.b16 {%0,%1,%2,%3}, [%4];"
                 : "=r"(r[0]), "=r"(r[1]), "=r"(r[2]), "=r"(r[3]) : "r"(addr));
}
__device__ __forceinline__ void cpa16(uint32_t dst, const void* src) {
    asm volatile("cp.async.ca.shared.global [%0], [%1], 16;" :: "r"(dst), "l"(src));
}

// ---------------- prep: fused weight layout + half nbr_fea ----------------
__global__ void prep_kernel(const float* __restrict__ conv_W,
                            const float* __restrict__ conv_b,
                            const float* __restrict__ embed_W,
                            const float* __restrict__ bil_W,
                            const float* __restrict__ fca_W,
                            const float* __restrict__ nbr_fea) {
    int idx = blockIdx.x * blockDim.x + threadIdx.x;
    if (idx < 3 * TWO_D * K2N) {                      // g_WnH [l][n][j]
        int l = idx / (TWO_D * K2N), r = idx % (TWO_D * K2N);
        int n = r / K2N, j = r % K2N;
        int k0 = 2 * j, k1 = 2 * j + 1;
        const float* wr = conv_W + (l * TWO_D + n) * KTOT;
        float a = (k0 < KTOT) ? wr[k0] : (k0 == KTOT ? conv_b[l * TWO_D + n] : 0.f);
        float b = (k1 < KTOT) ? wr[k1] : (k1 == KTOT ? conv_b[l * TWO_D + n] : 0.f);
        __half2 h = __floats2half2_rn(a, b);
        g_WnH[idx] = *(uint32_t*)&h;
        return;
    }
    int i2 = idx - 3 * TWO_D * K2N;
    if (i2 < ORIG * DIM) {                            // g_embT [k][d]
        int k = i2 / DIM, d = i2 % DIM;
        g_embT[i2] = embed_W[d * ORIG + k];
        return;
    }
    int i3 = i2 - ORIG * DIM;
    if (i3 < DIM * 6 * DIM) {                         // g_bilT [d][o*64+k]
        int d = i3 / 384, ok = i3 % 384;
        int o = ok >> 6, k2 = ok & 63;
        g_bilT[i3] = bil_W[(o * DIM + d) * DIM + k2];
        return;
    }
    int i4 = i3 - DIM * 6 * DIM;
    if (i4 < DIM * ORIG) {
        int k = i4 / ORIG, c = i4 % ORIG;
        g_fcaT[i4] = fca_W[c * DIM + k];
        return;
    }
    int i5 = i4 - DIM * ORIG;
    if (i5 < NATOM * MNBR * 24) {                     // g_nfH [row][j]
        int row = i5 / 24, j = i5 % 24;
        int h0 = 2 * j, h1 = 2 * j + 1;
        const float* nf = nbr_fea + (long)row * FNBR;
        float a = (h0 < FNBR) ? nf[h0] : (h0 == FNBR ? 1.0f : 0.f);
        float b = (h1 < FNBR) ? nf[h1] : (h1 == FNBR ? 1.0f : 0.f);
        __half2 h = __floats2half2_rn(a, b);
        g_nfH[i5] = *(uint32_t*)&h;
    }
}

// ---------------- embedding: x = atom_fea @ embed_W^T  (K=92); also writes half mirror ----------------
__global__ __launch_bounds__(256) void embed_kernel(const float* __restrict__ atom_fea) {
    __shared__ float As[64 * ORIG];
    __shared__ float Ws[ORIG * DIM];
    int t = threadIdx.x;
    int rb = blockIdx.x * 64;
    for (int e = t; e < ORIG * DIM; e += 256) Ws[e] = g_embT[e];
    int warp = t >> 5, lane = t & 31;
    for (int m = warp; m < 64; m += 8) {
        const float* row = atom_fea + (rb + m) * ORIG;
        As[m * ORIG + lane] = row[lane];
        As[m * ORIG + 32 + lane] = row[32 + lane];
        if (lane < ORIG - 64) As[m * ORIG + 64 + lane] = row[64 + lane];
    }
    __syncthreads();
    int ty = t >> 5, tx = t & 31;
    float acc[8][2];
#pragma unroll
    for (int i = 0; i < 8; i++) { acc[i][0] = 0.f; acc[i][1] = 0.f; }
    for (int k = 0; k < ORIG; k++) {
        float2 b = *(const float2*)&Ws[k * DIM + tx * 2];
#pragma unroll
        for (int i = 0; i < 8; i++) {
            float a = As[(ty * 8 + i) * ORIG + k];
            acc[i][0] = fmaf(a, b.x, acc[i][0]);
            acc[i][1] = fmaf(a, b.y, acc[i][1]);
        }
    }
#pragma unroll
    for (int i = 0; i < 8; i++) {
        int row = rb + ty * 8 + i;
        *(float2*)&g_x[0][row * DIM + tx * 2] = make_float2(acc[i][0], acc[i][1]);
        __half2 h = __floats2half2_rn(acc[i][0], acc[i][1]);
        g_xh[0][row * 32 + tx] = *(uint32_t*)&h;
    }
}

// ---------------- stat zeroing (padded arrays; every layer) ----------------
__global__ void zero_stats() {
    int t = blockIdx.x * 256 + threadIdx.x;
    if (t < TWO_D * SPAD) { g_s1[t] = 0.f; g_ss1[t] = 0.f; }
    int u = t - TWO_D * SPAD;
    if (u >= 0 && u < DIM * SPAD) { g_s2[u] = 0.f; g_ss2[u] = 0.f; }
}

// ---------------- fused conv GEMM (persistent CTAs, cp.async gather) ----------------
#define CZ_SMEM ((64 * AP + 128 * BP) * 4)

__global__ __launch_bounds__(256, 3) void convz_kernel(int l, int buf,
                                                       const int* __restrict__ nbr_idx) {
    extern __shared__ uint32_t smu[];
    uint32_t* As2 = smu;               // [64][AP]; reused as z staging [64][ZBP]
    uint32_t* Bs2 = smu + 64 * AP;     // [128][BP]
    __shared__ float redS[128], redQ[128];
    __shared__ int nbr_s[64];
    int t = threadIdx.x, w = t >> 5, lane = t & 31;
    const uint32_t* xh = g_xh[buf];
    if (t < 128) { redS[t] = 0.f; redQ[t] = 0.f; }
    // B: load fused weights ONCE per persistent CTA
    {
        const uint32_t* src = g_WnH + l * TWO_D * K2N;
        for (int e = t; e < TWO_D * K2N; e += 256)
            Bs2[(e / K2N) * BP + (e % K2N)] = src[e];
    }

    int wm = w & 1, wn = w >> 1;             // wm 0..1 (32 rows), wn 0..3 (32 cols)
    int q = lane >> 2, r = lane & 3;
    uint32_t sAs = (uint32_t)__cvta_generic_to_shared(As2);
    uint32_t sBs = (uint32_t)__cvta_generic_to_shared(Bs2);
    uint32_t aAddr0 = sAs + (((wm * 32) + (lane & 7) + ((lane >> 3) & 1) * 8) * AP +
                             ((lane >> 4) & 1) * 4) * 4;
    uint32_t aAddr1 = aAddr0 + 16 * AP * 4;
    uint32_t bAddr0 = sBs + (((wn * 32) + (lane & 7) + ((lane >> 4) & 1) * 8) * BP +
                             ((lane >> 3) & 1) * 4) * 4;
    uint32_t bAddr1 = bAddr0 + 16 * BP * 4;

    for (int tile = blockIdx.x; tile < NTILE; tile += CZGRID) {
        int rb = tile * 64;
        if (t < 64) nbr_s[t] = nbr_idx[rb + t];
        __syncthreads();   // prior tile's z-staging reads done; nbr_s visible
        // A: cp.async 16B chunks of pre-halved [x_self | x_nbr | nf+bias]
        for (int m = w; m < 64; m += 8) {
            int row = rb + m;
            int nself = row / MNBR;
            int nbr = nbr_s[m];
            uint32_t dstb = sAs + m * AP * 4;
            if (lane < 8) {
                cpa16(dstb + lane * 16, xh + nself * 32 + lane * 4);
            } else if (lane < 16) {
                cpa16(dstb + 128 + (lane - 8) * 16, xh + nbr * 32 + (lane - 8) * 4);
            } else if (lane < 22) {
                cpa16(dstb + 256 + (lane - 16) * 16, g_nfH + (long)row * 24 + (lane - 16) * 4);
            }
        }
        asm volatile("cp.async.commit_group;" ::: "memory");
        asm volatile("cp.async.wait_group 0;" ::: "memory");
        __syncthreads();

        float c[2][4][4];
#pragma unroll
        for (int mt = 0; mt < 2; mt++)
#pragma unroll
            for (int nf = 0; nf < 4; nf++)
#pragma unroll
                for (int e = 0; e < 4; e++) c[mt][nf][e] = 0.f;

#pragma unroll
        for (int ks = 0; ks < NKS; ks++) {
            uint32_t ko = ks * 32;               // 8 u32 per step
            uint32_t a[2][4], b01[4], b23[4];
            ldsm4(a[0], aAddr0 + ko);
            ldsm4(a[1], aAddr1 + ko);
            ldsm4(b01, bAddr0 + ko);
            ldsm4(b23, bAddr1 + ko);
            uint32_t bf[4][2] = {{b01[0], b01[1]}, {b01[2], b01[3]},
                                 {b23[0], b23[1]}, {b23[2], b23[3]}};
#pragma unroll
            for (int mt = 0; mt < 2; mt++)
#pragma unroll
                for (int nf = 0; nf < 4; nf++)
                    mma_f16(c[mt][nf], a[mt], bf[nf]);
        }
        __syncthreads();   // all warps done reading As via ldmatrix

        // epilogue: half2 round-trip, stats in registers, stage z in smem (bank-clean)
        uint32_t* zbuf = As2;   // [64][ZBP]
#pragma unroll
        for (int nf = 0; nf < 4; nf++) {
            int cc = wn * 32 + nf * 8 + r * 2;
            int cu = cc >> 1;
            float s0 = 0.f, s1 = 0.f, q0 = 0.f, q1 = 0.f;
#pragma unroll
            for (int mt = 0; mt < 2; mt++) {
                int m0 = wm * 32 + mt * 16 + q;
                __half2 h0 = __floats2half2_rn(c[mt][nf][0], c[mt][nf][1]);
                __half2 h1 = __floats2half2_rn(c[mt][nf][2], c[mt][nf][3]);
                zbuf[m0 * ZBP + cu] = *(uint32_t*)&h0;
                zbuf[(m0 + 8) * ZBP + cu] = *(uint32_t*)&h1;
                float2 v0 = __half22float2(h0);
                float2 v1 = __half22float2(h1);
                s0 += v0.x + v1.x; q0 += v0.x * v0.x + v1.x * v1.x;
                s1 += v0.y + v1.y; q1 += v0.y * v0.y + v1.y * v1.y;
            }
#pragma unroll
            for (int off = 4; off < 32; off <<= 1) {
                s0 += __shfl_xor_sync(0xffffffffu, s0, off);
                s1 += __shfl_xor_sync(0xffffffffu, s1, off);
                q0 += __shfl_xor_sync(0xffffffffu, q0, off);
                q1 += __shfl_xor_sync(0xffffffffu, q1, off);
            }
            if (lane < 4) {
                atomicAdd(&redS[cc], s0);
                atomicAdd(&redS[cc + 1], s1);
                atomicAdd(&redQ[cc], q0);
                atomicAdd(&redQ[cc + 1], q1);
            }
        }
        __syncthreads();   // zbuf complete
        // coalesced z store: 4 x uint4 per thread (128B sectors)
#pragma unroll
        for (int e = 0; e < 4; e++) {
            int idx = e * 256 + t;          // 0..1023 uint4 slots
            int row = idx >> 4;             // 64 rows
            int c4 = (idx & 15) * 4;        // 16 uint4 per row
            uint4 v = *(uint4*)&zbuf[row * ZBP + c4];
            *(uint4*)&g_z[((long)(rb + row)) * 64 + c4] = v;
        }
    }
    // one global-atomic flush per persistent CTA
    __syncthreads();
    if (t < 128) {
        atomicAdd(&g_s1[t * SPAD], redS[t]);
        atomicAdd(&g_ss1[t * SPAD], redQ[t]);
    }
}

// ---------------- BN1 + gate + sum over neighbors (half2 z), BN2 stats ----------------
__global__ __launch_bounds__(256) void reduce_kernel(int l,
                                                     const float* __restrict__ bn1_g,
                                                     const float* __restrict__ bn1_b) {
    __shared__ float r2S[64], r2Q[64];
    int c = threadIdx.x & 31, grp = threadIdx.x >> 5;
    int d0 = 2 * c;
    if (threadIdx.x < 64) { r2S[threadIdx.x] = 0.f; r2Q[threadIdx.x] = 0.f; }
    __syncthreads();
    float inv = 1.0f / CNT1F;
    float mf0 = g_s1[d0 * SPAD] * inv, mf1 = g_s1[(d0 + 1) * SPAD] * inv;
    float vf0 = g_ss1[d0 * SPAD] * inv - mf0 * mf0;
    float vf1 = g_ss1[(d0 + 1) * SPAD] * inv - mf1 * mf1;
    float scf0 = rsqrtf(vf0 + EPSBN) * bn1_g[l * TWO_D + d0];
    float scf1 = rsqrtf(vf1 + EPSBN) * bn1_g[l * TWO_D + d0 + 1];
    float shf0 = bn1_b[l * TWO_D + d0] - mf0 * scf0;
    float shf1 = bn1_b[l * TWO_D + d0 + 1] - mf1 * scf1;
    float mc0 = g_s1[(64 + d0) * SPAD] * inv, mc1 = g_s1[(64 + d0 + 1) * SPAD] * inv;
    float vc0 = g_ss1[(64 + d0) * SPAD] * inv - mc0 * mc0;
    float vc1 = g_ss1[(64 + d0 + 1) * SPAD] * inv - mc1 * mc1;
    float scc0 = rsqrtf(vc0 + EPSBN) * bn1_g[l * TWO_D + 64 + d0];
    float scc1 = rsqrtf(vc1 + EPSBN) * bn1_g[l * TWO_D + 64 + d0 + 1];
    float shc0 = bn1_b[l * TWO_D + 64 + d0] - mc0 * scc0;
    float shc1 = bn1_b[l * TWO_D + 64 + d0 + 1] - mc1 * scc1;

    float ls0 = 0.f, ls1 = 0.f, lq0 = 0.f, lq1 = 0.f;
    int n0 = blockIdx.x * 16 + grp * 2;
#pragma unroll
    for (int a = 0; a < 2; a++) {
        int n = n0 + a;
        const uint32_t* zr = g_z + (long)n * MNBR * 64;
        uint32_t zfp[MNBR], zcp[MNBR];
#pragma unroll
        for (int m = 0; m < MNBR; m++) zfp[m] = __ldg(&zr[m * 64 + c]);
#pragma unroll
        for (int m = 0; m < MNBR; m++) zcp[m] = __ldg(&zr[m * 64 + 32 + c]);
        float a0 = 0.f, a1 = 0.f;
#pragma unroll
        for (int m = 0; m < MNBR; m++) {
            float2 zf = __half22float2(*(__half2*)&zfp[m]);
            float2 zc = __half22float2(*(__half2*)&zcp[m]);
            a0 += gatef(zf.x * scf0 + shf0, zc.x * scc0 + shc0);
            a1 += gatef(zf.y * scf1 + shf1, zc.y * scc1 + shc1);
        }
        *(float2*)&g_summed[n * DIM + d0] = make_float2(a0, a1);
        ls0 += a0; lq0 += a0 * a0;
        ls1 += a1; lq1 += a1 * a1;
    }
    // stage BN2 stats in smem (8 warps share channels), then 1 global atomic/ch/block
    atomicAdd(&r2S[d0], ls0);
    atomicAdd(&r2S[d0 + 1], ls1);
    atomicAdd(&r2Q[d0], lq0);
    atomicAdd(&r2Q[d0 + 1], lq1);
    __syncthreads();
    if (threadIdx.x < 64) {
        atomicAdd(&g_s2[threadIdx.x * SPAD], r2S[threadIdx.x]);
        atomicAdd(&g_ss2[threadIdx.x * SPAD], r2Q[threadIdx.x]);
    }
}

// ---------------- BN2 + residual softplus -> x_out (fp32 + half mirror) ----------------
__global__ __launch_bounds__(256) void bnres_kernel(int l, int buf,
                                                    const float* __restrict__ bn2_g,
                                                    const float* __restrict__ bn2_b) {
    int gid2 = blockIdx.x * 256 + threadIdx.x;       // one per 2 elements
    int n = gid2 >> 5;
    int d0 = (gid2 & 31) * 2;
    float inv = 1.0f / CNT2F;
    float m0 = g_s2[d0 * SPAD] * inv, m1 = g_s2[(d0 + 1) * SPAD] * inv;
    float v0 = g_ss2[d0 * SPAD] * inv - m0 * m0;
    float v1 = g_ss2[(d0 + 1) * SPAD] * inv - m1 * m1;
    float sc0 = rsqrtf(v0 + EPSBN) * bn2_g[l * DIM + d0];
    float sc1 = rsqrtf(v1 + EPSBN) * bn2_g[l * DIM + d0 + 1];
    float sh0 = bn2_b[l * DIM + d0] - m0 * sc0;
    float sh1 = bn2_b[l * DIM + d0 + 1] - m1 * sc1;
    float2 xo = *(const float2*)&g_x[buf][n * DIM + d0];
    float2 sm = *(const float2*)&g_summed[n * DIM + d0];
    float a = xo.x + sm.x * sc0 + sh0;
    float b = xo.y + sm.y * sc1 + sh1;
    a = (a > 15.0f) ? a : __logf(1.0f + __expf(a));
    b = (b > 15.0f) ? b : __logf(1.0f + __expf(b));
    *(float2*)&g_x[1 - buf][n * DIM + d0] = make_float2(a, b);
    __half2 h = __floats2half2_rn(a, b);
    g_xh[1 - buf][n * 32 + (d0 >> 1)] = *(uint32_t*)&h;
}

// ---------------- G[bi, o*64+k] = f[bi,:] @ bilT  (K=64, scalar) ----------------
__global__ __launch_bounds__(256) void gmat_kernel(int buf, const int* __restrict__ cidx) {
    extern __shared__ float sm[];
    float* Ws = sm;                // [64][128]
    float* As = sm + 64 * TWO_D;   // [64][64]
    __shared__ int cid_s[64];
    int t = threadIdx.x;
    int rb = blockIdx.x * 64;
    int co = blockIdx.y * 128;
    const float* x = g_x[buf];
    if (t < 64) cid_s[t] = cidx[rb + t];
    for (int e = t; e < 64 * TWO_D; e += 256) {
        int k = e >> 7, oc = e & 127;
        Ws[e] = g_bilT[k * 384 + co + oc];
    }
    __syncthreads();
    int warp = t >> 5, lane = t & 31;
    for (int m = warp; m < 64; m += 8) {
        int a = cid_s[m];
        As[m * 64 + lane]      = x[a * DIM + lane];
        As[m * 64 + 32 + lane] = x[a * DIM + 32 + lane];
    }
    __syncthreads();
    int ty = t >> 5, tx = t & 31;
    float acc[8][4];
#pragma unroll
    for (int i = 0; i < 8; i++)
#pragma unroll
        for (int c = 0; c < 4; c++) acc[i][c] = 0.f;
    for (int k = 0; k < 64; k++) {
        float4 b = *(const float4*)&Ws[k * TWO_D + tx * 4];
#pragma unroll
        for (int i = 0; i < 8; i++) {
            float a = As[(ty * 8 + i) * 64 + k];
            acc[i][0] = fmaf(a, b.x, acc[i][0]);
            acc[i][1] = fmaf(a, b.y, acc[i][1]);
            acc[i][2] = fmaf(a, b.z, acc[i][2]);
            acc[i][3] = fmaf(a, b.w, acc[i][3]);
        }
    }
#pragma unroll
    for (int i = 0; i < 8; i++)
        *(float4*)&g_G[(long)(rb + ty * 8 + i) * 384 + co + tx * 4] =
            make_float4(acc[i][0], acc[i][1], acc[i][2], acc[i][3]);
}

// ---------------- edge: per-pair bilinear dot + fc1 + log_softmax ----------------
__global__ __launch_bounds__(256) void edge_kernel(int buf, const int* __restrict__ cidx,
                                                   const float* __restrict__ bil_b,
                                                   const float* __restrict__ fc1_W,
                                                   const float* __restrict__ fc1_b,
                                                   float* __restrict__ out) {
    __shared__ float f_s[64][65];
    __shared__ float Gi[4][384];
    __shared__ int cid_s[64];
    __shared__ float s_fc1W[36], s_fc1b[6], s_bilb[6];
    int b = blockIdx.x, it = blockIdx.y, t = threadIdx.x;
    const float* x = g_x[buf];
    if (t < 64) cid_s[t] = cidx[b * 64 + t];
    if (t < 36) s_fc1W[t] = fc1_W[t];
    if (t >= 64 && t < 70) s_fc1b[t - 64] = fc1_b[t - 64];
    if (t >= 96 && t < 102) s_bilb[t - 96] = bil_b[t - 96];
    __syncthreads();
    for (int e = t; e < 4096; e += 256) {
        int m = e >> 6, k = e & 63;
        f_s[m][k] = x[cid_s[m] * DIM + k];
    }
    for (int e = t; e < 1536; e += 256) {
        int i4 = e / 384, ok = e % 384;
        Gi[i4][ok] = g_G[(long)(b * 64 + it * 4 + i4) * 384 + ok];
    }
    __syncthreads();
    int i4 = t >> 6, j = t & 63;
    float ev[6];
#pragma unroll
    for (int o = 0; o < 6; o++) {
        float a = s_bilb[o];
#pragma unroll 16
        for (int k = 0; k < 64; k++) a = fmaf(Gi[i4][o * 64 + k], f_s[j][k], a);
        ev[o] = a;
    }
    float tr[6];
#pragma unroll
    for (int r = 0; r < 6; r++) {
        float a = s_fc1b[r];
#pragma unroll
        for (int o = 0; o < 6; o++) a = fmaf(s_fc1W[r * 6 + o], ev[o], a);
        tr[r] = a;
    }
    float mx = tr[0];
#pragma unroll
    for (int r = 1; r < 6; r++) mx = fmaxf(mx, tr[r]);
    float se = 0.f;
#pragma unroll
    for (int r = 0; r < 6; r++) se += expf(tr[r] - mx);
    float lse = mx + logf(se);
    int pair = (it * 4 + i4) * 64 + j;
    float* op = out + ((long)b * 4096 + pair) * 6;
#pragma unroll
    for (int r = 0; r < 6; r++) op[r] = tr[r] - lse;
}

// ---------------- atom_out = f @ fca_W^T + fca_b ----------------
__global__ __launch_bounds__(96) void atomout_kernel(int buf, const int* __restrict__ cidx,
                                                     const float* __restrict__ fca_b,
                                                     float* __restrict__ out2) {
    __shared__ float xr[64];
    int t = threadIdx.x;
    int r = blockIdx.x;
    int atom = cidx[r];
    if (t < 64) xr[t] = g_x[buf][atom * DIM + t];
    __syncthreads();
    if (t < ORIG) {
        float a = fca_b[t];
#pragma unroll 16
        for (int k = 0; k < 64; k++) a = fmaf(xr[k], g_fcaT[k * ORIG + t], a);
        out2[(long)r * ORIG + t] = a;
    }
}

// ---------------- launch ----------------
#define ZS_SM ((64 * TWO_D + 64 * 64) * 4)

extern "C" void kernel_launch(void* const* d_in, const int* in_sizes, int n_in,
                              void* d_out, int out_size) {
    (void)in_sizes; (void)n_in; (void)out_size;
    const float* atom_fea = (const float*)d_in[0];
    const float* nbr_fea  = (const float*)d_in[1];
    const int*   nbr_idx  = (const int*)d_in[2];
    const int*   cidx     = (const int*)d_in[3];
    const float* embed_W  = (const float*)d_in[4];
    const float* conv_W   = (const float*)d_in[5];
    const float* conv_b   = (const float*)d_in[6];
    const float* bn1_g    = (const float*)d_in[7];
    const float* bn1_b    = (const float*)d_in[8];
    const float* bn2_g    = (const float*)d_in[9];
    const float* bn2_b    = (const float*)d_in[10];
    const float* bil_W    = (const float*)d_in[11];
    const float* bil_b    = (const float*)d_in[12];
    const float* fc1_W    = (const float*)d_in[13];
    const float* fc1_b    = (const float*)d_in[14];
    const float* fca_W    = (const float*)d_in[15];
    const float* fca_b    = (const float*)d_in[16];
    float* out = (float*)d_out;

    cudaFuncSetAttribute(convz_kernel, cudaFuncAttributeMaxDynamicSharedMemorySize, CZ_SMEM);
    cudaFuncSetAttribute(gmat_kernel,  cudaFuncAttributeMaxDynamicSharedMemorySize, ZS_SM);

    long prep_elems = (long)3 * TWO_D * K2N + ORIG * DIM + DIM * 384 + DIM * ORIG +
                      (long)NATOM * MNBR * 24;
    prep_kernel<<<(int)((prep_elems + 255) / 256), 256>>>(conv_W, conv_b, embed_W, bil_W,
                                                          fca_W, nbr_fea);
    embed_kernel<<<NATOM / 64, 256>>>(atom_fea);

    int zs_blocks = (TWO_D * SPAD + DIM * SPAD + 255) / 256;
    int buf = 0;
    for (int l = 0; l < 3; l++) {
        zero_stats<<<zs_blocks, 256>>>();
        convz_kernel<<<CZGRID, 256, CZ_SMEM>>>(l, buf, nbr_idx);
        reduce_kernel<<<NATOM / 16, 256>>>(l, bn1_g, bn1_b);
        bnres_kernel<<<(NATOM * DIM / 2) / 256, 256>>>(l, buf, bn2_g, bn2_b);
        buf = 1 - buf;
    }

    gmat_kernel<<<dim3(NCRY * NA / 64, 3), 256, ZS_SM>>>(buf, cidx);
    edge_kernel<<<dim3(NCRY, 16), 256>>>(buf, cidx, bil_b, fc1_W, fc1_b, out);
    atomout_kernel<<<NCRY * NA, 96>>>(buf, cidx, fca_b, out + (long)NCRY * NA * NA * 6);
}

// round 16
// speedup vs baseline: 2.8642x; 1.0235x over previous
#include <cuda_runtime.h>
#include <cuda_fp16.h>
#include <math.h>
#include <stdint.h>

#define NATOM 32768
#define MNBR 12
#define DIM 64
#define FNBR 41
#define ORIG 92
#define TWO_D 128
#define KTOT 169
#define NCRY 512
#define NA 64
#define CNT1F (393216.0f)
#define CNT2F (32768.0f)
#define EPSBN 1e-5f

#define K2N 88          // u32 (half2) count per B row: K=170 padded to 176 halves
#define AP 92           // A smem pitch in u32
#define BP 92           // B smem pitch in u32
#define NKS 11          // k-steps of 16
#define SPAD 32         // stat array stride (32 floats = 128B) to spread LTS slices
#define NPAIR (NATOM * MNBR / 128)  // 3072 double-tiles
#define CZGRID 296                   // persistent CTAs (2/SM x 148)
#define ZBP 68          // z staging pitch in u32 (4q+r covers all banks)

// ---------------- scratch (device globals; no allocation) ----------------
__device__ float g_x[2][NATOM * DIM];
__device__ __align__(16) uint32_t g_xh[2][NATOM * 32];      // half2 mirror of x
__device__ __align__(16) uint32_t g_nfH[NATOM * MNBR * 24]; // [nbr_fea|1|pad] half2
__device__ uint32_t g_z[NATOM * MNBR * 64];          // z as half2, 100 MB
__device__ float g_summed[NATOM * DIM];
__device__ float g_G[NCRY * NA * 384];               // 50 MB
__device__ uint32_t g_WnH[3 * TWO_D * K2N];          // fused W half2 [l][n][k2]
__device__ float g_embT[ORIG * DIM];                 // [k][d]
__device__ float g_bilT[DIM * 6 * DIM];              // [d][o*64+k]
__device__ float g_fcaT[DIM * ORIG];                 // [k][c]
// padded stat arrays: one 128B line per channel -> many LTS slices
__device__ float g_s1[TWO_D * SPAD], g_ss1[TWO_D * SPAD];
__device__ float g_s2[DIM * SPAD], g_ss2[DIM * SPAD];

__device__ __forceinline__ float softplusf(float v) {
    return v > 20.0f ? v : log1pf(expf(v));
}
// fast softplus * sigmoid gate (approx intrinsics; err ~1e-6 rel, far below fp16 z noise)
__device__ __forceinline__ float gatef(float fv, float cv) {
    float sp = (cv > 15.0f) ? cv : __logf(1.0f + __expf(cv));
    return __fdividef(sp, 1.0f + __expf(-fv));
}
__device__ __forceinline__ void mma_f16(float* c, const uint32_t* a, const uint32_t* b) {
    asm volatile(
        "mma.sync.aligned.m16n8k16.row.col.f32.f16.f16.f32 "
        "{%0,%1,%2,%3}, {%4,%5,%6,%7}, {%8,%9}, {%0,%1,%2,%3};"
        : "+f"(c[0]), "+f"(c[1]), "+f"(c[2]), "+f"(c[3])
        : "r"(a[0]), "r"(a[1]), "r"(a[2]), "r"(a[3]), "r"(b[0]), "r"(b[1]));
}
__device__ __forceinline__ void ldsm4(uint32_t* r, uint32_t addr) {
    asm volatile("ldmatrix.sync.aligned.m8n8.x4.shared.b16 {%0,%1,%2,%3}, [%4];"
                 : "=r"(r[0]), "=r"(r[1]), "=r"(r[2]), "=r"(r[3]) : "r"(addr));
}
__device__ __forceinline__ void cpa16(uint32_t dst, const void* src) {
    asm volatile("cp.async.ca.shared.global [%0], [%1], 16;" :: "r"(dst), "l"(src));
}

// ---------------- prep: fused weight layout + half nbr_fea ----------------
__global__ void prep_kernel(const float* __restrict__ conv_W,
                            const float* __restrict__ conv_b,
                            const float* __restrict__ embed_W,
                            const float* __restrict__ bil_W,
                            const float* __restrict__ fca_W,
                            const float* __restrict__ nbr_fea) {
    int idx = blockIdx.x * blockDim.x + threadIdx.x;
    if (idx < 3 * TWO_D * K2N) {                      // g_WnH [l][n][j]
        int l = idx / (TWO_D * K2N), r = idx % (TWO_D * K2N);
        int n = r / K2N, j = r % K2N;
        int k0 = 2 * j, k1 = 2 * j + 1;
        const float* wr = conv_W + (l * TWO_D + n) * KTOT;
        float a = (k0 < KTOT) ? wr[k0] : (k0 == KTOT ? conv_b[l * TWO_D + n] : 0.f);
        float b = (k1 < KTOT) ? wr[k1] : (k1 == KTOT ? conv_b[l * TWO_D + n] : 0.f);
        __half2 h = __floats2half2_rn(a, b);
        g_WnH[idx] = *(uint32_t*)&h;
        return;
    }
    int i2 = idx - 3 * TWO_D * K2N;
    if (i2 < ORIG * DIM) {                            // g_embT [k][d]
        int k = i2 / DIM, d = i2 % DIM;
        g_embT[i2] = embed_W[d * ORIG + k];
        return;
    }
    int i3 = i2 - ORIG * DIM;
    if (i3 < DIM * 6 * DIM) {                         // g_bilT [d][o*64+k]
        int d = i3 / 384, ok = i3 % 384;
        int o = ok >> 6, k2 = ok & 63;
        g_bilT[i3] = bil_W[(o * DIM + d) * DIM + k2];
        return;
    }
    int i4 = i3 - DIM * 6 * DIM;
    if (i4 < DIM * ORIG) {
        int k = i4 / ORIG, c = i4 % ORIG;
        g_fcaT[i4] = fca_W[c * DIM + k];
        return;
    }
    int i5 = i4 - DIM * ORIG;
    if (i5 < NATOM * MNBR * 24) {                     // g_nfH [row][j]
        int row = i5 / 24, j = i5 % 24;
        int h0 = 2 * j, h1 = 2 * j + 1;
        const float* nf = nbr_fea + (long)row * FNBR;
        float a = (h0 < FNBR) ? nf[h0] : (h0 == FNBR ? 1.0f : 0.f);
        float b = (h1 < FNBR) ? nf[h1] : (h1 == FNBR ? 1.0f : 0.f);
        __half2 h = __floats2half2_rn(a, b);
        g_nfH[i5] = *(uint32_t*)&h;
    }
}

// ---------------- embedding: x = atom_fea @ embed_W^T  (K=92); also writes half mirror ----------------
__global__ __launch_bounds__(256) void embed_kernel(const float* __restrict__ atom_fea) {
    __shared__ float As[64 * ORIG];
    __shared__ float Ws[ORIG * DIM];
    int t = threadIdx.x;
    int rb = blockIdx.x * 64;
    for (int e = t; e < ORIG * DIM; e += 256) Ws[e] = g_embT[e];
    int warp = t >> 5, lane = t & 31;
    for (int m = warp; m < 64; m += 8) {
        const float* row = atom_fea + (rb + m) * ORIG;
        As[m * ORIG + lane] = row[lane];
        As[m * ORIG + 32 + lane] = row[32 + lane];
        if (lane < ORIG - 64) As[m * ORIG + 64 + lane] = row[64 + lane];
    }
    __syncthreads();
    int ty = t >> 5, tx = t & 31;
    float acc[8][2];
#pragma unroll
    for (int i = 0; i < 8; i++) { acc[i][0] = 0.f; acc[i][1] = 0.f; }
    for (int k = 0; k < ORIG; k++) {
        float2 b = *(const float2*)&Ws[k * DIM + tx * 2];
#pragma unroll
        for (int i = 0; i < 8; i++) {
            float a = As[(ty * 8 + i) * ORIG + k];
            acc[i][0] = fmaf(a, b.x, acc[i][0]);
            acc[i][1] = fmaf(a, b.y, acc[i][1]);
        }
    }
#pragma unroll
    for (int i = 0; i < 8; i++) {
        int row = rb + ty * 8 + i;
        *(float2*)&g_x[0][row * DIM + tx * 2] = make_float2(acc[i][0], acc[i][1]);
        __half2 h = __floats2half2_rn(acc[i][0], acc[i][1]);
        g_xh[0][row * 32 + tx] = *(uint32_t*)&h;
    }
}

// ---------------- stat zeroing (padded arrays; every layer) ----------------
__global__ void zero_stats() {
    int t = blockIdx.x * 256 + threadIdx.x;
    if (t < TWO_D * SPAD) { g_s1[t] = 0.f; g_ss1[t] = 0.f; }
    int u = t - TWO_D * SPAD;
    if (u >= 0 && u < DIM * SPAD) { g_s2[u] = 0.f; g_ss2[u] = 0.f; }
}

// ---------------- fused conv GEMM (persistent CTAs, double-tile B reuse) ----------------
#define CZ_SMEM ((128 * AP + 128 * BP) * 4)

__global__ __launch_bounds__(256, 2) void convz_kernel(int l, int buf,
                                                       const int* __restrict__ nbr_idx) {
    extern __shared__ uint32_t smu[];
    uint32_t* As2 = smu;                // [128][AP]; reused as z staging [128][ZBP]
    uint32_t* Bs2 = smu + 128 * AP;     // [128][BP]
    __shared__ float redS[128], redQ[128];
    __shared__ int nbr_s[128];
    int t = threadIdx.x, w = t >> 5, lane = t & 31;
    const uint32_t* xh = g_xh[buf];
    if (t < 128) { redS[t] = 0.f; redQ[t] = 0.f; }
    // B: load fused weights ONCE per persistent CTA
    {
        const uint32_t* src = g_WnH + l * TWO_D * K2N;
        for (int e = t; e < TWO_D * K2N; e += 256)
            Bs2[(e / K2N) * BP + (e % K2N)] = src[e];
    }

    int wm = w & 1, wn = w >> 1;             // wm: 32-row half per tile, wn: col quarter
    int q = lane >> 2, r = lane & 3;
    uint32_t sAs = (uint32_t)__cvta_generic_to_shared(As2);
    uint32_t sBs = (uint32_t)__cvta_generic_to_shared(Bs2);
    uint32_t aAddr0 = sAs + (((wm * 32) + (lane & 7) + ((lane >> 3) & 1) * 8) * AP +
                             ((lane >> 4) & 1) * 4) * 4;
    uint32_t bAddr0 = sBs + (((wn * 32) + (lane & 7) + ((lane >> 4) & 1) * 8) * BP +
                             ((lane >> 3) & 1) * 4) * 4;
    uint32_t bAddr1 = bAddr0 + 16 * BP * 4;

    for (int pair = blockIdx.x; pair < NPAIR; pair += CZGRID) {
        int rb = pair * 128;
        if (t < 128) nbr_s[t] = nbr_idx[rb + t];
        __syncthreads();   // prior iter's z-staging reads done; nbr_s visible
        // A: cp.async 16B chunks of pre-halved [x_self | x_nbr | nf+bias], 128 rows
        for (int m = w; m < 128; m += 8) {
            int row = rb + m;
            int nself = row / MNBR;
            int nbr = nbr_s[m];
            uint32_t dstb = sAs + m * AP * 4;
            if (lane < 8) {
                cpa16(dstb + lane * 16, xh + nself * 32 + lane * 4);
            } else if (lane < 16) {
                cpa16(dstb + 128 + (lane - 8) * 16, xh + nbr * 32 + (lane - 8) * 4);
            } else if (lane < 22) {
                cpa16(dstb + 256 + (lane - 16) * 16, g_nfH + (long)row * 24 + (lane - 16) * 4);
            }
        }
        asm volatile("cp.async.commit_group;" ::: "memory");
        asm volatile("cp.async.wait_group 0;" ::: "memory");
        __syncthreads();

        float c[2][2][4][4];
#pragma unroll
        for (int tt = 0; tt < 2; tt++)
#pragma unroll
            for (int mt = 0; mt < 2; mt++)
#pragma unroll
                for (int nf = 0; nf < 4; nf++)
#pragma unroll
                    for (int e = 0; e < 4; e++) c[tt][mt][nf][e] = 0.f;

#pragma unroll
        for (int ks = 0; ks < NKS; ks++) {
            uint32_t ko = ks * 32;               // 8 u32 per step
            uint32_t a[2][2][4], b01[4], b23[4];
            ldsm4(b01, bAddr0 + ko);
            ldsm4(b23, bAddr1 + ko);
            ldsm4(a[0][0], aAddr0 + ko);
            ldsm4(a[0][1], aAddr0 + 16 * AP * 4 + ko);
            ldsm4(a[1][0], aAddr0 + 64 * AP * 4 + ko);
            ldsm4(a[1][1], aAddr0 + 80 * AP * 4 + ko);
            uint32_t bf[4][2] = {{b01[0], b01[1]}, {b01[2], b01[3]},
                                 {b23[0], b23[1]}, {b23[2], b23[3]}};
#pragma unroll
            for (int tt = 0; tt < 2; tt++)
#pragma unroll
                for (int mt = 0; mt < 2; mt++)
#pragma unroll
                    for (int nf = 0; nf < 4; nf++)
                        mma_f16(c[tt][mt][nf], a[tt][mt], bf[nf]);
        }
        __syncthreads();   // all warps done reading As via ldmatrix

        // epilogue: half2 round-trip, stats in registers, stage z in smem (bank-clean)
        uint32_t* zbuf = As2;   // [128][ZBP]
#pragma unroll
        for (int nf = 0; nf < 4; nf++) {
            int cc = wn * 32 + nf * 8 + r * 2;
            int cu = cc >> 1;
            float s0 = 0.f, s1 = 0.f, q0 = 0.f, q1 = 0.f;
#pragma unroll
            for (int tt = 0; tt < 2; tt++)
#pragma unroll
                for (int mt = 0; mt < 2; mt++) {
                    int m0 = tt * 64 + wm * 32 + mt * 16 + q;
                    __half2 h0 = __floats2half2_rn(c[tt][mt][nf][0], c[tt][mt][nf][1]);
                    __half2 h1 = __floats2half2_rn(c[tt][mt][nf][2], c[tt][mt][nf][3]);
                    zbuf[m0 * ZBP + cu] = *(uint32_t*)&h0;
                    zbuf[(m0 + 8) * ZBP + cu] = *(uint32_t*)&h1;
                    float2 v0 = __half22float2(h0);
                    float2 v1 = __half22float2(h1);
                    s0 += v0.x + v1.x; q0 += v0.x * v0.x + v1.x * v1.x;
                    s1 += v0.y + v1.y; q1 += v0.y * v0.y + v1.y * v1.y;
                }
#pragma unroll
            for (int off = 4; off < 32; off <<= 1) {
                s0 += __shfl_xor_sync(0xffffffffu, s0, off);
                s1 += __shfl_xor_sync(0xffffffffu, s1, off);
                q0 += __shfl_xor_sync(0xffffffffu, q0, off);
                q1 += __shfl_xor_sync(0xffffffffu, q1, off);
            }
            if (lane < 4) {
                atomicAdd(&redS[cc], s0);
                atomicAdd(&redS[cc + 1], s1);
                atomicAdd(&redQ[cc], q0);
                atomicAdd(&redQ[cc + 1], q1);
            }
        }
        __syncthreads();   // zbuf complete
        // coalesced z store: 8 x uint4 per thread (128B sectors)
#pragma unroll
        for (int e = 0; e < 8; e++) {
            int idx = e * 256 + t;          // 0..2047 uint4 slots
            int row = idx >> 4;             // 128 rows
            int c4 = (idx & 15) * 4;        // 16 uint4 per row
            uint4 v = *(uint4*)&zbuf[row * ZBP + c4];
            *(uint4*)&g_z[((long)(rb + row)) * 64 + c4] = v;
        }
    }
    // one global-atomic flush per persistent CTA
    __syncthreads();
    if (t < 128) {
        atomicAdd(&g_s1[t * SPAD], redS[t]);
        atomicAdd(&g_ss1[t * SPAD], redQ[t]);
    }
}

// ---------------- BN1 + gate + sum over neighbors (half2 z), BN2 stats ----------------
__global__ __launch_bounds__(256) void reduce_kernel(int l,
                                                     const float* __restrict__ bn1_g,
                                                     const float* __restrict__ bn1_b) {
    __shared__ float r2S[64], r2Q[64];
    int c = threadIdx.x & 31, grp = threadIdx.x >> 5;
    int d0 = 2 * c;
    if (threadIdx.x < 64) { r2S[threadIdx.x] = 0.f; r2Q[threadIdx.x] = 0.f; }
    __syncthreads();
    float inv = 1.0f / CNT1F;
    float mf0 = g_s1[d0 * SPAD] * inv, mf1 = g_s1[(d0 + 1) * SPAD] * inv;
    float vf0 = g_ss1[d0 * SPAD] * inv - mf0 * mf0;
    float vf1 = g_ss1[(d0 + 1) * SPAD] * inv - mf1 * mf1;
    float scf0 = rsqrtf(vf0 + EPSBN) * bn1_g[l * TWO_D + d0];
    float scf1 = rsqrtf(vf1 + EPSBN) * bn1_g[l * TWO_D + d0 + 1];
    float shf0 = bn1_b[l * TWO_D + d0] - mf0 * scf0;
    float shf1 = bn1_b[l * TWO_D + d0 + 1] - mf1 * scf1;
    float mc0 = g_s1[(64 + d0) * SPAD] * inv, mc1 = g_s1[(64 + d0 + 1) * SPAD] * inv;
    float vc0 = g_ss1[(64 + d0) * SPAD] * inv - mc0 * mc0;
    float vc1 = g_ss1[(64 + d0 + 1) * SPAD] * inv - mc1 * mc1;
    float scc0 = rsqrtf(vc0 + EPSBN) * bn1_g[l * TWO_D + 64 + d0];
    float scc1 = rsqrtf(vc1 + EPSBN) * bn1_g[l * TWO_D + 64 + d0 + 1];
    float shc0 = bn1_b[l * TWO_D + 64 + d0] - mc0 * scc0;
    float shc1 = bn1_b[l * TWO_D + 64 + d0 + 1] - mc1 * scc1;

    float ls0 = 0.f, ls1 = 0.f, lq0 = 0.f, lq1 = 0.f;
    int n0 = blockIdx.x * 16 + grp * 2;
#pragma unroll
    for (int a = 0; a < 2; a++) {
        int n = n0 + a;
        const uint32_t* zr = g_z + (long)n * MNBR * 64;
        uint32_t zfp[MNBR], zcp[MNBR];
#pragma unroll
        for (int m = 0; m < MNBR; m++) zfp[m] = __ldg(&zr[m * 64 + c]);
#pragma unroll
        for (int m = 0; m < MNBR; m++) zcp[m] = __ldg(&zr[m * 64 + 32 + c]);
        float a0 = 0.f, a1 = 0.f;
#pragma unroll
        for (int m = 0; m < MNBR; m++) {
            float2 zf = __half22float2(*(__half2*)&zfp[m]);
            float2 zc = __half22float2(*(__half2*)&zcp[m]);
            a0 += gatef(zf.x * scf0 + shf0, zc.x * scc0 + shc0);
            a1 += gatef(zf.y * scf1 + shf1, zc.y * scc1 + shc1);
        }
        *(float2*)&g_summed[n * DIM + d0] = make_float2(a0, a1);
        ls0 += a0; lq0 += a0 * a0;
        ls1 += a1; lq1 += a1 * a1;
    }
    // stage BN2 stats in smem (8 warps share channels), then 1 global atomic/ch/block
    atomicAdd(&r2S[d0], ls0);
    atomicAdd(&r2S[d0 + 1], ls1);
    atomicAdd(&r2Q[d0], lq0);
    atomicAdd(&r2Q[d0 + 1], lq1);
    __syncthreads();
    if (threadIdx.x < 64) {
        atomicAdd(&g_s2[threadIdx.x * SPAD], r2S[threadIdx.x]);
        atomicAdd(&g_ss2[threadIdx.x * SPAD], r2Q[threadIdx.x]);
    }
}

// ---------------- BN2 + residual softplus -> x_out (fp32 + half mirror) ----------------
__global__ __launch_bounds__(256) void bnres_kernel(int l, int buf,
                                                    const float* __restrict__ bn2_g,
                                                    const float* __restrict__ bn2_b) {
    int gid2 = blockIdx.x * 256 + threadIdx.x;       // one per 2 elements
    int n = gid2 >> 5;
    int d0 = (gid2 & 31) * 2;
    float inv = 1.0f / CNT2F;
    float m0 = g_s2[d0 * SPAD] * inv, m1 = g_s2[(d0 + 1) * SPAD] * inv;
    float v0 = g_ss2[d0 * SPAD] * inv - m0 * m0;
    float v1 = g_ss2[(d0 + 1) * SPAD] * inv - m1 * m1;
    float sc0 = rsqrtf(v0 + EPSBN) * bn2_g[l * DIM + d0];
    float sc1 = rsqrtf(v1 + EPSBN) * bn2_g[l * DIM + d0 + 1];
    float sh0 = bn2_b[l * DIM + d0] - m0 * sc0;
    float sh1 = bn2_b[l * DIM + d0 + 1] - m1 * sc1;
    float2 xo = *(const float2*)&g_x[buf][n * DIM + d0];
    float2 sm = *(const float2*)&g_summed[n * DIM + d0];
    float a = xo.x + sm.x * sc0 + sh0;
    float b = xo.y + sm.y * sc1 + sh1;
    a = (a > 15.0f) ? a : __logf(1.0f + __expf(a));
    b = (b > 15.0f) ? b : __logf(1.0f + __expf(b));
    *(float2*)&g_x[1 - buf][n * DIM + d0] = make_float2(a, b);
    __half2 h = __floats2half2_rn(a, b);
    g_xh[1 - buf][n * 32 + (d0 >> 1)] = *(uint32_t*)&h;
}

// ---------------- G[bi, o*64+k] = f[bi,:] @ bilT  (K=64, scalar) ----------------
__global__ __launch_bounds__(256) void gmat_kernel(int buf, const int* __restrict__ cidx) {
    extern __shared__ float sm[];
    float* Ws = sm;                // [64][128]
    float* As = sm + 64 * TWO_D;   // [64][64]
    __shared__ int cid_s[64];
    int t = threadIdx.x;
    int rb = blockIdx.x * 64;
    int co = blockIdx.y * 128;
    const float* x = g_x[buf];
    if (t < 64) cid_s[t] = cidx[rb + t];
    for (int e = t; e < 64 * TWO_D; e += 256) {
        int k = e >> 7, oc = e & 127;
        Ws[e] = g_bilT[k * 384 + co + oc];
    }
    __syncthreads();
    int warp = t >> 5, lane = t & 31;
    for (int m = warp; m < 64; m += 8) {
        int a = cid_s[m];
        As[m * 64 + lane]      = x[a * DIM + lane];
        As[m * 64 + 32 + lane] = x[a * DIM + 32 + lane];
    }
    __syncthreads();
    int ty = t >> 5, tx = t & 31;
    float acc[8][4];
#pragma unroll
    for (int i = 0; i < 8; i++)
#pragma unroll
        for (int c = 0; c < 4; c++) acc[i][c] = 0.f;
    for (int k = 0; k < 64; k++) {
        float4 b = *(const float4*)&Ws[k * TWO_D + tx * 4];
#pragma unroll
        for (int i = 0; i < 8; i++) {
            float a = As[(ty * 8 + i) * 64 + k];
            acc[i][0] = fmaf(a, b.x, acc[i][0]);
            acc[i][1] = fmaf(a, b.y, acc[i][1]);
            acc[i][2] = fmaf(a, b.z, acc[i][2]);
            acc[i][3] = fmaf(a, b.w, acc[i][3]);
        }
    }
#pragma unroll
    for (int i = 0; i < 8; i++)
        *(float4*)&g_G[(long)(rb + ty * 8 + i) * 384 + co + tx * 4] =
            make_float4(acc[i][0], acc[i][1], acc[i][2], acc[i][3]);
}

// ---------------- edge: per-pair bilinear dot + fc1 + log_softmax ----------------
__global__ __launch_bounds__(256) void edge_kernel(int buf, const int* __restrict__ cidx,
                                                   const float* __restrict__ bil_b,
                                                   const float* __restrict__ fc1_W,
                                                   const float* __restrict__ fc1_b,
                                                   float* __restrict__ out) {
    __shared__ float f_s[64][65];
    __shared__ float Gi[4][384];
    __shared__ int cid_s[64];
    __shared__ float s_fc1W[36], s_fc1b[6], s_bilb[6];
    int b = blockIdx.x, it = blockIdx.y, t = threadIdx.x;
    const float* x = g_x[buf];
    if (t < 64) cid_s[t] = cidx[b * 64 + t];
    if (t < 36) s_fc1W[t] = fc1_W[t];
    if (t >= 64 && t < 70) s_fc1b[t - 64] = fc1_b[t - 64];
    if (t >= 96 && t < 102) s_bilb[t - 96] = bil_b[t - 96];
    __syncthreads();
    for (int e = t; e < 4096; e += 256) {
        int m = e >> 6, k = e & 63;
        f_s[m][k] = x[cid_s[m] * DIM + k];
    }
    for (int e = t; e < 1536; e += 256) {
        int i4 = e / 384, ok = e % 384;
        Gi[i4][ok] = g_G[(long)(b * 64 + it * 4 + i4) * 384 + ok];
    }
    __syncthreads();
    int i4 = t >> 6, j = t & 63;
    float ev[6];
#pragma unroll
    for (int o = 0; o < 6; o++) {
        float a = s_bilb[o];
#pragma unroll 16
        for (int k = 0; k < 64; k++) a = fmaf(Gi[i4][o * 64 + k], f_s[j][k], a);
        ev[o] = a;
    }
    float tr[6];
#pragma unroll
    for (int r = 0; r < 6; r++) {
        float a = s_fc1b[r];
#pragma unroll
        for (int o = 0; o < 6; o++) a = fmaf(s_fc1W[r * 6 + o], ev[o], a);
        tr[r] = a;
    }
    float mx = tr[0];
#pragma unroll
    for (int r = 1; r < 6; r++) mx = fmaxf(mx, tr[r]);
    float se = 0.f;
#pragma unroll
    for (int r = 0; r < 6; r++) se += expf(tr[r] - mx);
    float lse = mx + logf(se);
    int pair = (it * 4 + i4) * 64 + j;
    float* op = out + ((long)b * 4096 + pair) * 6;
#pragma unroll
    for (int r = 0; r < 6; r++) op[r] = tr[r] - lse;
}

// ---------------- atom_out = f @ fca_W^T + fca_b ----------------
__global__ __launch_bounds__(96) void atomout_kernel(int buf, const int* __restrict__ cidx,
                                                     const float* __restrict__ fca_b,
                                                     float* __restrict__ out2) {
    __shared__ float xr[64];
    int t = threadIdx.x;
    int r = blockIdx.x;
    int atom = cidx[r];
    if (t < 64) xr[t] = g_x[buf][atom * DIM + t];
    __syncthreads();
    if (t < ORIG) {
        float a = fca_b[t];
#pragma unroll 16
        for (int k = 0; k < 64; k++) a = fmaf(xr[k], g_fcaT[k * ORIG + t], a);
        out2[(long)r * ORIG + t] = a;
    }
}

// ---------------- launch ----------------
#define ZS_SM ((64 * TWO_D + 64 * 64) * 4)

extern "C" void kernel_launch(void* const* d_in, const int* in_sizes, int n_in,
                              void* d_out, int out_size) {
    (void)in_sizes; (void)n_in; (void)out_size;
    const float* atom_fea = (const float*)d_in[0];
    const float* nbr_fea  = (const float*)d_in[1];
    const int*   nbr_idx  = (const int*)d_in[2];
    const int*   cidx     = (const int*)d_in[3];
    const float* embed_W  = (const float*)d_in[4];
    const float* conv_W   = (const float*)d_in[5];
    const float* conv_b   = (const float*)d_in[6];
    const float* bn1_g    = (const float*)d_in[7];
    const float* bn1_b    = (const float*)d_in[8];
    const float* bn2_g    = (const float*)d_in[9];
    const float* bn2_b    = (const float*)d_in[10];
    const float* bil_W    = (const float*)d_in[11];
    const float* bil_b    = (const float*)d_in[12];
    const float* fc1_W    = (const float*)d_in[13];
    const float* fc1_b    = (const float*)d_in[14];
    const float* fca_W    = (const float*)d_in[15];
    const float* fca_b    = (const float*)d_in[16];
    float* out = (float*)d_out;

    cudaFuncSetAttribute(convz_kernel, cudaFuncAttributeMaxDynamicSharedMemorySize, CZ_SMEM);
    cudaFuncSetAttribute(gmat_kernel,  cudaFuncAttributeMaxDynamicSharedMemorySize, ZS_SM);

    long prep_elems = (long)3 * TWO_D * K2N + ORIG * DIM + DIM * 384 + DIM * ORIG +
                      (long)NATOM * MNBR * 24;
    prep_kernel<<<(int)((prep_elems + 255) / 256), 256>>>(conv_W, conv_b, embed_W, bil_W,
                                                          fca_W, nbr_fea);
    embed_kernel<<<NATOM / 64, 256>>>(atom_fea);

    int zs_blocks = (TWO_D * SPAD + DIM * SPAD + 255) / 256;
    int buf = 0;
    for (int l = 0; l < 3; l++) {
        zero_stats<<<zs_blocks, 256>>>();
        convz_kernel<<<CZGRID, 256, CZ_SMEM>>>(l, buf, nbr_idx);
        reduce_kernel<<<NATOM / 16, 256>>>(l, bn1_g, bn1_b);
        bnres_kernel<<<(NATOM * DIM / 2) / 256, 256>>>(l, buf, bn2_g, bn2_b);
        buf = 1 - buf;
    }

    gmat_kernel<<<dim3(NCRY * NA / 64, 3), 256, ZS_SM>>>(buf, cidx);
    edge_kernel<<<dim3(NCRY, 16), 256>>>(buf, cidx, bil_b, fc1_W, fc1_b, out);
    atomout_kernel<<<NCRY * NA, 96>>>(buf, cidx, fca_b, out + (long)NCRY * NA * NA * 6);
}